// round 1
// baseline (speedup 1.0000x reference)
#include <cuda_runtime.h>
#include <math.h>
#include <stdint.h>

// Problem constants
#define D      512
#define C      100
#define NX     2048
#define DD     (D*D)
#define ALPHA  0.5f
#define SHRINK 1e-4f
#define OMS    (1.0f - SHRINK)

#define NEWTON_ITERS 10
#define POWER_ITERS  10

// ---------------- scratch (device globals; no allocations allowed) ----------
__device__ float g_M [C*DD];   // shrunk regularized covariance  (~105 MB)
__device__ float g_Xa[C*DD];   // Newton iterate A
__device__ float g_Xb[C*DD];   // Newton iterate B
__device__ float g_Y [C*DD];   // temp M*X
__device__ float g_fpart[C*64];   // per-block partial Frobenius sums
__device__ float g_ab[C];         // Newton init scale a (X0 = a*I)
__device__ float g_base[C];       // log(prior) - 0.5*log(||RegSigma||_F)
__device__ float g_part[4*NX*C];  // quad partials per column-tile

// ---------------- f32x2 packed helpers --------------------------------------
typedef unsigned long long u64;

__device__ __forceinline__ void fma2(u64& c, u64 a, u64 b){
    asm("fma.rn.f32x2 %0, %1, %2, %0;" : "+l"(c) : "l"(a), "l"(b));
}
__device__ __forceinline__ u64 pk2(float x, float y){
    u64 r; asm("mov.b64 %0, {%1, %2};" : "=l"(r) : "f"(x), "f"(y)); return r;
}
__device__ __forceinline__ void upk2(u64 v, float& x, float& y){
    asm("mov.b64 {%0, %1}, %2;" : "=f"(x), "=f"(y) : "l"(v));
}

// ---------------- prep: build M, Frobenius partials -------------------------
// grid (64, C), 256 thr. Each thread: 4 float4 = 16 elems. 64*1024 float4 = 256K elems/class.
__global__ void __launch_bounds__(256) prep_kernel(const float* __restrict__ SigmaK,
                                                   const float* __restrict__ Sigma)
{
    const int cls = blockIdx.y;
    const int t   = threadIdx.x;
    const float4* Sk = (const float4*)(SigmaK + (size_t)cls*DD);
    const float4* Sg = (const float4*)Sigma;
    float4* Mo = (float4*)(g_M + (size_t)cls*DD);
    float fr = 0.f;
    #pragma unroll
    for (int j = 0; j < 4; j++){
        int id = blockIdx.x*1024 + j*256 + t;     // float4 index within class
        float4 a = Sk[id], b = Sg[id];
        float4 r;
        r.x = ALPHA*a.x + (1.0f-ALPHA)*b.x;
        r.y = ALPHA*a.y + (1.0f-ALPHA)*b.y;
        r.z = ALPHA*a.z + (1.0f-ALPHA)*b.z;
        r.w = ALPHA*a.w + (1.0f-ALPHA)*b.w;
        fr += r.x*r.x + r.y*r.y + r.z*r.z + r.w*r.w;
        float4 m;
        m.x = OMS*r.x; m.y = OMS*r.y; m.z = OMS*r.z; m.w = OMS*r.w;
        int e = id*4, row = e >> 9, c0 = e & (D-1);
        int dg = row - c0;
        if (dg >= 0 && dg < 4) ((float*)&m)[dg] += SHRINK;
        Mo[id] = m;
    }
    __shared__ float red[256];
    red[t] = fr; __syncthreads();
    for (int s = 128; s > 0; s >>= 1){ if (t < s) red[t] += red[t+s]; __syncthreads(); }
    if (t == 0) g_fpart[cls*64 + blockIdx.x] = red[0];
}

// ---------------- power iteration + per-class constants ---------------------
// grid (C), 256 thr. Estimates lambda_max, sets Newton init scale & score base.
__global__ void __launch_bounds__(256) power_kernel(const float* __restrict__ cK)
{
    const int cls  = blockIdx.x;
    const int t    = threadIdx.x;
    const int lane = t & 31, warp = t >> 5;
    const float* Mc = g_M + (size_t)cls*DD;
    __shared__ float v[D], w[D], red[256];

    // Frobenius^2 of RegSigma from partials
    float x = (t < 64) ? g_fpart[cls*64 + t] : 0.f;
    red[t] = x; __syncthreads();
    for (int s = 128; s > 0; s >>= 1){ if (t < s) red[t] += red[t+s]; __syncthreads(); }
    float frobsq = red[0]; __syncthreads();

    // sum of class counts
    float ckv = (t < C) ? cK[t] : 0.f;
    red[t] = ckv; __syncthreads();
    for (int s = 128; s > 0; s >>= 1){ if (t < s) red[t] += red[t+s]; __syncthreads(); }
    float csum = red[0]; __syncthreads();

    for (int i = t; i < D; i += 256) v[i] = 1.0f;
    __syncthreads();

    float lam = 1.0f;
    for (int it = 0; it < POWER_ITERS; ++it){
        // w = M v ; one warp per row, lane-strided k (coalesced)
        for (int r = warp; r < D; r += 8){
            float s = 0.f;
            const float* Mr = Mc + (size_t)r*D;
            for (int k = lane; k < D; k += 32) s += Mr[k]*v[k];
            #pragma unroll
            for (int o = 16; o > 0; o >>= 1) s += __shfl_down_sync(0xffffffffu, s, o);
            if (lane == 0) w[r] = s;
        }
        __syncthreads();
        float ns = 0.f;
        for (int i = t; i < D; i += 256) ns += w[i]*w[i];
        red[t] = ns; __syncthreads();
        for (int s = 128; s > 0; s >>= 1){ if (t < s) red[t] += red[t+s]; __syncthreads(); }
        lam = sqrtf(red[0]); __syncthreads();
        float inv = 1.0f/lam;
        for (int i = t; i < D; i += 256) v[i] = w[i]*inv;
        __syncthreads();
    }

    if (t == 0){
        // lambda_min >= 0.0999 structurally; generous safety on lambda_max estimate
        float bound = 1.35f*lam + 0.3f;
        g_ab[cls] = 2.0f/(0.09f + bound);
        float c0 = cK[cls];
        g_base[cls] = (c0 > 0.f) ? (logf(c0/csum) - 0.25f*logf(frobsq)) : -INFINITY;
    }
}

// ---------------- X0 = a * I -------------------------------------------------
__global__ void __launch_bounds__(256) setx0_kernel()
{
    const int cls = blockIdx.y;
    const float a = g_ab[cls];
    float4* Xo = (float4*)(g_Xa + (size_t)cls*DD);
    const int t = threadIdx.x;
    #pragma unroll
    for (int j = 0; j < 4; j++){
        int id = blockIdx.x*1024 + j*256 + t;
        float4 m = make_float4(0.f, 0.f, 0.f, 0.f);
        int e = id*4, row = e >> 9, c0 = e & (D-1);
        int dg = row - c0;
        if (dg >= 0 && dg < 4) ((float*)&m)[dg] = a;
        Xo[id] = m;
    }
}

// ---------------- batched 512x512x512 GEMM (f32x2 inner) --------------------
// grid (4, 4, C), 256 thr, BM=BN=128, BK=16, 8x8 per thread.
// newton==0: Cg = A*B ;  newton==1: Cg = 2*A - A*B
__global__ void __launch_bounds__(256) gemm512_kernel(const float* __restrict__ Ag,
                                                      const float* __restrict__ Bg,
                                                      float* __restrict__ Cg,
                                                      int newton)
{
    const int cls = blockIdx.z;
    const float* A = Ag + (size_t)cls*DD;
    const float* B = Bg + (size_t)cls*DD;
    float* Cc = Cg + (size_t)cls*DD;
    const int row0 = blockIdx.y*128, col0 = blockIdx.x*128;
    __shared__ float As[16][128];
    __shared__ float Bs[16][128];
    const int t = threadIdx.x;
    const int tx = t & 15, ty = t >> 4;

    u64 acc[8][4];
    #pragma unroll
    for (int i = 0; i < 8; i++)
        #pragma unroll
        for (int q = 0; q < 4; q++) acc[i][q] = 0ull;

    for (int k0 = 0; k0 < D; k0 += 16){
        #pragma unroll
        for (int l = 0; l < 2; l++){
            int id = t + l*256;
            int ar = id >> 2, ak = (id & 3)*4;
            float4 v = *(const float4*)(A + (size_t)(row0+ar)*D + k0 + ak);
            As[ak+0][ar] = v.x; As[ak+1][ar] = v.y; As[ak+2][ar] = v.z; As[ak+3][ar] = v.w;
        }
        #pragma unroll
        for (int l = 0; l < 2; l++){
            int id = t + l*256;
            int bk = id >> 5, bc = (id & 31)*4;
            *(float4*)&Bs[bk][bc] = *(const float4*)(B + (size_t)(k0+bk)*D + col0 + bc);
        }
        __syncthreads();
        #pragma unroll
        for (int k = 0; k < 16; k++){
            float a[8];
            *(float4*)(a)   = *(const float4*)&As[k][ty*8];
            *(float4*)(a+4) = *(const float4*)&As[k][ty*8+4];
            u64 b[4];
            const u64* bp = (const u64*)&Bs[k][tx*8];
            b[0] = bp[0]; b[1] = bp[1]; b[2] = bp[2]; b[3] = bp[3];
            #pragma unroll
            for (int i = 0; i < 8; i++){
                u64 aa = pk2(a[i], a[i]);
                fma2(acc[i][0], aa, b[0]);
                fma2(acc[i][1], aa, b[1]);
                fma2(acc[i][2], aa, b[2]);
                fma2(acc[i][3], aa, b[3]);
            }
        }
        __syncthreads();
    }

    if (!newton){
        #pragma unroll
        for (int i = 0; i < 8; i++){
            u64* cp = (u64*)(Cc + (size_t)(row0+ty*8+i)*D + col0 + tx*8);
            cp[0] = acc[i][0]; cp[1] = acc[i][1]; cp[2] = acc[i][2]; cp[3] = acc[i][3];
        }
    } else {
        #pragma unroll
        for (int i = 0; i < 8; i++){
            const float* arow = A  + (size_t)(row0+ty*8+i)*D + col0 + tx*8;
            float*       crow = Cc + (size_t)(row0+ty*8+i)*D + col0 + tx*8;
            #pragma unroll
            for (int q = 0; q < 4; q++){
                float x, y; upk2(acc[i][q], x, y);
                float2 av = *(const float2*)(arow + 2*q);
                float2 o; o.x = 2.0f*av.x - x; o.y = 2.0f*av.y - y;
                *(float2*)(crow + 2*q) = o;
            }
        }
    }
}

// ---------------- quad phase: T = (X - mu_c) * Lambda_c, row-dot with diff --
// grid (4 col-tiles, 16 row-tiles, C), 256 thr.
__global__ void __launch_bounds__(256) quad_kernel(const float* __restrict__ X,
                                                   const float* __restrict__ muK,
                                                   const float* __restrict__ Lam,
                                                   float* __restrict__ part)
{
    const int cls = blockIdx.z;
    const float* B  = Lam + (size_t)cls*DD;
    const float* mu = muK + (size_t)cls*D;
    const int row0 = blockIdx.y*128, col0 = blockIdx.x*128;
    __shared__ float As[16][128];
    __shared__ float Bs[16][128];
    __shared__ float red[128][17];
    const int t = threadIdx.x;
    const int tx = t & 15, ty = t >> 4;

    u64 acc[8][4];
    #pragma unroll
    for (int i = 0; i < 8; i++)
        #pragma unroll
        for (int q = 0; q < 4; q++) acc[i][q] = 0ull;

    for (int k0 = 0; k0 < D; k0 += 16){
        #pragma unroll
        for (int l = 0; l < 2; l++){
            int id = t + l*256;
            int ar = id >> 2, ak = (id & 3)*4;
            float4 v = *(const float4*)(X + (size_t)(row0+ar)*D + k0 + ak);
            float4 m = *(const float4*)(mu + k0 + ak);
            v.x -= m.x; v.y -= m.y; v.z -= m.z; v.w -= m.w;
            As[ak+0][ar] = v.x; As[ak+1][ar] = v.y; As[ak+2][ar] = v.z; As[ak+3][ar] = v.w;
        }
        #pragma unroll
        for (int l = 0; l < 2; l++){
            int id = t + l*256;
            int bk = id >> 5, bc = (id & 31)*4;
            *(float4*)&Bs[bk][bc] = *(const float4*)(B + (size_t)(k0+bk)*D + col0 + bc);
        }
        __syncthreads();
        #pragma unroll
        for (int k = 0; k < 16; k++){
            float a[8];
            *(float4*)(a)   = *(const float4*)&As[k][ty*8];
            *(float4*)(a+4) = *(const float4*)&As[k][ty*8+4];
            u64 b[4];
            const u64* bp = (const u64*)&Bs[k][tx*8];
            b[0] = bp[0]; b[1] = bp[1]; b[2] = bp[2]; b[3] = bp[3];
            #pragma unroll
            for (int i = 0; i < 8; i++){
                u64 aa = pk2(a[i], a[i]);
                fma2(acc[i][0], aa, b[0]);
                fma2(acc[i][1], aa, b[1]);
                fma2(acc[i][2], aa, b[2]);
                fma2(acc[i][3], aa, b[3]);
            }
        }
        __syncthreads();
    }

    // epilogue: partial quad = sum_j T[n][j] * diff[n][j] over this col tile
    #pragma unroll
    for (int i = 0; i < 8; i++){
        int row = row0 + ty*8 + i;
        float4 x1 = *(const float4*)(X + (size_t)row*D + col0 + tx*8);
        float4 x2 = *(const float4*)(X + (size_t)row*D + col0 + tx*8 + 4);
        float4 m1 = *(const float4*)(mu + col0 + tx*8);
        float4 m2 = *(const float4*)(mu + col0 + tx*8 + 4);
        float a0,a1,a2,a3,a4,a5,a6,a7;
        upk2(acc[i][0], a0, a1); upk2(acc[i][1], a2, a3);
        upk2(acc[i][2], a4, a5); upk2(acc[i][3], a6, a7);
        float p = a0*(x1.x-m1.x) + a1*(x1.y-m1.y) + a2*(x1.z-m1.z) + a3*(x1.w-m1.w)
                + a4*(x2.x-m2.x) + a5*(x2.y-m2.y) + a6*(x2.z-m2.z) + a7*(x2.w-m2.w);
        red[ty*8 + i][tx] = p;
    }
    __syncthreads();
    if (t < 128){
        float s = 0.f;
        #pragma unroll
        for (int q = 0; q < 16; q++) s += red[t][q];
        part[((size_t)blockIdx.x*NX + row0 + t)*C + cls] = s;
    }
}

// ---------------- combine ----------------------------------------------------
__global__ void __launch_bounds__(256) combine_kernel(float* __restrict__ out)
{
    int idx = blockIdx.x*256 + threadIdx.x;
    if (idx >= NX*C) return;
    int c = idx % C;
    float q = g_part[idx] + g_part[NX*C + idx] + g_part[2*NX*C + idx] + g_part[3*NX*C + idx];
    out[idx] = g_base[c] - 0.5f*q;
}

// ---------------- host launcher ----------------------------------------------
extern "C" void kernel_launch(void* const* d_in, const int* in_sizes, int n_in,
                              void* d_out, int out_size)
{
    const float* X      = (const float*)d_in[0];
    const float* muK    = (const float*)d_in[1];
    const float* SigmaK = (const float*)d_in[2];
    const float* Sigma  = (const float*)d_in[3];
    const float* cK     = (const float*)d_in[4];
    float* out = (float*)d_out;

    float *pM, *pXa, *pXb, *pY, *pPart;
    cudaGetSymbolAddress((void**)&pM,    g_M);
    cudaGetSymbolAddress((void**)&pXa,   g_Xa);
    cudaGetSymbolAddress((void**)&pXb,   g_Xb);
    cudaGetSymbolAddress((void**)&pY,    g_Y);
    cudaGetSymbolAddress((void**)&pPart, g_part);

    prep_kernel <<<dim3(64, C), 256>>>(SigmaK, Sigma);
    power_kernel<<<C, 256>>>(cK);
    setx0_kernel<<<dim3(64, C), 256>>>();

    float* cur = pXa; float* nxt = pXb;
    for (int it = 0; it < NEWTON_ITERS; ++it){
        gemm512_kernel<<<dim3(4, 4, C), 256>>>(pM,  cur, pY,  0);  // Y  = M*X
        gemm512_kernel<<<dim3(4, 4, C), 256>>>(cur, pY,  nxt, 1);  // X' = 2X - X*Y
        float* tmp = cur; cur = nxt; nxt = tmp;
    }

    quad_kernel   <<<dim3(4, 16, C), 256>>>(X, muK, cur, pPart);
    combine_kernel<<<(NX*C + 255)/256, 256>>>(out);
}

// round 6
// speedup vs baseline: 2.2294x; 2.2294x over previous
#include <cuda_runtime.h>
#include <cuda_bf16.h>
#include <math.h>
#include <stdint.h>

// ---------------- problem constants ----------------
#define D      512
#define C      100
#define NX     2048
#define DD     (D*D)
#define ALPHA  0.5f
#define SHRINK 1e-4f
#define OMS    (1.0f - SHRINK)

#define NEWTON_ITERS 9
#define POWER_ITERS  10

typedef unsigned int u32;
typedef __nv_bfloat16 bf16;

// ---------------- scratch (device globals; no allocs allowed) ----------------
__device__ float g_W  [C*DD];    // fp32 M (power iter), then Newton W = T*X
__device__ bf16  g_Mhi[C*DD];
__device__ bf16  g_Mlo[C*DD];
__device__ bf16  g_Xhi[C*DD];
__device__ bf16  g_Xlo[C*DD];
__device__ bf16  g_Yhi[C*DD];
__device__ bf16  g_Ylo[C*DD];
__device__ float g_fpart[C*64];
__device__ float g_ab[C];
__device__ float g_base[C];
__device__ float g_part[4*NX*C];

// ---------------- PTX helpers -------------------------------------------------
__device__ __forceinline__ u32 smem_u32(const void* p){
    u32 a; asm("{ .reg .u64 t; cvta.to.shared.u64 t, %1; cvt.u32.u64 %0, t; }" : "=r"(a) : "l"(p));
    return a;
}
#define CPA16(dst, src) \
    asm volatile("cp.async.cg.shared.global [%0], [%1], 16;" :: "r"(dst), "l"(src) : "memory")
#define CP_COMMIT() asm volatile("cp.async.commit_group;" ::: "memory")
#define CP_WAIT1()  asm volatile("cp.async.wait_group 1;" ::: "memory")
#define CP_WAIT0()  asm volatile("cp.async.wait_group 0;" ::: "memory")

#define LDMX4(d0, d1, d2, d3, addr) \
    asm volatile("ldmatrix.sync.aligned.m8n8.x4.shared.b16 {%0,%1,%2,%3}, [%4];" \
        : "=r"(d0), "=r"(d1), "=r"(d2), "=r"(d3) : "r"(addr))

#define MMA(c, a, b) \
    asm volatile("mma.sync.aligned.m16n8k16.row.col.f32.bf16.bf16.f32 " \
        "{%0,%1,%2,%3}, {%4,%5,%6,%7}, {%8,%9}, {%0,%1,%2,%3};" \
        : "+f"((c)[0]), "+f"((c)[1]), "+f"((c)[2]), "+f"((c)[3]) \
        : "r"((a)[0]), "r"((a)[1]), "r"((a)[2]), "r"((a)[3]), "r"((b)[0]), "r"((b)[1]))

// ---------------- smem layout --------------------------------------------------
// Tiles 128 rows x 32 bf16, padded to 40 elems (80B) per row -> 10240B per tile.
// Stage: [Ahi][Alo][Bhi][Blo] = 40960B.  Two stages = 81920B dynamic smem.
#define ROWB    80
#define TILE_B  10240
#define STAGE_B 40960
#define SMEM_DYN (2*STAGE_B)

__device__ __forceinline__ u32 pack_bf2(bf16 a, bf16 b){
    __nv_bfloat162 v = __halves2bfloat162(a, b);
    return *(u32*)&v;
}
__device__ __forceinline__ void split2(float a, float b, u32& h, u32& l){
    bf16 ha = __float2bfloat16(a), hb = __float2bfloat16(b);
    bf16 la = __float2bfloat16(a - __bfloat162float(ha));
    bf16 lb = __float2bfloat16(b - __bfloat162float(hb));
    h = pack_bf2(ha, hb); l = pack_bf2(la, lb);
}

// ---------------- loaders ------------------------------------------------------
// cp.async one 128x32 bf16 tile (K-major, gmem row stride D) into padded smem
__device__ __forceinline__ void cpa_tile(u32 sdst, const bf16* __restrict__ g,
                                         int row0, int k0, int t){
    int r = t >> 1, half = t & 1;
    const bf16* src = g + (size_t)(row0 + r)*D + k0 + half*16;
    u32 dst = sdst + r*ROWB + half*32;
    CPA16(dst,      src);
    CPA16(dst + 16, src + 8);
}

// diff = X - mu, split to bf16 hi/lo, STS into padded smem (quad A operand)
__device__ __forceinline__ void conv_diff_p(char* sdst, const float* __restrict__ X,
                                            const float* __restrict__ mu,
                                            int row0, int k0, int t){
    int r = t >> 1, half = t & 1;
    const float4* xs = (const float4*)(X + (size_t)(row0 + r)*D + k0 + half*16);
    const float4* ms = (const float4*)(mu + k0 + half*16);
    alignas(16) bf16 h[16], l[16];
    #pragma unroll
    for (int q = 0; q < 4; q++){
        float4 x = xs[q], m = ms[q];
        float v[4] = {x.x-m.x, x.y-m.y, x.z-m.z, x.w-m.w};
        #pragma unroll
        for (int j = 0; j < 4; j++){
            h[q*4+j] = __float2bfloat16(v[j]);
            l[q*4+j] = __float2bfloat16(v[j] - __bfloat162float(h[q*4+j]));
        }
    }
    char* dh = sdst + r*ROWB + half*32;
    char* dl = dh + TILE_B;
    *(uint4*)dh        = *(const uint4*)h;
    *(uint4*)(dh + 16) = *(const uint4*)(h + 8);
    *(uint4*)dl        = *(const uint4*)l;
    *(uint4*)(dl + 16) = *(const uint4*)(l + 8);
}

// ---------------- warp-tile compute (BK=32 chunk) ------------------------------
// acc[ma][na][4]; A tiles at stage+0 (hi) / +TILE_B (lo); B at +2T (hi) / +3T (lo)
__device__ __forceinline__ void compute_chunk2(float acc[2][8][4], u32 stage,
                                               int warp_m, int warp_n, int lane){
    const u32 aoff = stage + (warp_m*32 + (lane & 15))*ROWB + (lane >> 4)*16;
    const u32 boff = stage + 2*TILE_B
                   + (warp_n*64 + (lane & 7) + ((lane >> 4) << 3))*ROWB
                   + ((lane >> 3) & 1)*16;
    #pragma unroll
    for (int ks = 0; ks < 2; ks++){
        u32 ah[2][4], al[2][4], bh[8][2], bl[8][2];
        #pragma unroll
        for (int ma = 0; ma < 2; ma++){
            LDMX4(ah[ma][0], ah[ma][1], ah[ma][2], ah[ma][3], aoff + ma*1280 + ks*32);
            LDMX4(al[ma][0], al[ma][1], al[ma][2], al[ma][3], aoff + TILE_B + ma*1280 + ks*32);
        }
        #pragma unroll
        for (int p = 0; p < 4; p++){
            LDMX4(bh[2*p][0], bh[2*p][1], bh[2*p+1][0], bh[2*p+1][1], boff + p*1280 + ks*32);
            LDMX4(bl[2*p][0], bl[2*p][1], bl[2*p+1][0], bl[2*p+1][1], boff + TILE_B + p*1280 + ks*32);
        }
        #pragma unroll
        for (int ma = 0; ma < 2; ma++)
            #pragma unroll
            for (int na = 0; na < 8; na++){
                MMA(acc[ma][na], ah[ma], bh[na]);
                MMA(acc[ma][na], ah[ma], bl[na]);
                MMA(acc[ma][na], al[ma], bh[na]);
            }
    }
}

// ---------------- prep: build M fp32 + split, Frobenius partials ---------------
__global__ void __launch_bounds__(256) prep_kernel(const float* __restrict__ SigmaK,
                                                   const float* __restrict__ Sigma)
{
    const int cls = blockIdx.y;
    const int t   = threadIdx.x;
    const size_t co = (size_t)cls*DD;
    const float4* Sk = (const float4*)(SigmaK + co);
    const float4* Sg = (const float4*)Sigma;
    float4* Mo = (float4*)(g_W + co);
    float fr = 0.f;
    #pragma unroll
    for (int j = 0; j < 4; j++){
        int id = blockIdx.x*1024 + j*256 + t;
        float4 a = Sk[id], b = Sg[id];
        float4 r;
        r.x = ALPHA*a.x + (1.0f-ALPHA)*b.x;
        r.y = ALPHA*a.y + (1.0f-ALPHA)*b.y;
        r.z = ALPHA*a.z + (1.0f-ALPHA)*b.z;
        r.w = ALPHA*a.w + (1.0f-ALPHA)*b.w;
        fr += r.x*r.x + r.y*r.y + r.z*r.z + r.w*r.w;
        float4 m;
        m.x = OMS*r.x; m.y = OMS*r.y; m.z = OMS*r.z; m.w = OMS*r.w;
        int e = id*4, row = e >> 9, c0 = e & (D-1);
        int dg = row - c0;
        if (dg >= 0 && dg < 4) ((float*)&m)[dg] += SHRINK;
        Mo[id] = m;
        alignas(8) bf16 hh[4], ll[4];
        #pragma unroll
        for (int q = 0; q < 4; q++){
            float v = ((float*)&m)[q];
            hh[q] = __float2bfloat16(v);
            ll[q] = __float2bfloat16(v - __bfloat162float(hh[q]));
        }
        *(uint2*)(g_Mhi + co + e) = *(const uint2*)hh;
        *(uint2*)(g_Mlo + co + e) = *(const uint2*)ll;
    }
    __shared__ float red[256];
    red[t] = fr; __syncthreads();
    for (int s = 128; s > 0; s >>= 1){ if (t < s) red[t] += red[t+s]; __syncthreads(); }
    if (t == 0) g_fpart[cls*64 + blockIdx.x] = red[0];
}

// ---------------- power iteration + per-class constants ------------------------
__global__ void __launch_bounds__(256) power_kernel(const float* __restrict__ cK)
{
    const int cls  = blockIdx.x;
    const int t    = threadIdx.x;
    const int lane = t & 31, warp = t >> 5;
    const float* Mc = g_W + (size_t)cls*DD;
    __shared__ float v[D], w[D], red[256];

    float x = (t < 64) ? g_fpart[cls*64 + t] : 0.f;
    red[t] = x; __syncthreads();
    for (int s = 128; s > 0; s >>= 1){ if (t < s) red[t] += red[t+s]; __syncthreads(); }
    float frobsq = red[0]; __syncthreads();

    float ckv = (t < C) ? cK[t] : 0.f;
    red[t] = ckv; __syncthreads();
    for (int s = 128; s > 0; s >>= 1){ if (t < s) red[t] += red[t+s]; __syncthreads(); }
    float csum = red[0]; __syncthreads();

    for (int i = t; i < D; i += 256) v[i] = 1.0f;
    __syncthreads();

    float lam = 1.0f;
    for (int it = 0; it < POWER_ITERS; ++it){
        for (int r = warp; r < D; r += 8){
            float s = 0.f;
            const float* Mr = Mc + (size_t)r*D;
            for (int k = lane; k < D; k += 32) s += Mr[k]*v[k];
            #pragma unroll
            for (int o = 16; o > 0; o >>= 1) s += __shfl_down_sync(0xffffffffu, s, o);
            if (lane == 0) w[r] = s;
        }
        __syncthreads();
        float ns = 0.f;
        for (int i = t; i < D; i += 256) ns += w[i]*w[i];
        red[t] = ns; __syncthreads();
        for (int s = 128; s > 0; s >>= 1){ if (t < s) red[t] += red[t+s]; __syncthreads(); }
        lam = sqrtf(red[0]); __syncthreads();
        float inv = 1.0f/lam;
        for (int i = t; i < D; i += 256) v[i] = w[i]*inv;
        __syncthreads();
    }

    if (t == 0){
        float bound = 1.35f*lam + 0.3f;
        g_ab[cls] = 2.0f/(0.09f + bound);
        float c0 = cK[cls];
        g_base[cls] = (c0 > 0.f) ? (logf(c0/csum) - 0.25f*logf(frobsq)) : -INFINITY;
    }
}

// ---------------- X0 = a*I in split bf16 ---------------------------------------
__global__ void __launch_bounds__(256) setx0_kernel()
{
    const int cls = blockIdx.y;
    const size_t co = (size_t)cls*DD;
    const float a = g_ab[cls];
    bf16 ahi = __float2bfloat16(a);
    bf16 alo = __float2bfloat16(a - __bfloat162float(ahi));
    const int t = threadIdx.x;
    #pragma unroll
    for (int j = 0; j < 4; j++){
        int id = blockIdx.x*1024 + j*256 + t;
        alignas(8) bf16 hh[4] = {bf16(0.f), bf16(0.f), bf16(0.f), bf16(0.f)};
        alignas(8) bf16 ll[4] = {bf16(0.f), bf16(0.f), bf16(0.f), bf16(0.f)};
        int e = id*4, row = e >> 9, c0 = e & (D-1);
        int dg = row - c0;
        if (dg >= 0 && dg < 4){ hh[dg] = ahi; ll[dg] = alo; }
        *(uint2*)(g_Xhi + co + e) = *(const uint2*)hh;
        *(uint2*)(g_Xlo + co + e) = *(const uint2*)ll;
    }
}

// ---------------- Newton GEMM (mma.sync, split-bf16) ---------------------------
// mode 0: grid (16,1,C), full;  Out hi/lo = A * B^T  (split-bf16 store)
// mode 1: grid (10,1,C), lower-triangle tiles only;  OW = A * B^T (fp32 store)
__global__ void __launch_bounds__(256, 1) mma_newton_kernel(
    const bf16* __restrict__ Ahi, const bf16* __restrict__ Alo,
    const bf16* __restrict__ Bhi, const bf16* __restrict__ Blo,
    bf16* __restrict__ Ohi, bf16* __restrict__ Olo,
    float* __restrict__ OW, int mode)
{
    extern __shared__ char smem[];
    const u32 sb = smem_u32(smem);
    const int t = threadIdx.x, lane = t & 31, wid = t >> 5;
    const int warp_m = wid & 3, warp_n = wid >> 2;
    const int cls = blockIdx.z;
    const size_t co = (size_t)cls*DD;

    int bi, bj;
    if (mode == 1){
        int i = blockIdx.x; bi = 0;
        while (i >= bi + 1){ i -= bi + 1; bi++; }
        bj = i;
    } else { bi = blockIdx.x >> 2; bj = blockIdx.x & 3; }
    const int row0 = bi*128, col0 = bj*128;

    const bf16* Ah = Ahi + co; const bf16* Al = Alo + co;
    const bf16* Bh = Bhi + co; const bf16* Bl = Blo + co;

    float acc[2][8][4];
    #pragma unroll
    for (int ma = 0; ma < 2; ma++)
        #pragma unroll
        for (int na = 0; na < 8; na++)
            #pragma unroll
            for (int q = 0; q < 4; q++) acc[ma][na][q] = 0.f;

    // prefetch chunk 0
    cpa_tile(sb,            Ah, row0, 0, t);
    cpa_tile(sb +   TILE_B, Al, row0, 0, t);
    cpa_tile(sb + 2*TILE_B, Bh, col0, 0, t);
    cpa_tile(sb + 3*TILE_B, Bl, col0, 0, t);
    CP_COMMIT();

    for (int c = 0; c < 16; ++c){
        if (c + 1 < 16){
            u32 st = sb + ((c+1) & 1)*STAGE_B;
            int k0 = (c+1)*32;
            cpa_tile(st,            Ah, row0, k0, t);
            cpa_tile(st +   TILE_B, Al, row0, k0, t);
            cpa_tile(st + 2*TILE_B, Bh, col0, k0, t);
            cpa_tile(st + 3*TILE_B, Bl, col0, k0, t);
            CP_COMMIT();
            CP_WAIT1();
        } else {
            CP_WAIT0();
        }
        __syncthreads();
        compute_chunk2(acc, sb + (c & 1)*STAGE_B, warp_m, warp_n, lane);
        __syncthreads();
    }

    // epilogue
    const int g = lane >> 2, tig = lane & 3;
    #pragma unroll
    for (int ma = 0; ma < 2; ma++){
        #pragma unroll
        for (int na = 0; na < 8; na++){
            const float* cc = acc[ma][na];
            int r0 = row0 + warp_m*32 + ma*16 + g;
            int col = col0 + warp_n*64 + na*8 + 2*tig;
            if (mode == 0){
                u32 h0, l0, h1, l1;
                split2(cc[0], cc[1], h0, l0);
                split2(cc[2], cc[3], h1, l1);
                *(u32*)(Ohi + co + (size_t)r0*D + col)       = h0;
                *(u32*)(Olo + co + (size_t)r0*D + col)       = l0;
                *(u32*)(Ohi + co + (size_t)(r0+8)*D + col)   = h1;
                *(u32*)(Olo + co + (size_t)(r0+8)*D + col)   = l1;
            } else {
                *(float2*)(OW + co + (size_t)r0*D + col)     = make_float2(cc[0], cc[1]);
                *(float2*)(OW + co + (size_t)(r0+8)*D + col) = make_float2(cc[2], cc[3]);
            }
        }
    }
}

// ---------------- quad kernel: out = diff * Lambda^T, row-dot with diff --------
__global__ void __launch_bounds__(256, 1) mma_quad_kernel(
    const float* __restrict__ X, const float* __restrict__ muK,
    const bf16* __restrict__ Lhi, const bf16* __restrict__ Llo,
    float* __restrict__ part)
{
    extern __shared__ char smem[];
    const u32 sb = smem_u32(smem);
    const int t = threadIdx.x, lane = t & 31, wid = t >> 5;
    const int warp_m = wid & 3, warp_n = wid >> 2;
    const int cls = blockIdx.z;
    const size_t co = (size_t)cls*DD;
    const float* mu = muK + (size_t)cls*D;
    const int row0 = blockIdx.y*128, col0 = blockIdx.x*128;

    const bf16* Bh = Lhi + co; const bf16* Bl = Llo + co;

    float acc[2][8][4];
    #pragma unroll
    for (int ma = 0; ma < 2; ma++)
        #pragma unroll
        for (int na = 0; na < 8; na++)
            #pragma unroll
            for (int q = 0; q < 4; q++) acc[ma][na][q] = 0.f;

    cpa_tile(sb + 2*TILE_B, Bh, col0, 0, t);
    cpa_tile(sb + 3*TILE_B, Bl, col0, 0, t);
    CP_COMMIT();
    conv_diff_p(smem, X, mu, row0, 0, t);

    for (int c = 0; c < 16; ++c){
        if (c + 1 < 16){
            int s1 = (c+1) & 1;
            int k0 = (c+1)*32;
            cpa_tile(sb + s1*STAGE_B + 2*TILE_B, Bh, col0, k0, t);
            cpa_tile(sb + s1*STAGE_B + 3*TILE_B, Bl, col0, k0, t);
            CP_COMMIT();
            conv_diff_p(smem + s1*STAGE_B, X, mu, row0, k0, t);
            CP_WAIT1();
        } else {
            CP_WAIT0();
        }
        __syncthreads();
        compute_chunk2(acc, sb + (c & 1)*STAGE_B, warp_m, warp_n, lane);
        __syncthreads();
    }

    // epilogue: per-row dot with diff over this 128-col block
    const int g = lane >> 2, tig = lane & 3;
    float* sred = (float*)smem;   // [128][2]
    __syncthreads();

    #pragma unroll
    for (int ma = 0; ma < 2; ma++){
        float p0 = 0.f, p1 = 0.f;   // rows g and g+8 of this ma atom
        int r0 = row0 + warp_m*32 + ma*16 + g;
        int r1 = r0 + 8;
        #pragma unroll
        for (int na = 0; na < 8; na++){
            int col = col0 + warp_n*64 + na*8 + 2*tig;
            float m0 = mu[col], m1 = mu[col+1];
            float d00 = X[(size_t)r0*D + col]   - m0;
            float d01 = X[(size_t)r0*D + col+1] - m1;
            float d10 = X[(size_t)r1*D + col]   - m0;
            float d11 = X[(size_t)r1*D + col+1] - m1;
            const float* cc = acc[ma][na];
            p0 += cc[0]*d00 + cc[1]*d01;
            p1 += cc[2]*d10 + cc[3]*d11;
        }
        p0 += __shfl_down_sync(0xffffffffu, p0, 2);
        p0 += __shfl_down_sync(0xffffffffu, p0, 1);
        p1 += __shfl_down_sync(0xffffffffu, p1, 2);
        p1 += __shfl_down_sync(0xffffffffu, p1, 1);
        if (tig == 0){
            int rl0 = warp_m*32 + ma*16 + g;
            sred[rl0*2 + warp_n]     = p0;
            sred[(rl0+8)*2 + warp_n] = p1;
        }
    }
    __syncthreads();
    if (t < 128){
        float s = sred[t*2] + sred[t*2 + 1];
        part[((size_t)blockIdx.x*NX + row0 + t)*C + cls] = s;
    }
}

// ---------------- symsplit: X' = split(sym(2X - W)), lower->mirror -------------
// grid (136, C), 256 thr; block handles 32x32 lower tile (I,J), writes (I,J)+(J,I)
__global__ void __launch_bounds__(256) symsplit_kernel(const float* __restrict__ W,
                                                       const bf16* __restrict__ Xh,
                                                       const bf16* __restrict__ Xl,
                                                       bf16* __restrict__ Ohi,
                                                       bf16* __restrict__ Olo)
{
    __shared__ float sv[32][33];
    const int cls = blockIdx.y;
    const size_t co = (size_t)cls*DD;
    int i = blockIdx.x, I = 0;
    while (i >= I + 1){ i -= I + 1; I++; }
    const int J = i;
    const int t = threadIdx.x;
    const int tx = t & 31, ty = t >> 5;

    #pragma unroll
    for (int q = 0; q < 4; q++){
        int r = I*32 + ty + q*8, c = J*32 + tx;
        size_t idx = co + (size_t)r*D + c;
        float x = __bfloat162float(Xh[idx]) + __bfloat162float(Xl[idx]);
        sv[ty + q*8][tx] = 2.0f*x - W[idx];
    }
    __syncthreads();

    if (I != J){
        #pragma unroll
        for (int q = 0; q < 4; q++){
            int rl = ty + q*8;
            float v = sv[rl][tx];
            bf16 h = __float2bfloat16(v);
            size_t idx = co + (size_t)(I*32 + rl)*D + J*32 + tx;
            Ohi[idx] = h; Olo[idx] = __float2bfloat16(v - __bfloat162float(h));
            float vt = sv[tx][rl];
            bf16 ht = __float2bfloat16(vt);
            size_t idt = co + (size_t)(J*32 + rl)*D + I*32 + tx;
            Ohi[idt] = ht; Olo[idt] = __float2bfloat16(vt - __bfloat162float(ht));
        }
    } else {
        #pragma unroll
        for (int q = 0; q < 4; q++){
            int rl = ty + q*8;
            float v = (rl >= tx) ? sv[rl][tx] : sv[tx][rl];
            bf16 h = __float2bfloat16(v);
            size_t idx = co + (size_t)(I*32 + rl)*D + J*32 + tx;
            Ohi[idx] = h; Olo[idx] = __float2bfloat16(v - __bfloat162float(h));
        }
    }
}

// ---------------- combine ------------------------------------------------------
__global__ void __launch_bounds__(256) combine_kernel(float* __restrict__ out)
{
    int idx = blockIdx.x*256 + threadIdx.x;
    if (idx >= NX*C) return;
    int c = idx % C;
    float q = g_part[idx] + g_part[NX*C + idx] + g_part[2*NX*C + idx] + g_part[3*NX*C + idx];
    out[idx] = g_base[c] - 0.5f*q;
}

// ---------------- host launcher ------------------------------------------------
extern "C" void kernel_launch(void* const* d_in, const int* in_sizes, int n_in,
                              void* d_out, int out_size)
{
    const float* X      = (const float*)d_in[0];
    const float* muK    = (const float*)d_in[1];
    const float* SigmaK = (const float*)d_in[2];
    const float* Sigma  = (const float*)d_in[3];
    const float* cK     = (const float*)d_in[4];
    float* out = (float*)d_out;

    float *pW, *pPart;
    bf16 *pMhi, *pMlo, *pXhi, *pXlo, *pYhi, *pYlo;
    cudaGetSymbolAddress((void**)&pW,    g_W);
    cudaGetSymbolAddress((void**)&pMhi,  g_Mhi);
    cudaGetSymbolAddress((void**)&pMlo,  g_Mlo);
    cudaGetSymbolAddress((void**)&pXhi,  g_Xhi);
    cudaGetSymbolAddress((void**)&pXlo,  g_Xlo);
    cudaGetSymbolAddress((void**)&pYhi,  g_Yhi);
    cudaGetSymbolAddress((void**)&pYlo,  g_Ylo);
    cudaGetSymbolAddress((void**)&pPart, g_part);

    cudaFuncSetAttribute(mma_newton_kernel, cudaFuncAttributeMaxDynamicSharedMemorySize, SMEM_DYN);
    cudaFuncSetAttribute(mma_quad_kernel,   cudaFuncAttributeMaxDynamicSharedMemorySize, SMEM_DYN);

    prep_kernel <<<dim3(64, C), 256>>>(SigmaK, Sigma);
    power_kernel<<<C, 256>>>(cK);
    setx0_kernel<<<dim3(64, C), 256>>>();

    for (int it = 0; it < NEWTON_ITERS; ++it){
        // T = X * M^T = X*M (M sym)  -> Yhi/Ylo  (full 16 tiles)
        mma_newton_kernel<<<dim3(16, 1, C), 256, SMEM_DYN>>>(
            pXhi, pXlo, pMhi, pMlo, pYhi, pYlo, (float*)0, 0);
        // W = T * X^T = T*X = XMX (X sym) -> fp32, lower-triangle tiles only
        mma_newton_kernel<<<dim3(10, 1, C), 256, SMEM_DYN>>>(
            pYhi, pYlo, pXhi, pXlo, (bf16*)0, (bf16*)0, pW, 1);
        // X = split(sym(2X - W))
        symsplit_kernel<<<dim3(136, C), 256>>>(pW, pXhi, pXlo, pXhi, pXlo);
    }

    mma_quad_kernel<<<dim3(4, 16, C), 256, SMEM_DYN>>>(X, muK, pXhi, pXlo, pPart);
    combine_kernel <<<(NX*C + 255)/256, 256>>>(out);
}

// round 7
// speedup vs baseline: 2.6565x; 1.1916x over previous
#include <cuda_runtime.h>
#include <cuda_bf16.h>
#include <math.h>
#include <stdint.h>

// ---------------- problem constants ----------------
#define D      512
#define C      100
#define NX     2048
#define DD     (D*D)
#define ALPHA  0.5f
#define SHRINK 1e-4f
#define OMS    (1.0f - SHRINK)

#define NEWTON_ITERS 9
#define POWER_ITERS  10

typedef unsigned int u32;
typedef __nv_bfloat16 bf16;

// ---------------- scratch (device globals; no allocs allowed) ----------------
__device__ float g_W  [C*DD];    // fp32 M (power iter), then Newton W = T*X
__device__ bf16  g_Mhi[C*DD];
__device__ bf16  g_Mlo[C*DD];
__device__ bf16  g_Xhi[C*DD];
__device__ bf16  g_Xlo[C*DD];
__device__ bf16  g_Yhi[C*DD];
__device__ bf16  g_Ylo[C*DD];
__device__ float g_fpart[C*64];
__device__ float g_ab[C];
__device__ float g_base[C];
__device__ float g_part[4*NX*C];

// ---------------- PTX helpers -------------------------------------------------
__device__ __forceinline__ u32 smem_u32(const void* p){
    u32 a; asm("{ .reg .u64 t; cvta.to.shared.u64 t, %1; cvt.u32.u64 %0, t; }" : "=r"(a) : "l"(p));
    return a;
}
#define CPA16(dst, src) \
    asm volatile("cp.async.cg.shared.global [%0], [%1], 16;" :: "r"(dst), "l"(src) : "memory")
#define CP_COMMIT() asm volatile("cp.async.commit_group;" ::: "memory")
#define CP_WAIT1()  asm volatile("cp.async.wait_group 1;" ::: "memory")
#define CP_WAIT0()  asm volatile("cp.async.wait_group 0;" ::: "memory")

#define LDMX4(d0, d1, d2, d3, addr) \
    asm volatile("ldmatrix.sync.aligned.m8n8.x4.shared.b16 {%0,%1,%2,%3}, [%4];" \
        : "=r"(d0), "=r"(d1), "=r"(d2), "=r"(d3) : "r"(addr))

#define MMA(c, a, b) \
    asm volatile("mma.sync.aligned.m16n8k16.row.col.f32.bf16.bf16.f32 " \
        "{%0,%1,%2,%3}, {%4,%5,%6,%7}, {%8,%9}, {%0,%1,%2,%3};" \
        : "+f"((c)[0]), "+f"((c)[1]), "+f"((c)[2]), "+f"((c)[3]) \
        : "r"((a)[0]), "r"((a)[1]), "r"((a)[2]), "r"((a)[3]), "r"((b)[0]), "r"((b)[1]))

// ---------------- smem layout --------------------------------------------------
// Tiles 128 rows x 32 bf16, padded to 40 elems (80B) per row -> 10240B per tile.
// Stage: [Ahi][Alo][Bhi][Blo] = 40960B.  Two stages = 81920B dynamic smem.
#define ROWB    80
#define TILE_B  10240
#define STAGE_B 40960
#define SMEM_DYN (2*STAGE_B)

__device__ __forceinline__ u32 pack_bf2(bf16 a, bf16 b){
    __nv_bfloat162 v = __halves2bfloat162(a, b);
    return *(u32*)&v;
}
__device__ __forceinline__ void split2(float a, float b, u32& h, u32& l){
    bf16 ha = __float2bfloat16(a), hb = __float2bfloat16(b);
    bf16 la = __float2bfloat16(a - __bfloat162float(ha));
    bf16 lb = __float2bfloat16(b - __bfloat162float(hb));
    h = pack_bf2(ha, hb); l = pack_bf2(la, lb);
}

// ---------------- loaders ------------------------------------------------------
// cp.async one 128x32 bf16 tile (K-major, gmem row stride D) into padded smem
__device__ __forceinline__ void cpa_tile(u32 sdst, const bf16* __restrict__ g,
                                         int row0, int k0, int t){
    int r = t >> 1, half = t & 1;
    const bf16* src = g + (size_t)(row0 + r)*D + k0 + half*16;
    u32 dst = sdst + r*ROWB + half*32;
    CPA16(dst,      src);
    CPA16(dst + 16, src + 8);
}

// diff = X - mu, split to bf16 hi/lo, STS into padded smem (quad A operand)
__device__ __forceinline__ void conv_diff_p(char* sdst, const float* __restrict__ X,
                                            const float* __restrict__ mu,
                                            int row0, int k0, int t){
    int r = t >> 1, half = t & 1;
    const float4* xs = (const float4*)(X + (size_t)(row0 + r)*D + k0 + half*16);
    const float4* ms = (const float4*)(mu + k0 + half*16);
    alignas(16) bf16 h[16], l[16];
    #pragma unroll
    for (int q = 0; q < 4; q++){
        float4 x = xs[q], m = ms[q];
        float v[4] = {x.x-m.x, x.y-m.y, x.z-m.z, x.w-m.w};
        #pragma unroll
        for (int j = 0; j < 4; j++){
            h[q*4+j] = __float2bfloat16(v[j]);
            l[q*4+j] = __float2bfloat16(v[j] - __bfloat162float(h[q*4+j]));
        }
    }
    char* dh = sdst + r*ROWB + half*32;
    char* dl = dh + TILE_B;
    *(uint4*)dh        = *(const uint4*)h;
    *(uint4*)(dh + 16) = *(const uint4*)(h + 8);
    *(uint4*)dl        = *(const uint4*)l;
    *(uint4*)(dl + 16) = *(const uint4*)(l + 8);
}

// ---------------- warp-tile compute (BK=32 chunk) ------------------------------
// Register-lean ordering: keep only one B-set (hi OR lo) live at a time.
// acc[ma][na][4]; A tiles at stage+0 (hi) / +TILE_B (lo); B at +2T (hi) / +3T (lo)
__device__ __forceinline__ void compute_chunk2(float acc[2][8][4], u32 stage,
                                               int warp_m, int warp_n, int lane){
    const u32 aoff = stage + (warp_m*32 + (lane & 15))*ROWB + (lane >> 4)*16;
    const u32 boff = stage + 2*TILE_B
                   + (warp_n*64 + (lane & 7) + ((lane >> 4) << 3))*ROWB
                   + ((lane >> 3) & 1)*16;
    #pragma unroll
    for (int ks = 0; ks < 2; ks++){
        u32 ah[2][4], al[2][4], b[8][2];
        #pragma unroll
        for (int ma = 0; ma < 2; ma++){
            LDMX4(ah[ma][0], ah[ma][1], ah[ma][2], ah[ma][3], aoff + ma*1280 + ks*32);
            LDMX4(al[ma][0], al[ma][1], al[ma][2], al[ma][3], aoff + TILE_B + ma*1280 + ks*32);
        }
        // B-hi pass: Ah*Bh + Al*Bh
        #pragma unroll
        for (int p = 0; p < 4; p++)
            LDMX4(b[2*p][0], b[2*p][1], b[2*p+1][0], b[2*p+1][1], boff + p*1280 + ks*32);
        #pragma unroll
        for (int ma = 0; ma < 2; ma++)
            #pragma unroll
            for (int na = 0; na < 8; na++){
                MMA(acc[ma][na], ah[ma], b[na]);
                MMA(acc[ma][na], al[ma], b[na]);
            }
        // B-lo pass: Ah*Bl (reuse b registers)
        #pragma unroll
        for (int p = 0; p < 4; p++)
            LDMX4(b[2*p][0], b[2*p][1], b[2*p+1][0], b[2*p+1][1], boff + TILE_B + p*1280 + ks*32);
        #pragma unroll
        for (int ma = 0; ma < 2; ma++)
            #pragma unroll
            for (int na = 0; na < 8; na++)
                MMA(acc[ma][na], ah[ma], b[na]);
    }
}

// ---------------- prep: build M fp32 + split, Frobenius partials ---------------
__global__ void __launch_bounds__(256) prep_kernel(const float* __restrict__ SigmaK,
                                                   const float* __restrict__ Sigma)
{
    const int cls = blockIdx.y;
    const int t   = threadIdx.x;
    const size_t co = (size_t)cls*DD;
    const float4* Sk = (const float4*)(SigmaK + co);
    const float4* Sg = (const float4*)Sigma;
    float4* Mo = (float4*)(g_W + co);
    float fr = 0.f;
    #pragma unroll
    for (int j = 0; j < 4; j++){
        int id = blockIdx.x*1024 + j*256 + t;
        float4 a = Sk[id], b = Sg[id];
        float4 r;
        r.x = ALPHA*a.x + (1.0f-ALPHA)*b.x;
        r.y = ALPHA*a.y + (1.0f-ALPHA)*b.y;
        r.z = ALPHA*a.z + (1.0f-ALPHA)*b.z;
        r.w = ALPHA*a.w + (1.0f-ALPHA)*b.w;
        fr += r.x*r.x + r.y*r.y + r.z*r.z + r.w*r.w;
        float4 m;
        m.x = OMS*r.x; m.y = OMS*r.y; m.z = OMS*r.z; m.w = OMS*r.w;
        int e = id*4, row = e >> 9, c0 = e & (D-1);
        int dg = row - c0;
        if (dg >= 0 && dg < 4) ((float*)&m)[dg] += SHRINK;
        Mo[id] = m;
        alignas(8) bf16 hh[4], ll[4];
        #pragma unroll
        for (int q = 0; q < 4; q++){
            float v = ((float*)&m)[q];
            hh[q] = __float2bfloat16(v);
            ll[q] = __float2bfloat16(v - __bfloat162float(hh[q]));
        }
        *(uint2*)(g_Mhi + co + e) = *(const uint2*)hh;
        *(uint2*)(g_Mlo + co + e) = *(const uint2*)ll;
    }
    __shared__ float red[256];
    red[t] = fr; __syncthreads();
    for (int s = 128; s > 0; s >>= 1){ if (t < s) red[t] += red[t+s]; __syncthreads(); }
    if (t == 0) g_fpart[cls*64 + blockIdx.x] = red[0];
}

// ---------------- power iteration + per-class constants ------------------------
__global__ void __launch_bounds__(256) power_kernel(const float* __restrict__ cK)
{
    const int cls  = blockIdx.x;
    const int t    = threadIdx.x;
    const int lane = t & 31, warp = t >> 5;
    const float* Mc = g_W + (size_t)cls*DD;
    __shared__ float v[D], w[D], red[256];

    float x = (t < 64) ? g_fpart[cls*64 + t] : 0.f;
    red[t] = x; __syncthreads();
    for (int s = 128; s > 0; s >>= 1){ if (t < s) red[t] += red[t+s]; __syncthreads(); }
    float frobsq = red[0]; __syncthreads();

    float ckv = (t < C) ? cK[t] : 0.f;
    red[t] = ckv; __syncthreads();
    for (int s = 128; s > 0; s >>= 1){ if (t < s) red[t] += red[t+s]; __syncthreads(); }
    float csum = red[0]; __syncthreads();

    for (int i = t; i < D; i += 256) v[i] = 1.0f;
    __syncthreads();

    float lam = 1.0f;
    for (int it = 0; it < POWER_ITERS; ++it){
        for (int r = warp; r < D; r += 8){
            float s = 0.f;
            const float* Mr = Mc + (size_t)r*D;
            for (int k = lane; k < D; k += 32) s += Mr[k]*v[k];
            #pragma unroll
            for (int o = 16; o > 0; o >>= 1) s += __shfl_down_sync(0xffffffffu, s, o);
            if (lane == 0) w[r] = s;
        }
        __syncthreads();
        float ns = 0.f;
        for (int i = t; i < D; i += 256) ns += w[i]*w[i];
        red[t] = ns; __syncthreads();
        for (int s = 128; s > 0; s >>= 1){ if (t < s) red[t] += red[t+s]; __syncthreads(); }
        lam = sqrtf(red[0]); __syncthreads();
        float inv = 1.0f/lam;
        for (int i = t; i < D; i += 256) v[i] = w[i]*inv;
        __syncthreads();
    }

    if (t == 0){
        float bound = 1.35f*lam + 0.3f;
        g_ab[cls] = 2.0f/(0.09f + bound);
        float c0 = cK[cls];
        g_base[cls] = (c0 > 0.f) ? (logf(c0/csum) - 0.25f*logf(frobsq)) : -INFINITY;
    }
}

// ---------------- X0 = a*I in split bf16 ---------------------------------------
__global__ void __launch_bounds__(256) setx0_kernel()
{
    const int cls = blockIdx.y;
    const size_t co = (size_t)cls*DD;
    const float a = g_ab[cls];
    bf16 ahi = __float2bfloat16(a);
    bf16 alo = __float2bfloat16(a - __bfloat162float(ahi));
    const int t = threadIdx.x;
    #pragma unroll
    for (int j = 0; j < 4; j++){
        int id = blockIdx.x*1024 + j*256 + t;
        alignas(8) bf16 hh[4] = {bf16(0.f), bf16(0.f), bf16(0.f), bf16(0.f)};
        alignas(8) bf16 ll[4] = {bf16(0.f), bf16(0.f), bf16(0.f), bf16(0.f)};
        int e = id*4, row = e >> 9, c0 = e & (D-1);
        int dg = row - c0;
        if (dg >= 0 && dg < 4){ hh[dg] = ahi; ll[dg] = alo; }
        *(uint2*)(g_Xhi + co + e) = *(const uint2*)hh;
        *(uint2*)(g_Xlo + co + e) = *(const uint2*)ll;
    }
}

// ---------------- Newton GEMM (mma.sync, split-bf16) ---------------------------
// mode 0: grid (16,1,C), full;  Out hi/lo = A * B^T  (split-bf16 store)
// mode 1: grid (10,1,C), lower-triangle tiles only;  OW = A * B^T (fp32 store)
__global__ void __launch_bounds__(256, 2) mma_newton_kernel(
    const bf16* __restrict__ Ahi, const bf16* __restrict__ Alo,
    const bf16* __restrict__ Bhi, const bf16* __restrict__ Blo,
    bf16* __restrict__ Ohi, bf16* __restrict__ Olo,
    float* __restrict__ OW, int mode)
{
    extern __shared__ char smem[];
    const u32 sb = smem_u32(smem);
    const int t = threadIdx.x, lane = t & 31, wid = t >> 5;
    const int warp_m = wid & 3, warp_n = wid >> 2;
    const int cls = blockIdx.z;
    const size_t co = (size_t)cls*DD;

    int bi, bj;
    if (mode == 1){
        int i = blockIdx.x; bi = 0;
        while (i >= bi + 1){ i -= bi + 1; bi++; }
        bj = i;
    } else { bi = blockIdx.x >> 2; bj = blockIdx.x & 3; }
    const int row0 = bi*128, col0 = bj*128;

    const bf16* Ah = Ahi + co; const bf16* Al = Alo + co;
    const bf16* Bh = Bhi + co; const bf16* Bl = Blo + co;

    float acc[2][8][4];
    #pragma unroll
    for (int ma = 0; ma < 2; ma++)
        #pragma unroll
        for (int na = 0; na < 8; na++)
            #pragma unroll
            for (int q = 0; q < 4; q++) acc[ma][na][q] = 0.f;

    // prefetch chunk 0
    cpa_tile(sb,            Ah, row0, 0, t);
    cpa_tile(sb +   TILE_B, Al, row0, 0, t);
    cpa_tile(sb + 2*TILE_B, Bh, col0, 0, t);
    cpa_tile(sb + 3*TILE_B, Bl, col0, 0, t);
    CP_COMMIT();

    for (int c = 0; c < 16; ++c){
        if (c + 1 < 16){
            u32 st = sb + ((c+1) & 1)*STAGE_B;
            int k0 = (c+1)*32;
            cpa_tile(st,            Ah, row0, k0, t);
            cpa_tile(st +   TILE_B, Al, row0, k0, t);
            cpa_tile(st + 2*TILE_B, Bh, col0, k0, t);
            cpa_tile(st + 3*TILE_B, Bl, col0, k0, t);
            CP_COMMIT();
            CP_WAIT1();
        } else {
            CP_WAIT0();
        }
        __syncthreads();
        compute_chunk2(acc, sb + (c & 1)*STAGE_B, warp_m, warp_n, lane);
        __syncthreads();
    }

    // epilogue
    const int g = lane >> 2, tig = lane & 3;
    #pragma unroll
    for (int ma = 0; ma < 2; ma++){
        #pragma unroll
        for (int na = 0; na < 8; na++){
            const float* cc = acc[ma][na];
            int r0 = row0 + warp_m*32 + ma*16 + g;
            int col = col0 + warp_n*64 + na*8 + 2*tig;
            if (mode == 0){
                u32 h0, l0, h1, l1;
                split2(cc[0], cc[1], h0, l0);
                split2(cc[2], cc[3], h1, l1);
                *(u32*)(Ohi + co + (size_t)r0*D + col)       = h0;
                *(u32*)(Olo + co + (size_t)r0*D + col)       = l0;
                *(u32*)(Ohi + co + (size_t)(r0+8)*D + col)   = h1;
                *(u32*)(Olo + co + (size_t)(r0+8)*D + col)   = l1;
            } else {
                *(float2*)(OW + co + (size_t)r0*D + col)     = make_float2(cc[0], cc[1]);
                *(float2*)(OW + co + (size_t)(r0+8)*D + col) = make_float2(cc[2], cc[3]);
            }
        }
    }
}

// ---------------- quad kernel: out = diff * Lambda^T, row-dot with diff --------
__global__ void __launch_bounds__(256, 2) mma_quad_kernel(
    const float* __restrict__ X, const float* __restrict__ muK,
    const bf16* __restrict__ Lhi, const bf16* __restrict__ Llo,
    float* __restrict__ part)
{
    extern __shared__ char smem[];
    const u32 sb = smem_u32(smem);
    const int t = threadIdx.x, lane = t & 31, wid = t >> 5;
    const int warp_m = wid & 3, warp_n = wid >> 2;
    const int cls = blockIdx.z;
    const size_t co = (size_t)cls*DD;
    const float* mu = muK + (size_t)cls*D;
    const int row0 = blockIdx.y*128, col0 = blockIdx.x*128;

    const bf16* Bh = Lhi + co; const bf16* Bl = Llo + co;

    float acc[2][8][4];
    #pragma unroll
    for (int ma = 0; ma < 2; ma++)
        #pragma unroll
        for (int na = 0; na < 8; na++)
            #pragma unroll
            for (int q = 0; q < 4; q++) acc[ma][na][q] = 0.f;

    cpa_tile(sb + 2*TILE_B, Bh, col0, 0, t);
    cpa_tile(sb + 3*TILE_B, Bl, col0, 0, t);
    CP_COMMIT();
    conv_diff_p(smem, X, mu, row0, 0, t);

    for (int c = 0; c < 16; ++c){
        if (c + 1 < 16){
            int s1 = (c+1) & 1;
            int k0 = (c+1)*32;
            cpa_tile(sb + s1*STAGE_B + 2*TILE_B, Bh, col0, k0, t);
            cpa_tile(sb + s1*STAGE_B + 3*TILE_B, Bl, col0, k0, t);
            CP_COMMIT();
            conv_diff_p(smem + s1*STAGE_B, X, mu, row0, k0, t);
            CP_WAIT1();
        } else {
            CP_WAIT0();
        }
        __syncthreads();
        compute_chunk2(acc, sb + (c & 1)*STAGE_B, warp_m, warp_n, lane);
        __syncthreads();
    }

    // epilogue: per-row dot with diff over this 128-col block
    const int g = lane >> 2, tig = lane & 3;
    float* sred = (float*)smem;   // [128][2]
    __syncthreads();

    #pragma unroll
    for (int ma = 0; ma < 2; ma++){
        float p0 = 0.f, p1 = 0.f;   // rows g and g+8 of this ma atom
        int r0 = row0 + warp_m*32 + ma*16 + g;
        int r1 = r0 + 8;
        #pragma unroll
        for (int na = 0; na < 8; na++){
            int col = col0 + warp_n*64 + na*8 + 2*tig;
            float m0 = mu[col], m1 = mu[col+1];
            float d00 = X[(size_t)r0*D + col]   - m0;
            float d01 = X[(size_t)r0*D + col+1] - m1;
            float d10 = X[(size_t)r1*D + col]   - m0;
            float d11 = X[(size_t)r1*D + col+1] - m1;
            const float* cc = acc[ma][na];
            p0 += cc[0]*d00 + cc[1]*d01;
            p1 += cc[2]*d10 + cc[3]*d11;
        }
        p0 += __shfl_down_sync(0xffffffffu, p0, 2);
        p0 += __shfl_down_sync(0xffffffffu, p0, 1);
        p1 += __shfl_down_sync(0xffffffffu, p1, 2);
        p1 += __shfl_down_sync(0xffffffffu, p1, 1);
        if (tig == 0){
            int rl0 = warp_m*32 + ma*16 + g;
            sred[rl0*2 + warp_n]     = p0;
            sred[(rl0+8)*2 + warp_n] = p1;
        }
    }
    __syncthreads();
    if (t < 128){
        float s = sred[t*2] + sred[t*2 + 1];
        part[((size_t)blockIdx.x*NX + row0 + t)*C + cls] = s;
    }
}

// ---------------- symsplit: X' = split(sym(2X - W)), lower->mirror -------------
// grid (136, C), 256 thr; block handles 32x32 lower tile (I,J), writes (I,J)+(J,I)
__global__ void __launch_bounds__(256) symsplit_kernel(const float* __restrict__ W,
                                                       const bf16* __restrict__ Xh,
                                                       const bf16* __restrict__ Xl,
                                                       bf16* __restrict__ Ohi,
                                                       bf16* __restrict__ Olo)
{
    __shared__ float sv[32][33];
    const int cls = blockIdx.y;
    const size_t co = (size_t)cls*DD;
    int i = blockIdx.x, I = 0;
    while (i >= I + 1){ i -= I + 1; I++; }
    const int J = i;
    const int t = threadIdx.x;
    const int tx = t & 31, ty = t >> 5;

    #pragma unroll
    for (int q = 0; q < 4; q++){
        int r = I*32 + ty + q*8, c = J*32 + tx;
        size_t idx = co + (size_t)r*D + c;
        float x = __bfloat162float(Xh[idx]) + __bfloat162float(Xl[idx]);
        sv[ty + q*8][tx] = 2.0f*x - W[idx];
    }
    __syncthreads();

    if (I != J){
        #pragma unroll
        for (int q = 0; q < 4; q++){
            int rl = ty + q*8;
            float v = sv[rl][tx];
            bf16 h = __float2bfloat16(v);
            size_t idx = co + (size_t)(I*32 + rl)*D + J*32 + tx;
            Ohi[idx] = h; Olo[idx] = __float2bfloat16(v - __bfloat162float(h));
            float vt = sv[tx][rl];
            bf16 ht = __float2bfloat16(vt);
            size_t idt = co + (size_t)(J*32 + rl)*D + I*32 + tx;
            Ohi[idt] = ht; Olo[idt] = __float2bfloat16(vt - __bfloat162float(ht));
        }
    } else {
        #pragma unroll
        for (int q = 0; q < 4; q++){
            int rl = ty + q*8;
            float v = (rl >= tx) ? sv[rl][tx] : sv[tx][rl];
            bf16 h = __float2bfloat16(v);
            size_t idx = co + (size_t)(I*32 + rl)*D + J*32 + tx;
            Ohi[idx] = h; Olo[idx] = __float2bfloat16(v - __bfloat162float(h));
        }
    }
}

// ---------------- combine ------------------------------------------------------
__global__ void __launch_bounds__(256) combine_kernel(float* __restrict__ out)
{
    int idx = blockIdx.x*256 + threadIdx.x;
    if (idx >= NX*C) return;
    int c = idx % C;
    float q = g_part[idx] + g_part[NX*C + idx] + g_part[2*NX*C + idx] + g_part[3*NX*C + idx];
    out[idx] = g_base[c] - 0.5f*q;
}

// ---------------- host launcher ------------------------------------------------
extern "C" void kernel_launch(void* const* d_in, const int* in_sizes, int n_in,
                              void* d_out, int out_size)
{
    const float* X      = (const float*)d_in[0];
    const float* muK    = (const float*)d_in[1];
    const float* SigmaK = (const float*)d_in[2];
    const float* Sigma  = (const float*)d_in[3];
    const float* cK     = (const float*)d_in[4];
    float* out = (float*)d_out;

    float *pW, *pPart;
    bf16 *pMhi, *pMlo, *pXhi, *pXlo, *pYhi, *pYlo;
    cudaGetSymbolAddress((void**)&pW,    g_W);
    cudaGetSymbolAddress((void**)&pMhi,  g_Mhi);
    cudaGetSymbolAddress((void**)&pMlo,  g_Mlo);
    cudaGetSymbolAddress((void**)&pXhi,  g_Xhi);
    cudaGetSymbolAddress((void**)&pXlo,  g_Xlo);
    cudaGetSymbolAddress((void**)&pYhi,  g_Yhi);
    cudaGetSymbolAddress((void**)&pYlo,  g_Ylo);
    cudaGetSymbolAddress((void**)&pPart, g_part);

    cudaFuncSetAttribute(mma_newton_kernel, cudaFuncAttributeMaxDynamicSharedMemorySize, SMEM_DYN);
    cudaFuncSetAttribute(mma_quad_kernel,   cudaFuncAttributeMaxDynamicSharedMemorySize, SMEM_DYN);

    prep_kernel <<<dim3(64, C), 256>>>(SigmaK, Sigma);
    power_kernel<<<C, 256>>>(cK);
    setx0_kernel<<<dim3(64, C), 256>>>();

    for (int it = 0; it < NEWTON_ITERS; ++it){
        // T = X * M^T = X*M (M sym)  -> Yhi/Ylo  (full 16 tiles)
        mma_newton_kernel<<<dim3(16, 1, C), 256, SMEM_DYN>>>(
            pXhi, pXlo, pMhi, pMlo, pYhi, pYlo, (float*)0, 0);
        // W = T * X^T = T*X = XMX (X sym) -> fp32, lower-triangle tiles only
        mma_newton_kernel<<<dim3(10, 1, C), 256, SMEM_DYN>>>(
            pYhi, pYlo, pXhi, pXlo, (bf16*)0, (bf16*)0, pW, 1);
        // X = split(sym(2X - W))
        symsplit_kernel<<<dim3(136, C), 256>>>(pW, pXhi, pXlo, pXhi, pXlo);
    }

    mma_quad_kernel<<<dim3(4, 16, C), 256, SMEM_DYN>>>(X, muK, pXhi, pXlo, pPart);
    combine_kernel <<<(NX*C + 255)/256, 256>>>(out);
}

// round 8
// speedup vs baseline: 2.9620x; 1.1150x over previous
#include <cuda_runtime.h>
#include <cuda_bf16.h>
#include <math.h>
#include <stdint.h>

// ---------------- problem constants ----------------
#define D      512
#define C      100
#define NX     2048
#define DD     (D*D)
#define ALPHA  0.5f
#define SHRINK 1e-4f
#define OMS    (1.0f - SHRINK)

#define NEWTON_ITERS 8
#define POWER_ITERS  10

typedef unsigned int u32;
typedef __nv_bfloat16 bf16;

// ---------------- scratch (device globals; no allocs allowed) ----------------
__device__ float g_M  [C*DD];    // fp32 M for power iteration
__device__ bf16  g_Mhi[C*DD];
__device__ bf16  g_Mlo[C*DD];
__device__ bf16  g_Xhi[C*DD];    // Newton iterate ping
__device__ bf16  g_Xlo[C*DD];
__device__ bf16  g_Yhi[C*DD];    // T = X*M
__device__ bf16  g_Ylo[C*DD];
__device__ bf16  g_Zhi[C*DD];    // Newton iterate pong
__device__ bf16  g_Zlo[C*DD];
__device__ float g_fpart[C*64];
__device__ float g_ab[C];
__device__ float g_base[C];
__device__ float g_part[4*NX*C];

// ---------------- PTX helpers -------------------------------------------------
__device__ __forceinline__ u32 smem_u32(const void* p){
    u32 a; asm("{ .reg .u64 t; cvta.to.shared.u64 t, %1; cvt.u32.u64 %0, t; }" : "=r"(a) : "l"(p));
    return a;
}
#define CPA16(dst, src) \
    asm volatile("cp.async.cg.shared.global [%0], [%1], 16;" :: "r"(dst), "l"(src) : "memory")
#define CP_COMMIT() asm volatile("cp.async.commit_group;" ::: "memory")
#define CP_WAIT1()  asm volatile("cp.async.wait_group 1;" ::: "memory")
#define CP_WAIT0()  asm volatile("cp.async.wait_group 0;" ::: "memory")

#define LDMX4(d0, d1, d2, d3, addr) \
    asm volatile("ldmatrix.sync.aligned.m8n8.x4.shared.b16 {%0,%1,%2,%3}, [%4];" \
        : "=r"(d0), "=r"(d1), "=r"(d2), "=r"(d3) : "r"(addr))

#define MMA(c, a, b) \
    asm volatile("mma.sync.aligned.m16n8k16.row.col.f32.bf16.bf16.f32 " \
        "{%0,%1,%2,%3}, {%4,%5,%6,%7}, {%8,%9}, {%0,%1,%2,%3};" \
        : "+f"((c)[0]), "+f"((c)[1]), "+f"((c)[2]), "+f"((c)[3]) \
        : "r"((a)[0]), "r"((a)[1]), "r"((a)[2]), "r"((a)[3]), "r"((b)[0]), "r"((b)[1]))

// ---------------- smem layout --------------------------------------------------
// Tiles 128 rows x 32 bf16, padded to 40 elems (80B) per row -> 10240B per tile.
// Stage: [Ahi][Alo][Bhi][Blo] = 40960B.  Two stages = 81920B dynamic smem.
// Mode-1 epilogue reuses smem as u32 sh32[128][129] (66048B <= 81920B).
#define ROWB    80
#define TILE_B  10240
#define STAGE_B 40960
#define SMEM_DYN (2*STAGE_B)
#define PITCH   129

__device__ __forceinline__ u32 pack_bf2(bf16 a, bf16 b){
    __nv_bfloat162 v = __halves2bfloat162(a, b);
    return *(u32*)&v;
}
__device__ __forceinline__ void split2(float a, float b, u32& h, u32& l){
    bf16 ha = __float2bfloat16(a), hb = __float2bfloat16(b);
    bf16 la = __float2bfloat16(a - __bfloat162float(ha));
    bf16 lb = __float2bfloat16(b - __bfloat162float(hb));
    h = pack_bf2(ha, hb); l = pack_bf2(la, lb);
}

// ---------------- loaders ------------------------------------------------------
__device__ __forceinline__ void cpa_tile(u32 sdst, const bf16* __restrict__ g,
                                         int row0, int k0, int t){
    int r = t >> 1, half = t & 1;
    const bf16* src = g + (size_t)(row0 + r)*D + k0 + half*16;
    u32 dst = sdst + r*ROWB + half*32;
    CPA16(dst,      src);
    CPA16(dst + 16, src + 8);
}

// diff = X - mu, split to bf16 hi/lo, STS into padded smem (quad A operand)
__device__ __forceinline__ void conv_diff_p(char* sdst, const float* __restrict__ X,
                                            const float* __restrict__ mu,
                                            int row0, int k0, int t){
    int r = t >> 1, half = t & 1;
    const float4* xs = (const float4*)(X + (size_t)(row0 + r)*D + k0 + half*16);
    const float4* ms = (const float4*)(mu + k0 + half*16);
    alignas(16) bf16 h[16], l[16];
    #pragma unroll
    for (int q = 0; q < 4; q++){
        float4 x = xs[q], m = ms[q];
        float v[4] = {x.x-m.x, x.y-m.y, x.z-m.z, x.w-m.w};
        #pragma unroll
        for (int j = 0; j < 4; j++){
            h[q*4+j] = __float2bfloat16(v[j]);
            l[q*4+j] = __float2bfloat16(v[j] - __bfloat162float(h[q*4+j]));
        }
    }
    char* dh = sdst + r*ROWB + half*32;
    char* dl = dh + TILE_B;
    *(uint4*)dh        = *(const uint4*)h;
    *(uint4*)(dh + 16) = *(const uint4*)(h + 8);
    *(uint4*)dl        = *(const uint4*)l;
    *(uint4*)(dl + 16) = *(const uint4*)(l + 8);
}

// ---------------- warp-tile compute (BK=32 chunk) ------------------------------
__device__ __forceinline__ void compute_chunk2(float acc[2][8][4], u32 stage,
                                               int warp_m, int warp_n, int lane){
    const u32 aoff = stage + (warp_m*32 + (lane & 15))*ROWB + (lane >> 4)*16;
    const u32 boff = stage + 2*TILE_B
                   + (warp_n*64 + (lane & 7) + ((lane >> 4) << 3))*ROWB
                   + ((lane >> 3) & 1)*16;
    #pragma unroll
    for (int ks = 0; ks < 2; ks++){
        u32 ah[2][4], al[2][4], b[8][2];
        #pragma unroll
        for (int ma = 0; ma < 2; ma++){
            LDMX4(ah[ma][0], ah[ma][1], ah[ma][2], ah[ma][3], aoff + ma*1280 + ks*32);
            LDMX4(al[ma][0], al[ma][1], al[ma][2], al[ma][3], aoff + TILE_B + ma*1280 + ks*32);
        }
        #pragma unroll
        for (int p = 0; p < 4; p++)
            LDMX4(b[2*p][0], b[2*p][1], b[2*p+1][0], b[2*p+1][1], boff + p*1280 + ks*32);
        #pragma unroll
        for (int ma = 0; ma < 2; ma++)
            #pragma unroll
            for (int na = 0; na < 8; na++){
                MMA(acc[ma][na], ah[ma], b[na]);
                MMA(acc[ma][na], al[ma], b[na]);
            }
        #pragma unroll
        for (int p = 0; p < 4; p++)
            LDMX4(b[2*p][0], b[2*p][1], b[2*p+1][0], b[2*p+1][1], boff + TILE_B + p*1280 + ks*32);
        #pragma unroll
        for (int ma = 0; ma < 2; ma++)
            #pragma unroll
            for (int na = 0; na < 8; na++)
                MMA(acc[ma][na], ah[ma], b[na]);
    }
}

// ---------------- prep: build M fp32 + split, Frobenius partials ---------------
__global__ void __launch_bounds__(256) prep_kernel(const float* __restrict__ SigmaK,
                                                   const float* __restrict__ Sigma)
{
    const int cls = blockIdx.y;
    const int t   = threadIdx.x;
    const size_t co = (size_t)cls*DD;
    const float4* Sk = (const float4*)(SigmaK + co);
    const float4* Sg = (const float4*)Sigma;
    float4* Mo = (float4*)(g_M + co);
    float fr = 0.f;
    #pragma unroll
    for (int j = 0; j < 4; j++){
        int id = blockIdx.x*1024 + j*256 + t;
        float4 a = Sk[id], b = Sg[id];
        float4 r;
        r.x = ALPHA*a.x + (1.0f-ALPHA)*b.x;
        r.y = ALPHA*a.y + (1.0f-ALPHA)*b.y;
        r.z = ALPHA*a.z + (1.0f-ALPHA)*b.z;
        r.w = ALPHA*a.w + (1.0f-ALPHA)*b.w;
        fr += r.x*r.x + r.y*r.y + r.z*r.z + r.w*r.w;
        float4 m;
        m.x = OMS*r.x; m.y = OMS*r.y; m.z = OMS*r.z; m.w = OMS*r.w;
        int e = id*4, row = e >> 9, c0 = e & (D-1);
        int dg = row - c0;
        if (dg >= 0 && dg < 4) ((float*)&m)[dg] += SHRINK;
        Mo[id] = m;
        alignas(8) bf16 hh[4], ll[4];
        #pragma unroll
        for (int q = 0; q < 4; q++){
            float v = ((float*)&m)[q];
            hh[q] = __float2bfloat16(v);
            ll[q] = __float2bfloat16(v - __bfloat162float(hh[q]));
        }
        *(uint2*)(g_Mhi + co + e) = *(const uint2*)hh;
        *(uint2*)(g_Mlo + co + e) = *(const uint2*)ll;
    }
    __shared__ float red[256];
    red[t] = fr; __syncthreads();
    for (int s = 128; s > 0; s >>= 1){ if (t < s) red[t] += red[t+s]; __syncthreads(); }
    if (t == 0) g_fpart[cls*64 + blockIdx.x] = red[0];
}

// ---------------- power iteration + per-class constants ------------------------
__global__ void __launch_bounds__(256) power_kernel(const float* __restrict__ cK)
{
    const int cls  = blockIdx.x;
    const int t    = threadIdx.x;
    const int lane = t & 31, warp = t >> 5;
    const float* Mc = g_M + (size_t)cls*DD;
    __shared__ float v[D], w[D], red[256];

    float x = (t < 64) ? g_fpart[cls*64 + t] : 0.f;
    red[t] = x; __syncthreads();
    for (int s = 128; s > 0; s >>= 1){ if (t < s) red[t] += red[t+s]; __syncthreads(); }
    float frobsq = red[0]; __syncthreads();

    float ckv = (t < C) ? cK[t] : 0.f;
    red[t] = ckv; __syncthreads();
    for (int s = 128; s > 0; s >>= 1){ if (t < s) red[t] += red[t+s]; __syncthreads(); }
    float csum = red[0]; __syncthreads();

    for (int i = t; i < D; i += 256) v[i] = 1.0f;
    __syncthreads();

    float lam = 1.0f;
    for (int it = 0; it < POWER_ITERS; ++it){
        for (int r = warp; r < D; r += 8){
            float s = 0.f;
            const float* Mr = Mc + (size_t)r*D;
            for (int k = lane; k < D; k += 32) s += Mr[k]*v[k];
            #pragma unroll
            for (int o = 16; o > 0; o >>= 1) s += __shfl_down_sync(0xffffffffu, s, o);
            if (lane == 0) w[r] = s;
        }
        __syncthreads();
        float ns = 0.f;
        for (int i = t; i < D; i += 256) ns += w[i]*w[i];
        red[t] = ns; __syncthreads();
        for (int s = 128; s > 0; s >>= 1){ if (t < s) red[t] += red[t+s]; __syncthreads(); }
        lam = sqrtf(red[0]); __syncthreads();
        float inv = 1.0f/lam;
        for (int i = t; i < D; i += 256) v[i] = w[i]*inv;
        __syncthreads();
    }

    if (t == 0){
        float bound = 1.35f*lam + 0.3f;
        g_ab[cls] = 2.0f/(0.09f + bound);
        float c0 = cK[cls];
        g_base[cls] = (c0 > 0.f) ? (logf(c0/csum) - 0.25f*logf(frobsq)) : -INFINITY;
    }
}

// ---------------- X0 = a*I in split bf16 ---------------------------------------
__global__ void __launch_bounds__(256) setx0_kernel()
{
    const int cls = blockIdx.y;
    const size_t co = (size_t)cls*DD;
    const float a = g_ab[cls];
    bf16 ahi = __float2bfloat16(a);
    bf16 alo = __float2bfloat16(a - __bfloat162float(ahi));
    const int t = threadIdx.x;
    #pragma unroll
    for (int j = 0; j < 4; j++){
        int id = blockIdx.x*1024 + j*256 + t;
        alignas(8) bf16 hh[4] = {bf16(0.f), bf16(0.f), bf16(0.f), bf16(0.f)};
        alignas(8) bf16 ll[4] = {bf16(0.f), bf16(0.f), bf16(0.f), bf16(0.f)};
        int e = id*4, row = e >> 9, c0 = e & (D-1);
        int dg = row - c0;
        if (dg >= 0 && dg < 4){ hh[dg] = ahi; ll[dg] = alo; }
        *(uint2*)(g_Xhi + co + e) = *(const uint2*)hh;
        *(uint2*)(g_Xlo + co + e) = *(const uint2*)ll;
    }
}

// ---------------- Newton GEMM (mma.sync, split-bf16) ---------------------------
// mode 0: grid (16,1,C), full;    Ohi/Olo = A * B^T  (split-bf16 store)
// mode 1: grid (10,1,C), lower-triangle tiles; fused symmetrizing epilogue:
//         X' = split(2*X - A*B^T), written to (bi,bj) and mirrored (bj,bi).
__global__ void __launch_bounds__(256, 2) mma_newton_kernel(
    const bf16* __restrict__ Ahi, const bf16* __restrict__ Alo,
    const bf16* __restrict__ Bhi, const bf16* __restrict__ Blo,
    bf16* __restrict__ Ohi, bf16* __restrict__ Olo, int mode)
{
    extern __shared__ char smem[];
    const u32 sb = smem_u32(smem);
    const int t = threadIdx.x, lane = t & 31, wid = t >> 5;
    const int warp_m = wid & 3, warp_n = wid >> 2;
    const int cls = blockIdx.z;
    const size_t co = (size_t)cls*DD;

    int bi, bj;
    if (mode == 1){
        int i = blockIdx.x; bi = 0;
        while (i >= bi + 1){ i -= bi + 1; bi++; }
        bj = i;
    } else { bi = blockIdx.x >> 2; bj = blockIdx.x & 3; }
    const int row0 = bi*128, col0 = bj*128;

    const bf16* Ah = Ahi + co; const bf16* Al = Alo + co;
    const bf16* Bh = Bhi + co; const bf16* Bl = Blo + co;

    float acc[2][8][4];
    #pragma unroll
    for (int ma = 0; ma < 2; ma++)
        #pragma unroll
        for (int na = 0; na < 8; na++)
            #pragma unroll
            for (int q = 0; q < 4; q++) acc[ma][na][q] = 0.f;

    // prefetch chunk 0
    cpa_tile(sb,            Ah, row0, 0, t);
    cpa_tile(sb +   TILE_B, Al, row0, 0, t);
    cpa_tile(sb + 2*TILE_B, Bh, col0, 0, t);
    cpa_tile(sb + 3*TILE_B, Bl, col0, 0, t);
    CP_COMMIT();

    for (int c = 0; c < 16; ++c){
        if (c + 1 < 16){
            u32 st = sb + ((c+1) & 1)*STAGE_B;
            int k0 = (c+1)*32;
            cpa_tile(st,            Ah, row0, k0, t);
            cpa_tile(st +   TILE_B, Al, row0, k0, t);
            cpa_tile(st + 2*TILE_B, Bh, col0, k0, t);
            cpa_tile(st + 3*TILE_B, Bl, col0, k0, t);
            CP_COMMIT();
            CP_WAIT1();
        } else {
            CP_WAIT0();
        }
        __syncthreads();
        compute_chunk2(acc, sb + (c & 1)*STAGE_B, warp_m, warp_n, lane);
        __syncthreads();
    }

    const int g = lane >> 2, tig = lane & 3;

    if (mode == 0){
        #pragma unroll
        for (int ma = 0; ma < 2; ma++){
            #pragma unroll
            for (int na = 0; na < 8; na++){
                const float* cc = acc[ma][na];
                int r0 = row0 + warp_m*32 + ma*16 + g;
                int col = col0 + warp_n*64 + na*8 + 2*tig;
                u32 h0, l0, h1, l1;
                split2(cc[0], cc[1], h0, l0);
                split2(cc[2], cc[3], h1, l1);
                *(u32*)(Ohi + co + (size_t)r0*D + col)       = h0;
                *(u32*)(Olo + co + (size_t)r0*D + col)       = l0;
                *(u32*)(Ohi + co + (size_t)(r0+8)*D + col)   = h1;
                *(u32*)(Olo + co + (size_t)(r0+8)*D + col)   = l1;
            }
        }
        return;
    }

    // ---- mode 1: fused symmetrizing epilogue ----
    // Phase A: v = 2*X - acc  -> packed split (hi|lo) into sh32[r][c], pitch 129
    u32* sh32 = (u32*)smem;
    #pragma unroll
    for (int ma = 0; ma < 2; ma++){
        #pragma unroll
        for (int na = 0; na < 8; na++){
            const float* cc = acc[ma][na];
            int rl = warp_m*32 + ma*16 + g;
            int cl = warp_n*64 + na*8 + 2*tig;
            #pragma unroll
            for (int h = 0; h < 2; h++){
                int r = rl + 8*h;
                size_t gidx = co + (size_t)(row0 + r)*D + col0 + cl;
                u32 xh = *(const u32*)(Bhi + gidx);   // B == current X
                u32 xl = *(const u32*)(Blo + gidx);
                __nv_bfloat162 bh2 = *(__nv_bfloat162*)&xh;
                __nv_bfloat162 bl2 = *(__nv_bfloat162*)&xl;
                float x0 = __bfloat162float(bh2.x) + __bfloat162float(bl2.x);
                float x1 = __bfloat162float(bh2.y) + __bfloat162float(bl2.y);
                float v0 = 2.0f*x0 - cc[2*h + 0];
                float v1 = 2.0f*x1 - cc[2*h + 1];
                bf16 h0 = __float2bfloat16(v0);
                bf16 l0 = __float2bfloat16(v0 - __bfloat162float(h0));
                bf16 h1 = __float2bfloat16(v1);
                bf16 l1 = __float2bfloat16(v1 - __bfloat162float(h1));
                sh32[r*PITCH + cl]     = pack_bf2(h0, l0);
                sh32[r*PITCH + cl + 1] = pack_bf2(h1, l1);
            }
        }
    }
    __syncthreads();

    // Phase B: coalesced writes of (bi,bj) tile and mirrored (bj,bi) tile
    const int wrow = t >> 5, lane5 = t & 31;
    if (bi != bj){
        #pragma unroll 4
        for (int it2 = 0; it2 < 16; it2++){
            int p = wrow + 8*it2;
            #pragma unroll
            for (int jq = 0; jq < 4; jq++){
                int q = lane5 + 32*jq;
                u32 u = sh32[p*PITCH + q];
                size_t di = co + (size_t)(row0 + p)*D + col0 + q;
                Ohi[di] = *(bf16*)&u;
                Olo[di] = *((bf16*)&u + 1);
                u32 ut = sh32[q*PITCH + p];
                size_t dt = co + (size_t)(col0 + p)*D + row0 + q;
                Ohi[dt] = *(bf16*)&ut;
                Olo[dt] = *((bf16*)&ut + 1);
            }
        }
    } else {
        #pragma unroll 4
        for (int it2 = 0; it2 < 16; it2++){
            int p = wrow + 8*it2;
            #pragma unroll
            for (int jq = 0; jq < 4; jq++){
                int q = lane5 + 32*jq;
                u32 u = (p >= q) ? sh32[p*PITCH + q] : sh32[q*PITCH + p];
                size_t di = co + (size_t)(row0 + p)*D + col0 + q;
                Ohi[di] = *(bf16*)&u;
                Olo[di] = *((bf16*)&u + 1);
            }
        }
    }
}

// ---------------- quad kernel: out = diff * Lambda^T, row-dot with diff --------
__global__ void __launch_bounds__(256, 2) mma_quad_kernel(
    const float* __restrict__ X, const float* __restrict__ muK,
    const bf16* __restrict__ Lhi, const bf16* __restrict__ Llo,
    float* __restrict__ part)
{
    extern __shared__ char smem[];
    const u32 sb = smem_u32(smem);
    const int t = threadIdx.x, lane = t & 31, wid = t >> 5;
    const int warp_m = wid & 3, warp_n = wid >> 2;
    const int cls = blockIdx.z;
    const size_t co = (size_t)cls*DD;
    const float* mu = muK + (size_t)cls*D;
    const int row0 = blockIdx.y*128, col0 = blockIdx.x*128;

    const bf16* Bh = Lhi + co; const bf16* Bl = Llo + co;

    float acc[2][8][4];
    #pragma unroll
    for (int ma = 0; ma < 2; ma++)
        #pragma unroll
        for (int na = 0; na < 8; na++)
            #pragma unroll
            for (int q = 0; q < 4; q++) acc[ma][na][q] = 0.f;

    cpa_tile(sb + 2*TILE_B, Bh, col0, 0, t);
    cpa_tile(sb + 3*TILE_B, Bl, col0, 0, t);
    CP_COMMIT();
    conv_diff_p(smem, X, mu, row0, 0, t);

    for (int c = 0; c < 16; ++c){
        if (c + 1 < 16){
            int s1 = (c+1) & 1;
            int k0 = (c+1)*32;
            cpa_tile(sb + s1*STAGE_B + 2*TILE_B, Bh, col0, k0, t);
            cpa_tile(sb + s1*STAGE_B + 3*TILE_B, Bl, col0, k0, t);
            CP_COMMIT();
            conv_diff_p(smem + s1*STAGE_B, X, mu, row0, k0, t);
            CP_WAIT1();
        } else {
            CP_WAIT0();
        }
        __syncthreads();
        compute_chunk2(acc, sb + (c & 1)*STAGE_B, warp_m, warp_n, lane);
        __syncthreads();
    }

    const int g = lane >> 2, tig = lane & 3;
    float* sred = (float*)smem;   // [128][2]
    __syncthreads();

    #pragma unroll
    for (int ma = 0; ma < 2; ma++){
        float p0 = 0.f, p1 = 0.f;
        int r0 = row0 + warp_m*32 + ma*16 + g;
        int r1 = r0 + 8;
        #pragma unroll
        for (int na = 0; na < 8; na++){
            int col = col0 + warp_n*64 + na*8 + 2*tig;
            float m0 = mu[col], m1 = mu[col+1];
            float d00 = X[(size_t)r0*D + col]   - m0;
            float d01 = X[(size_t)r0*D + col+1] - m1;
            float d10 = X[(size_t)r1*D + col]   - m0;
            float d11 = X[(size_t)r1*D + col+1] - m1;
            const float* cc = acc[ma][na];
            p0 += cc[0]*d00 + cc[1]*d01;
            p1 += cc[2]*d10 + cc[3]*d11;
        }
        p0 += __shfl_down_sync(0xffffffffu, p0, 2);
        p0 += __shfl_down_sync(0xffffffffu, p0, 1);
        p1 += __shfl_down_sync(0xffffffffu, p1, 2);
        p1 += __shfl_down_sync(0xffffffffu, p1, 1);
        if (tig == 0){
            int rl0 = warp_m*32 + ma*16 + g;
            sred[rl0*2 + warp_n]     = p0;
            sred[(rl0+8)*2 + warp_n] = p1;
        }
    }
    __syncthreads();
    if (t < 128){
        float s = sred[t*2] + sred[t*2 + 1];
        part[((size_t)blockIdx.x*NX + row0 + t)*C + cls] = s;
    }
}

// ---------------- combine ------------------------------------------------------
__global__ void __launch_bounds__(256) combine_kernel(float* __restrict__ out)
{
    int idx = blockIdx.x*256 + threadIdx.x;
    if (idx >= NX*C) return;
    int c = idx % C;
    float q = g_part[idx] + g_part[NX*C + idx] + g_part[2*NX*C + idx] + g_part[3*NX*C + idx];
    out[idx] = g_base[c] - 0.5f*q;
}

// ---------------- host launcher ------------------------------------------------
extern "C" void kernel_launch(void* const* d_in, const int* in_sizes, int n_in,
                              void* d_out, int out_size)
{
    const float* X      = (const float*)d_in[0];
    const float* muK    = (const float*)d_in[1];
    const float* SigmaK = (const float*)d_in[2];
    const float* Sigma  = (const float*)d_in[3];
    const float* cK     = (const float*)d_in[4];
    float* out = (float*)d_out;

    float *pPart;
    bf16 *pMhi, *pMlo, *pXhi, *pXlo, *pYhi, *pYlo, *pZhi, *pZlo;
    cudaGetSymbolAddress((void**)&pMhi,  g_Mhi);
    cudaGetSymbolAddress((void**)&pMlo,  g_Mlo);
    cudaGetSymbolAddress((void**)&pXhi,  g_Xhi);
    cudaGetSymbolAddress((void**)&pXlo,  g_Xlo);
    cudaGetSymbolAddress((void**)&pYhi,  g_Yhi);
    cudaGetSymbolAddress((void**)&pYlo,  g_Ylo);
    cudaGetSymbolAddress((void**)&pZhi,  g_Zhi);
    cudaGetSymbolAddress((void**)&pZlo,  g_Zlo);
    cudaGetSymbolAddress((void**)&pPart, g_part);

    cudaFuncSetAttribute(mma_newton_kernel, cudaFuncAttributeMaxDynamicSharedMemorySize, SMEM_DYN);
    cudaFuncSetAttribute(mma_quad_kernel,   cudaFuncAttributeMaxDynamicSharedMemorySize, SMEM_DYN);

    prep_kernel <<<dim3(64, C), 256>>>(SigmaK, Sigma);
    power_kernel<<<C, 256>>>(cK);
    setx0_kernel<<<dim3(64, C), 256>>>();

    bf16 *curh = pXhi, *curl = pXlo, *nxth = pZhi, *nxtl = pZlo;
    for (int it = 0; it < NEWTON_ITERS; ++it){
        // T = Xcur * M^T = Xcur*M (M sym) -> Y (full 16 tiles)
        mma_newton_kernel<<<dim3(16, 1, C), 256, SMEM_DYN>>>(
            curh, curl, pMhi, pMlo, pYhi, pYlo, 0);
        // Xnext = split(2*Xcur - T * Xcur^T), lower tiles + mirrored writes
        mma_newton_kernel<<<dim3(10, 1, C), 256, SMEM_DYN>>>(
            pYhi, pYlo, curh, curl, nxth, nxtl, 1);
        bf16* th = curh; curh = nxth; nxth = th;
        bf16* tl = curl; curl = nxtl; nxtl = tl;
    }

    mma_quad_kernel<<<dim3(4, 16, C), 256, SMEM_DYN>>>(X, muK, curh, curl, pPart);
    combine_kernel <<<(NX*C + 255)/256, 256>>>(out);
}

// round 9
// speedup vs baseline: 4.0735x; 1.3752x over previous
#include <cuda_runtime.h>
#include <cuda_bf16.h>
#include <math.h>
#include <stdint.h>

// ---------------- problem constants ----------------
#define D      512
#define C      100
#define NX     2048
#define DD     (D*D)
#define ALPHA  0.5f
#define SHRINK 1e-4f
#define OMS    (1.0f - SHRINK)

#define NEWTON_ITERS 8
#define CHEAP_ITERS  6      // iters [0, CHEAP_ITERS) use bf16-only products
#define POWER_ITERS  10

typedef unsigned int u32;
typedef __nv_bfloat16 bf16;

// ---------------- scratch (device globals; no allocs allowed) ----------------
__device__ float g_M  [C*DD];    // fp32 M for power iteration
__device__ bf16  g_Mhi[C*DD];
__device__ bf16  g_Mlo[C*DD];
__device__ bf16  g_Xhi[C*DD];    // Newton iterate ping
__device__ bf16  g_Xlo[C*DD];
__device__ bf16  g_Yhi[C*DD];    // T = X*M
__device__ bf16  g_Ylo[C*DD];
__device__ bf16  g_Zhi[C*DD];    // Newton iterate pong
__device__ bf16  g_Zlo[C*DD];
__device__ float g_fpart[C*64];
__device__ float g_ab[C];
__device__ float g_base[C];
__device__ float g_part[4*NX*C];

// ---------------- PTX helpers -------------------------------------------------
__device__ __forceinline__ u32 smem_u32(const void* p){
    u32 a; asm("{ .reg .u64 t; cvta.to.shared.u64 t, %1; cvt.u32.u64 %0, t; }" : "=r"(a) : "l"(p));
    return a;
}
#define CPA16(dst, src) \
    asm volatile("cp.async.cg.shared.global [%0], [%1], 16;" :: "r"(dst), "l"(src) : "memory")
#define CP_COMMIT() asm volatile("cp.async.commit_group;" ::: "memory")
#define CP_WAIT1()  asm volatile("cp.async.wait_group 1;" ::: "memory")
#define CP_WAIT0()  asm volatile("cp.async.wait_group 0;" ::: "memory")

#define LDMX4(d0, d1, d2, d3, addr) \
    asm volatile("ldmatrix.sync.aligned.m8n8.x4.shared.b16 {%0,%1,%2,%3}, [%4];" \
        : "=r"(d0), "=r"(d1), "=r"(d2), "=r"(d3) : "r"(addr))

#define MMA(c, a, b) \
    asm volatile("mma.sync.aligned.m16n8k16.row.col.f32.bf16.bf16.f32 " \
        "{%0,%1,%2,%3}, {%4,%5,%6,%7}, {%8,%9}, {%0,%1,%2,%3};" \
        : "+f"((c)[0]), "+f"((c)[1]), "+f"((c)[2]), "+f"((c)[3]) \
        : "r"((a)[0]), "r"((a)[1]), "r"((a)[2]), "r"((a)[3]), "r"((b)[0]), "r"((b)[1]))

// ---------------- smem layout --------------------------------------------------
// Tiles 128 rows x 32 bf16, padded to 40 elems (80B) per row -> 10240B per tile.
// Stage: [Ahi][Alo][Bhi][Blo] = 40960B.  Two stages = 81920B dynamic smem.
// Mode-1 epilogue reuses smem as u32 sh32[128][129] (66048B <= 81920B).
#define ROWB    80
#define TILE_B  10240
#define STAGE_B 40960
#define SMEM_DYN (2*STAGE_B)
#define PITCH   129

__device__ __forceinline__ u32 pack_bf2(bf16 a, bf16 b){
    __nv_bfloat162 v = __halves2bfloat162(a, b);
    return *(u32*)&v;
}
__device__ __forceinline__ void split2(float a, float b, u32& h, u32& l){
    bf16 ha = __float2bfloat16(a), hb = __float2bfloat16(b);
    bf16 la = __float2bfloat16(a - __bfloat162float(ha));
    bf16 lb = __float2bfloat16(b - __bfloat162float(hb));
    h = pack_bf2(ha, hb); l = pack_bf2(la, lb);
}

// ---------------- loaders ------------------------------------------------------
__device__ __forceinline__ void cpa_tile(u32 sdst, const bf16* __restrict__ g,
                                         int row0, int k0, int t){
    int r = t >> 1, half = t & 1;
    const bf16* src = g + (size_t)(row0 + r)*D + k0 + half*16;
    u32 dst = sdst + r*ROWB + half*32;
    CPA16(dst,      src);
    CPA16(dst + 16, src + 8);
}

// diff = X - mu, split to bf16 hi/lo, STS into padded smem (quad A operand)
__device__ __forceinline__ void conv_diff_p(char* sdst, const float* __restrict__ X,
                                            const float* __restrict__ mu,
                                            int row0, int k0, int t){
    int r = t >> 1, half = t & 1;
    const float4* xs = (const float4*)(X + (size_t)(row0 + r)*D + k0 + half*16);
    const float4* ms = (const float4*)(mu + k0 + half*16);
    alignas(16) bf16 h[16], l[16];
    #pragma unroll
    for (int q = 0; q < 4; q++){
        float4 x = xs[q], m = ms[q];
        float v[4] = {x.x-m.x, x.y-m.y, x.z-m.z, x.w-m.w};
        #pragma unroll
        for (int j = 0; j < 4; j++){
            h[q*4+j] = __float2bfloat16(v[j]);
            l[q*4+j] = __float2bfloat16(v[j] - __bfloat162float(h[q*4+j]));
        }
    }
    char* dh = sdst + r*ROWB + half*32;
    char* dl = dh + TILE_B;
    *(uint4*)dh        = *(const uint4*)h;
    *(uint4*)(dh + 16) = *(const uint4*)(h + 8);
    *(uint4*)dl        = *(const uint4*)l;
    *(uint4*)(dl + 16) = *(const uint4*)(l + 8);
}

// ---------------- warp-tile compute (BK=32 chunk) ------------------------------
// Precise: 3 split products. A tiles at stage+0 (hi) / +TILE_B (lo);
// B at +2T (hi) / +3T (lo).
__device__ __forceinline__ void compute_chunk2(float acc[2][8][4], u32 stage,
                                               int warp_m, int warp_n, int lane){
    const u32 aoff = stage + (warp_m*32 + (lane & 15))*ROWB + (lane >> 4)*16;
    const u32 boff = stage + 2*TILE_B
                   + (warp_n*64 + (lane & 7) + ((lane >> 4) << 3))*ROWB
                   + ((lane >> 3) & 1)*16;
    #pragma unroll
    for (int ks = 0; ks < 2; ks++){
        u32 ah[2][4], al[2][4], b[8][2];
        #pragma unroll
        for (int ma = 0; ma < 2; ma++){
            LDMX4(ah[ma][0], ah[ma][1], ah[ma][2], ah[ma][3], aoff + ma*1280 + ks*32);
            LDMX4(al[ma][0], al[ma][1], al[ma][2], al[ma][3], aoff + TILE_B + ma*1280 + ks*32);
        }
        #pragma unroll
        for (int p = 0; p < 4; p++)
            LDMX4(b[2*p][0], b[2*p][1], b[2*p+1][0], b[2*p+1][1], boff + p*1280 + ks*32);
        #pragma unroll
        for (int ma = 0; ma < 2; ma++)
            #pragma unroll
            for (int na = 0; na < 8; na++){
                MMA(acc[ma][na], ah[ma], b[na]);
                MMA(acc[ma][na], al[ma], b[na]);
            }
        #pragma unroll
        for (int p = 0; p < 4; p++)
            LDMX4(b[2*p][0], b[2*p][1], b[2*p+1][0], b[2*p+1][1], boff + TILE_B + p*1280 + ks*32);
        #pragma unroll
        for (int ma = 0; ma < 2; ma++)
            #pragma unroll
            for (int na = 0; na < 8; na++)
                MMA(acc[ma][na], ah[ma], b[na]);
    }
}

// Cheap: single bf16 product (hi tiles only)
__device__ __forceinline__ void compute_chunk_cheap(float acc[2][8][4], u32 stage,
                                                    int warp_m, int warp_n, int lane){
    const u32 aoff = stage + (warp_m*32 + (lane & 15))*ROWB + (lane >> 4)*16;
    const u32 boff = stage + 2*TILE_B
                   + (warp_n*64 + (lane & 7) + ((lane >> 4) << 3))*ROWB
                   + ((lane >> 3) & 1)*16;
    #pragma unroll
    for (int ks = 0; ks < 2; ks++){
        u32 ah[2][4], b[8][2];
        #pragma unroll
        for (int ma = 0; ma < 2; ma++)
            LDMX4(ah[ma][0], ah[ma][1], ah[ma][2], ah[ma][3], aoff + ma*1280 + ks*32);
        #pragma unroll
        for (int p = 0; p < 4; p++)
            LDMX4(b[2*p][0], b[2*p][1], b[2*p+1][0], b[2*p+1][1], boff + p*1280 + ks*32);
        #pragma unroll
        for (int ma = 0; ma < 2; ma++)
            #pragma unroll
            for (int na = 0; na < 8; na++)
                MMA(acc[ma][na], ah[ma], b[na]);
    }
}

// ---------------- prep: build M fp32 + split, Frobenius partials ---------------
__global__ void __launch_bounds__(256) prep_kernel(const float* __restrict__ SigmaK,
                                                   const float* __restrict__ Sigma)
{
    const int cls = blockIdx.y;
    const int t   = threadIdx.x;
    const size_t co = (size_t)cls*DD;
    const float4* Sk = (const float4*)(SigmaK + co);
    const float4* Sg = (const float4*)Sigma;
    float4* Mo = (float4*)(g_M + co);
    float fr = 0.f;
    #pragma unroll
    for (int j = 0; j < 4; j++){
        int id = blockIdx.x*1024 + j*256 + t;
        float4 a = Sk[id], b = Sg[id];
        float4 r;
        r.x = ALPHA*a.x + (1.0f-ALPHA)*b.x;
        r.y = ALPHA*a.y + (1.0f-ALPHA)*b.y;
        r.z = ALPHA*a.z + (1.0f-ALPHA)*b.z;
        r.w = ALPHA*a.w + (1.0f-ALPHA)*b.w;
        fr += r.x*r.x + r.y*r.y + r.z*r.z + r.w*r.w;
        float4 m;
        m.x = OMS*r.x; m.y = OMS*r.y; m.z = OMS*r.z; m.w = OMS*r.w;
        int e = id*4, row = e >> 9, c0 = e & (D-1);
        int dg = row - c0;
        if (dg >= 0 && dg < 4) ((float*)&m)[dg] += SHRINK;
        Mo[id] = m;
        alignas(8) bf16 hh[4], ll[4];
        #pragma unroll
        for (int q = 0; q < 4; q++){
            float v = ((float*)&m)[q];
            hh[q] = __float2bfloat16(v);
            ll[q] = __float2bfloat16(v - __bfloat162float(hh[q]));
        }
        *(uint2*)(g_Mhi + co + e) = *(const uint2*)hh;
        *(uint2*)(g_Mlo + co + e) = *(const uint2*)ll;
    }
    __shared__ float red[256];
    red[t] = fr; __syncthreads();
    for (int s = 128; s > 0; s >>= 1){ if (t < s) red[t] += red[t+s]; __syncthreads(); }
    if (t == 0) g_fpart[cls*64 + blockIdx.x] = red[0];
}

// ---------------- power iteration + per-class constants ------------------------
__global__ void __launch_bounds__(256) power_kernel(const float* __restrict__ cK)
{
    const int cls  = blockIdx.x;
    const int t    = threadIdx.x;
    const int lane = t & 31, warp = t >> 5;
    const float* Mc = g_M + (size_t)cls*DD;
    __shared__ float v[D], w[D], red[256];

    float x = (t < 64) ? g_fpart[cls*64 + t] : 0.f;
    red[t] = x; __syncthreads();
    for (int s = 128; s > 0; s >>= 1){ if (t < s) red[t] += red[t+s]; __syncthreads(); }
    float frobsq = red[0]; __syncthreads();

    float ckv = (t < C) ? cK[t] : 0.f;
    red[t] = ckv; __syncthreads();
    for (int s = 128; s > 0; s >>= 1){ if (t < s) red[t] += red[t+s]; __syncthreads(); }
    float csum = red[0]; __syncthreads();

    for (int i = t; i < D; i += 256) v[i] = 1.0f;
    __syncthreads();

    float lam = 1.0f;
    for (int it = 0; it < POWER_ITERS; ++it){
        for (int r = warp; r < D; r += 8){
            float s = 0.f;
            const float* Mr = Mc + (size_t)r*D;
            for (int k = lane; k < D; k += 32) s += Mr[k]*v[k];
            #pragma unroll
            for (int o = 16; o > 0; o >>= 1) s += __shfl_down_sync(0xffffffffu, s, o);
            if (lane == 0) w[r] = s;
        }
        __syncthreads();
        float ns = 0.f;
        for (int i = t; i < D; i += 256) ns += w[i]*w[i];
        red[t] = ns; __syncthreads();
        for (int s = 128; s > 0; s >>= 1){ if (t < s) red[t] += red[t+s]; __syncthreads(); }
        lam = sqrtf(red[0]); __syncthreads();
        float inv = 1.0f/lam;
        for (int i = t; i < D; i += 256) v[i] = w[i]*inv;
        __syncthreads();
    }

    if (t == 0){
        float bound = 1.35f*lam + 0.3f;
        g_ab[cls] = 2.0f/(0.09f + bound);
        float c0 = cK[cls];
        g_base[cls] = (c0 > 0.f) ? (logf(c0/csum) - 0.25f*logf(frobsq)) : -INFINITY;
    }
}

// ---------------- X0 = a*I in split bf16 ---------------------------------------
__global__ void __launch_bounds__(256) setx0_kernel()
{
    const int cls = blockIdx.y;
    const size_t co = (size_t)cls*DD;
    const float a = g_ab[cls];
    bf16 ahi = __float2bfloat16(a);
    bf16 alo = __float2bfloat16(a - __bfloat162float(ahi));
    const int t = threadIdx.x;
    #pragma unroll
    for (int j = 0; j < 4; j++){
        int id = blockIdx.x*1024 + j*256 + t;
        alignas(8) bf16 hh[4] = {bf16(0.f), bf16(0.f), bf16(0.f), bf16(0.f)};
        alignas(8) bf16 ll[4] = {bf16(0.f), bf16(0.f), bf16(0.f), bf16(0.f)};
        int e = id*4, row = e >> 9, c0 = e & (D-1);
        int dg = row - c0;
        if (dg >= 0 && dg < 4){ hh[dg] = ahi; ll[dg] = alo; }
        *(uint2*)(g_Xhi + co + e) = *(const uint2*)hh;
        *(uint2*)(g_Xlo + co + e) = *(const uint2*)ll;
    }
}

// ---------------- Newton GEMM (mma.sync, split-bf16 / cheap bf16) --------------
// mode 0: grid (16,1,C), full;    Ohi(/Olo if prec) = A * B^T
// mode 1: grid (10,1,C), lower-triangle tiles; fused symmetrizing epilogue:
//         X' = split(2*X - A*B^T), written to (bi,bj) and mirrored (bj,bi).
// prec 0: bf16-only products (hi tiles), mode 0 stores hi only.
__global__ void __launch_bounds__(256, 2) mma_newton_kernel(
    const bf16* __restrict__ Ahi, const bf16* __restrict__ Alo,
    const bf16* __restrict__ Bhi, const bf16* __restrict__ Blo,
    bf16* __restrict__ Ohi, bf16* __restrict__ Olo, int mode, int prec)
{
    extern __shared__ char smem[];
    const u32 sb = smem_u32(smem);
    const int t = threadIdx.x, lane = t & 31, wid = t >> 5;
    const int warp_m = wid & 3, warp_n = wid >> 2;
    const int cls = blockIdx.z;
    const size_t co = (size_t)cls*DD;

    int bi, bj;
    if (mode == 1){
        int i = blockIdx.x; bi = 0;
        while (i >= bi + 1){ i -= bi + 1; bi++; }
        bj = i;
    } else { bi = blockIdx.x >> 2; bj = blockIdx.x & 3; }
    const int row0 = bi*128, col0 = bj*128;

    const bf16* Ah = Ahi + co; const bf16* Al = Alo + co;
    const bf16* Bh = Bhi + co; const bf16* Bl = Blo + co;

    float acc[2][8][4];
    #pragma unroll
    for (int ma = 0; ma < 2; ma++)
        #pragma unroll
        for (int na = 0; na < 8; na++)
            #pragma unroll
            for (int q = 0; q < 4; q++) acc[ma][na][q] = 0.f;

    // prefetch chunk 0
    cpa_tile(sb,            Ah, row0, 0, t);
    cpa_tile(sb + 2*TILE_B, Bh, col0, 0, t);
    if (prec){
        cpa_tile(sb +   TILE_B, Al, row0, 0, t);
        cpa_tile(sb + 3*TILE_B, Bl, col0, 0, t);
    }
    CP_COMMIT();

    for (int c = 0; c < 16; ++c){
        if (c + 1 < 16){
            u32 st = sb + ((c+1) & 1)*STAGE_B;
            int k0 = (c+1)*32;
            cpa_tile(st,            Ah, row0, k0, t);
            cpa_tile(st + 2*TILE_B, Bh, col0, k0, t);
            if (prec){
                cpa_tile(st +   TILE_B, Al, row0, k0, t);
                cpa_tile(st + 3*TILE_B, Bl, col0, k0, t);
            }
            CP_COMMIT();
            CP_WAIT1();
        } else {
            CP_WAIT0();
        }
        __syncthreads();
        if (prec) compute_chunk2(acc, sb + (c & 1)*STAGE_B, warp_m, warp_n, lane);
        else      compute_chunk_cheap(acc, sb + (c & 1)*STAGE_B, warp_m, warp_n, lane);
        __syncthreads();
    }

    const int g = lane >> 2, tig = lane & 3;

    if (mode == 0){
        #pragma unroll
        for (int ma = 0; ma < 2; ma++){
            #pragma unroll
            for (int na = 0; na < 8; na++){
                const float* cc = acc[ma][na];
                int r0 = row0 + warp_m*32 + ma*16 + g;
                int col = col0 + warp_n*64 + na*8 + 2*tig;
                if (prec){
                    u32 h0, l0, h1, l1;
                    split2(cc[0], cc[1], h0, l0);
                    split2(cc[2], cc[3], h1, l1);
                    *(u32*)(Ohi + co + (size_t)r0*D + col)       = h0;
                    *(u32*)(Olo + co + (size_t)r0*D + col)       = l0;
                    *(u32*)(Ohi + co + (size_t)(r0+8)*D + col)   = h1;
                    *(u32*)(Olo + co + (size_t)(r0+8)*D + col)   = l1;
                } else {
                    *(u32*)(Ohi + co + (size_t)r0*D + col)
                        = pack_bf2(__float2bfloat16(cc[0]), __float2bfloat16(cc[1]));
                    *(u32*)(Ohi + co + (size_t)(r0+8)*D + col)
                        = pack_bf2(__float2bfloat16(cc[2]), __float2bfloat16(cc[3]));
                }
            }
        }
        return;
    }

    // ---- mode 1: fused symmetrizing epilogue ----
    // Phase A: v = 2*X - acc  -> packed split (hi|lo) into sh32[r][c], pitch 129
    u32* sh32 = (u32*)smem;
    #pragma unroll
    for (int ma = 0; ma < 2; ma++){
        #pragma unroll
        for (int na = 0; na < 8; na++){
            const float* cc = acc[ma][na];
            int rl = warp_m*32 + ma*16 + g;
            int cl = warp_n*64 + na*8 + 2*tig;
            #pragma unroll
            for (int h = 0; h < 2; h++){
                int r = rl + 8*h;
                size_t gidx = co + (size_t)(row0 + r)*D + col0 + cl;
                u32 xh = *(const u32*)(Bhi + gidx);   // B == current X
                u32 xl = *(const u32*)(Blo + gidx);
                __nv_bfloat162 bh2 = *(__nv_bfloat162*)&xh;
                __nv_bfloat162 bl2 = *(__nv_bfloat162*)&xl;
                float x0 = __bfloat162float(bh2.x) + __bfloat162float(bl2.x);
                float x1 = __bfloat162float(bh2.y) + __bfloat162float(bl2.y);
                float v0 = 2.0f*x0 - cc[2*h + 0];
                float v1 = 2.0f*x1 - cc[2*h + 1];
                bf16 h0 = __float2bfloat16(v0);
                bf16 l0 = __float2bfloat16(v0 - __bfloat162float(h0));
                bf16 h1 = __float2bfloat16(v1);
                bf16 l1 = __float2bfloat16(v1 - __bfloat162float(h1));
                sh32[r*PITCH + cl]     = pack_bf2(h0, l0);
                sh32[r*PITCH + cl + 1] = pack_bf2(h1, l1);
            }
        }
    }
    __syncthreads();

    // Phase B: coalesced writes of (bi,bj) tile and mirrored (bj,bi) tile
    const int wrow = t >> 5, lane5 = t & 31;
    if (bi != bj){
        #pragma unroll 4
        for (int it2 = 0; it2 < 16; it2++){
            int p = wrow + 8*it2;
            #pragma unroll
            for (int jq = 0; jq < 4; jq++){
                int q = lane5 + 32*jq;
                u32 u = sh32[p*PITCH + q];
                size_t di = co + (size_t)(row0 + p)*D + col0 + q;
                Ohi[di] = *(bf16*)&u;
                Olo[di] = *((bf16*)&u + 1);
                u32 ut = sh32[q*PITCH + p];
                size_t dt = co + (size_t)(col0 + p)*D + row0 + q;
                Ohi[dt] = *(bf16*)&ut;
                Olo[dt] = *((bf16*)&ut + 1);
            }
        }
    } else {
        #pragma unroll 4
        for (int it2 = 0; it2 < 16; it2++){
            int p = wrow + 8*it2;
            #pragma unroll
            for (int jq = 0; jq < 4; jq++){
                int q = lane5 + 32*jq;
                u32 u = (p >= q) ? sh32[p*PITCH + q] : sh32[q*PITCH + p];
                size_t di = co + (size_t)(row0 + p)*D + col0 + q;
                Ohi[di] = *(bf16*)&u;
                Olo[di] = *((bf16*)&u + 1);
            }
        }
    }
}

// ---------------- quad kernel: out = diff * Lambda^T, row-dot with diff --------
__global__ void __launch_bounds__(256, 2) mma_quad_kernel(
    const float* __restrict__ X, const float* __restrict__ muK,
    const bf16* __restrict__ Lhi, const bf16* __restrict__ Llo,
    float* __restrict__ part)
{
    extern __shared__ char smem[];
    const u32 sb = smem_u32(smem);
    const int t = threadIdx.x, lane = t & 31, wid = t >> 5;
    const int warp_m = wid & 3, warp_n = wid >> 2;
    const int cls = blockIdx.z;
    const size_t co = (size_t)cls*DD;
    const float* mu = muK + (size_t)cls*D;
    const int row0 = blockIdx.y*128, col0 = blockIdx.x*128;

    const bf16* Bh = Lhi + co; const bf16* Bl = Llo + co;

    float acc[2][8][4];
    #pragma unroll
    for (int ma = 0; ma < 2; ma++)
        #pragma unroll
        for (int na = 0; na < 8; na++)
            #pragma unroll
            for (int q = 0; q < 4; q++) acc[ma][na][q] = 0.f;

    cpa_tile(sb + 2*TILE_B, Bh, col0, 0, t);
    cpa_tile(sb + 3*TILE_B, Bl, col0, 0, t);
    CP_COMMIT();
    conv_diff_p(smem, X, mu, row0, 0, t);

    for (int c = 0; c < 16; ++c){
        if (c + 1 < 16){
            int s1 = (c+1) & 1;
            int k0 = (c+1)*32;
            cpa_tile(sb + s1*STAGE_B + 2*TILE_B, Bh, col0, k0, t);
            cpa_tile(sb + s1*STAGE_B + 3*TILE_B, Bl, col0, k0, t);
            CP_COMMIT();
            conv_diff_p(smem + s1*STAGE_B, X, mu, row0, k0, t);
            CP_WAIT1();
        } else {
            CP_WAIT0();
        }
        __syncthreads();
        compute_chunk2(acc, sb + (c & 1)*STAGE_B, warp_m, warp_n, lane);
        __syncthreads();
    }

    const int g = lane >> 2, tig = lane & 3;
    float* sred = (float*)smem;   // [128][2]
    __syncthreads();

    #pragma unroll
    for (int ma = 0; ma < 2; ma++){
        float p0 = 0.f, p1 = 0.f;
        int r0 = row0 + warp_m*32 + ma*16 + g;
        int r1 = r0 + 8;
        #pragma unroll
        for (int na = 0; na < 8; na++){
            int col = col0 + warp_n*64 + na*8 + 2*tig;
            float m0 = mu[col], m1 = mu[col+1];
            float d00 = X[(size_t)r0*D + col]   - m0;
            float d01 = X[(size_t)r0*D + col+1] - m1;
            float d10 = X[(size_t)r1*D + col]   - m0;
            float d11 = X[(size_t)r1*D + col+1] - m1;
            const float* cc = acc[ma][na];
            p0 += cc[0]*d00 + cc[1]*d01;
            p1 += cc[2]*d10 + cc[3]*d11;
        }
        p0 += __shfl_down_sync(0xffffffffu, p0, 2);
        p0 += __shfl_down_sync(0xffffffffu, p0, 1);
        p1 += __shfl_down_sync(0xffffffffu, p1, 2);
        p1 += __shfl_down_sync(0xffffffffu, p1, 1);
        if (tig == 0){
            int rl0 = warp_m*32 + ma*16 + g;
            sred[rl0*2 + warp_n]     = p0;
            sred[(rl0+8)*2 + warp_n] = p1;
        }
    }
    __syncthreads();
    if (t < 128){
        float s = sred[t*2] + sred[t*2 + 1];
        part[((size_t)blockIdx.x*NX + row0 + t)*C + cls] = s;
    }
}

// ---------------- combine ------------------------------------------------------
__global__ void __launch_bounds__(256) combine_kernel(float* __restrict__ out)
{
    int idx = blockIdx.x*256 + threadIdx.x;
    if (idx >= NX*C) return;
    int c = idx % C;
    float q = g_part[idx] + g_part[NX*C + idx] + g_part[2*NX*C + idx] + g_part[3*NX*C + idx];
    out[idx] = g_base[c] - 0.5f*q;
}

// ---------------- host launcher ------------------------------------------------
extern "C" void kernel_launch(void* const* d_in, const int* in_sizes, int n_in,
                              void* d_out, int out_size)
{
    const float* X      = (const float*)d_in[0];
    const float* muK    = (const float*)d_in[1];
    const float* SigmaK = (const float*)d_in[2];
    const float* Sigma  = (const float*)d_in[3];
    const float* cK     = (const float*)d_in[4];
    float* out = (float*)d_out;

    float *pPart;
    bf16 *pMhi, *pMlo, *pXhi, *pXlo, *pYhi, *pYlo, *pZhi, *pZlo;
    cudaGetSymbolAddress((void**)&pMhi,  g_Mhi);
    cudaGetSymbolAddress((void**)&pMlo,  g_Mlo);
    cudaGetSymbolAddress((void**)&pXhi,  g_Xhi);
    cudaGetSymbolAddress((void**)&pXlo,  g_Xlo);
    cudaGetSymbolAddress((void**)&pYhi,  g_Yhi);
    cudaGetSymbolAddress((void**)&pYlo,  g_Ylo);
    cudaGetSymbolAddress((void**)&pZhi,  g_Zhi);
    cudaGetSymbolAddress((void**)&pZlo,  g_Zlo);
    cudaGetSymbolAddress((void**)&pPart, g_part);

    cudaFuncSetAttribute(mma_newton_kernel, cudaFuncAttributeMaxDynamicSharedMemorySize, SMEM_DYN);
    cudaFuncSetAttribute(mma_quad_kernel,   cudaFuncAttributeMaxDynamicSharedMemorySize, SMEM_DYN);

    prep_kernel <<<dim3(64, C), 256>>>(SigmaK, Sigma);
    power_kernel<<<C, 256>>>(cK);
    setx0_kernel<<<dim3(64, C), 256>>>();

    bf16 *curh = pXhi, *curl = pXlo, *nxth = pZhi, *nxtl = pZlo;
    for (int it = 0; it < NEWTON_ITERS; ++it){
        int prec = (it >= CHEAP_ITERS) ? 1 : 0;
        // T = Xcur * M^T = Xcur*M (M sym) -> Y (full 16 tiles)
        mma_newton_kernel<<<dim3(16, 1, C), 256, SMEM_DYN>>>(
            curh, curl, pMhi, pMlo, pYhi, pYlo, 0, prec);
        // Xnext = split(2*Xcur - T * Xcur^T), lower tiles + mirrored writes
        mma_newton_kernel<<<dim3(10, 1, C), 256, SMEM_DYN>>>(
            pYhi, pYlo, curh, curl, nxth, nxtl, 1, prec);
        bf16* th = curh; curh = nxth; nxth = th;
        bf16* tl = curl; curl = nxtl; nxtl = tl;
    }

    mma_quad_kernel<<<dim3(4, 16, C), 256, SMEM_DYN>>>(X, muK, curh, curl, pPart);
    combine_kernel <<<(NX*C + 255)/256, 256>>>(out);
}

// round 10
// speedup vs baseline: 4.1048x; 1.0077x over previous
#include <cuda_runtime.h>
#include <cuda_bf16.h>
#include <math.h>
#include <stdint.h>

// ---------------- problem constants ----------------
#define D      512
#define C      100
#define NX     2048
#define DD     (D*D)
#define ALPHA  0.5f
#define SHRINK 1e-4f
#define OMS    (1.0f - SHRINK)

#define NEWTON_ITERS 8
#define CHEAP_ITERS  6      // iters [0, CHEAP_ITERS) use bf16-only products
#define POWER_ITERS  4

typedef unsigned int u32;
typedef __nv_bfloat16 bf16;

// ---------------- scratch (device globals; no allocs allowed) ----------------
__device__ float g_M  [C*DD];    // fp32 M for power iteration
__device__ bf16  g_Mhi[C*DD];
__device__ bf16  g_Mlo[C*DD];
__device__ bf16  g_Xhi[C*DD];    // Newton iterate ping
__device__ bf16  g_Xlo[C*DD];
__device__ bf16  g_Yhi[C*DD];    // T = X*M
__device__ bf16  g_Ylo[C*DD];
__device__ bf16  g_Zhi[C*DD];    // Newton iterate pong
__device__ bf16  g_Zlo[C*DD];
__device__ bf16  g_XShi[NX*D];   // presplit test matrix X
__device__ bf16  g_XSlo[NX*D];
__device__ float g_fpart[C*64];
__device__ float g_ab[C];
__device__ float g_base[C];
__device__ float g_muLmu[C];
__device__ float g_part[4*NX*C];

// ---------------- PTX helpers -------------------------------------------------
__device__ __forceinline__ u32 smem_u32(const void* p){
    u32 a; asm("{ .reg .u64 t; cvta.to.shared.u64 t, %1; cvt.u32.u64 %0, t; }" : "=r"(a) : "l"(p));
    return a;
}
#define CPA16(dst, src) \
    asm volatile("cp.async.cg.shared.global [%0], [%1], 16;" :: "r"(dst), "l"(src) : "memory")
#define CP_COMMIT() asm volatile("cp.async.commit_group;" ::: "memory")
#define CP_WAIT1()  asm volatile("cp.async.wait_group 1;" ::: "memory")
#define CP_WAIT0()  asm volatile("cp.async.wait_group 0;" ::: "memory")

#define LDMX4(d0, d1, d2, d3, addr) \
    asm volatile("ldmatrix.sync.aligned.m8n8.x4.shared.b16 {%0,%1,%2,%3}, [%4];" \
        : "=r"(d0), "=r"(d1), "=r"(d2), "=r"(d3) : "r"(addr))

#define MMA(c, a, b) \
    asm volatile("mma.sync.aligned.m16n8k16.row.col.f32.bf16.bf16.f32 " \
        "{%0,%1,%2,%3}, {%4,%5,%6,%7}, {%8,%9}, {%0,%1,%2,%3};" \
        : "+f"((c)[0]), "+f"((c)[1]), "+f"((c)[2]), "+f"((c)[3]) \
        : "r"((a)[0]), "r"((a)[1]), "r"((a)[2]), "r"((a)[3]), "r"((b)[0]), "r"((b)[1]))

// ---------------- smem layout --------------------------------------------------
#define ROWB    80
#define TILE_B  10240
#define STAGE_B 40960
#define SMEM_DYN (2*STAGE_B)
#define PITCH   129

__device__ __forceinline__ u32 pack_bf2(bf16 a, bf16 b){
    __nv_bfloat162 v = __halves2bfloat162(a, b);
    return *(u32*)&v;
}
__device__ __forceinline__ void split2(float a, float b, u32& h, u32& l){
    bf16 ha = __float2bfloat16(a), hb = __float2bfloat16(b);
    bf16 la = __float2bfloat16(a - __bfloat162float(ha));
    bf16 lb = __float2bfloat16(b - __bfloat162float(hb));
    h = pack_bf2(ha, hb); l = pack_bf2(la, lb);
}

// ---------------- loaders ------------------------------------------------------
__device__ __forceinline__ void cpa_tile(u32 sdst, const bf16* __restrict__ g,
                                         int row0, int k0, int t){
    int r = t >> 1, half = t & 1;
    const bf16* src = g + (size_t)(row0 + r)*D + k0 + half*16;
    u32 dst = sdst + r*ROWB + half*32;
    CPA16(dst,      src);
    CPA16(dst + 16, src + 8);
}

// ---------------- warp-tile compute --------------------------------------------
// Precise: 3 split products, BK=32 chunk.
__device__ __forceinline__ void compute_chunk2(float acc[2][8][4], u32 stage,
                                               int warp_m, int warp_n, int lane){
    const u32 aoff = stage + (warp_m*32 + (lane & 15))*ROWB + (lane >> 4)*16;
    const u32 boff = stage + 2*TILE_B
                   + (warp_n*64 + (lane & 7) + ((lane >> 4) << 3))*ROWB
                   + ((lane >> 3) & 1)*16;
    #pragma unroll
    for (int ks = 0; ks < 2; ks++){
        u32 ah[2][4], al[2][4], b[8][2];
        #pragma unroll
        for (int ma = 0; ma < 2; ma++){
            LDMX4(ah[ma][0], ah[ma][1], ah[ma][2], ah[ma][3], aoff + ma*1280 + ks*32);
            LDMX4(al[ma][0], al[ma][1], al[ma][2], al[ma][3], aoff + TILE_B + ma*1280 + ks*32);
        }
        #pragma unroll
        for (int p = 0; p < 4; p++)
            LDMX4(b[2*p][0], b[2*p][1], b[2*p+1][0], b[2*p+1][1], boff + p*1280 + ks*32);
        #pragma unroll
        for (int ma = 0; ma < 2; ma++)
            #pragma unroll
            for (int na = 0; na < 8; na++){
                MMA(acc[ma][na], ah[ma], b[na]);
                MMA(acc[ma][na], al[ma], b[na]);
            }
        #pragma unroll
        for (int p = 0; p < 4; p++)
            LDMX4(b[2*p][0], b[2*p][1], b[2*p+1][0], b[2*p+1][1], boff + TILE_B + p*1280 + ks*32);
        #pragma unroll
        for (int ma = 0; ma < 2; ma++)
            #pragma unroll
            for (int na = 0; na < 8; na++)
                MMA(acc[ma][na], ah[ma], b[na]);
    }
}

// Cheap: single bf16 product on one BK=32 sub-chunk; A at abase, B at bbase
__device__ __forceinline__ void compute_chunk_cheap(float acc[2][8][4],
                                                    u32 abase, u32 bbase,
                                                    int warp_m, int warp_n, int lane){
    const u32 aoff = abase + (warp_m*32 + (lane & 15))*ROWB + (lane >> 4)*16;
    const u32 boff = bbase + (warp_n*64 + (lane & 7) + ((lane >> 4) << 3))*ROWB
                   + ((lane >> 3) & 1)*16;
    #pragma unroll
    for (int ks = 0; ks < 2; ks++){
        u32 ah[2][4], b[8][2];
        #pragma unroll
        for (int ma = 0; ma < 2; ma++)
            LDMX4(ah[ma][0], ah[ma][1], ah[ma][2], ah[ma][3], aoff + ma*1280 + ks*32);
        #pragma unroll
        for (int p = 0; p < 4; p++)
            LDMX4(b[2*p][0], b[2*p][1], b[2*p+1][0], b[2*p+1][1], boff + p*1280 + ks*32);
        #pragma unroll
        for (int ma = 0; ma < 2; ma++)
            #pragma unroll
            for (int na = 0; na < 8; na++)
                MMA(acc[ma][na], ah[ma], b[na]);
    }
}

// ---------------- prep: build M fp32 + split, Frobenius partials ---------------
__global__ void __launch_bounds__(256) prep_kernel(const float* __restrict__ SigmaK,
                                                   const float* __restrict__ Sigma)
{
    const int cls = blockIdx.y;
    const int t   = threadIdx.x;
    const size_t co = (size_t)cls*DD;
    const float4* Sk = (const float4*)(SigmaK + co);
    const float4* Sg = (const float4*)Sigma;
    float4* Mo = (float4*)(g_M + co);
    float fr = 0.f;
    #pragma unroll
    for (int j = 0; j < 4; j++){
        int id = blockIdx.x*1024 + j*256 + t;
        float4 a = Sk[id], b = Sg[id];
        float4 r;
        r.x = ALPHA*a.x + (1.0f-ALPHA)*b.x;
        r.y = ALPHA*a.y + (1.0f-ALPHA)*b.y;
        r.z = ALPHA*a.z + (1.0f-ALPHA)*b.z;
        r.w = ALPHA*a.w + (1.0f-ALPHA)*b.w;
        fr += r.x*r.x + r.y*r.y + r.z*r.z + r.w*r.w;
        float4 m;
        m.x = OMS*r.x; m.y = OMS*r.y; m.z = OMS*r.z; m.w = OMS*r.w;
        int e = id*4, row = e >> 9, c0 = e & (D-1);
        int dg = row - c0;
        if (dg >= 0 && dg < 4) ((float*)&m)[dg] += SHRINK;
        Mo[id] = m;
        alignas(8) bf16 hh[4], ll[4];
        #pragma unroll
        for (int q = 0; q < 4; q++){
            float v = ((float*)&m)[q];
            hh[q] = __float2bfloat16(v);
            ll[q] = __float2bfloat16(v - __bfloat162float(hh[q]));
        }
        *(uint2*)(g_Mhi + co + e) = *(const uint2*)hh;
        *(uint2*)(g_Mlo + co + e) = *(const uint2*)ll;
    }
    __shared__ float red[256];
    red[t] = fr; __syncthreads();
    for (int s = 128; s > 0; s >>= 1){ if (t < s) red[t] += red[t+s]; __syncthreads(); }
    if (t == 0) g_fpart[cls*64 + blockIdx.x] = red[0];
}

// ---------------- split X once -------------------------------------------------
__global__ void __launch_bounds__(256) splitx_kernel(const float* __restrict__ X)
{
    int id = blockIdx.x*256 + threadIdx.x;      // float4 index, NX*D/4 total
    float4 v = ((const float4*)X)[id];
    alignas(8) bf16 hh[4], ll[4];
    #pragma unroll
    for (int q = 0; q < 4; q++){
        float x = ((float*)&v)[q];
        hh[q] = __float2bfloat16(x);
        ll[q] = __float2bfloat16(x - __bfloat162float(hh[q]));
    }
    *(uint2*)(g_XShi + id*4) = *(const uint2*)hh;
    *(uint2*)(g_XSlo + id*4) = *(const uint2*)ll;
}

// ---------------- power iteration + per-class constants ------------------------
__global__ void __launch_bounds__(256) power_kernel(const float* __restrict__ cK)
{
    const int cls  = blockIdx.x;
    const int t    = threadIdx.x;
    const int lane = t & 31, warp = t >> 5;
    const float* Mc = g_M + (size_t)cls*DD;
    __shared__ float v[D], w[D], red[256];

    float x = (t < 64) ? g_fpart[cls*64 + t] : 0.f;
    red[t] = x; __syncthreads();
    for (int s = 128; s > 0; s >>= 1){ if (t < s) red[t] += red[t+s]; __syncthreads(); }
    float frobsq = red[0]; __syncthreads();

    float ckv = (t < C) ? cK[t] : 0.f;
    red[t] = ckv; __syncthreads();
    for (int s = 128; s > 0; s >>= 1){ if (t < s) red[t] += red[t+s]; __syncthreads(); }
    float csum = red[0]; __syncthreads();

    for (int i = t; i < D; i += 256) v[i] = 1.0f;
    __syncthreads();

    float lam = 1.0f;
    for (int it = 0; it < POWER_ITERS; ++it){
        for (int r = warp; r < D; r += 8){
            float s = 0.f;
            const float* Mr = Mc + (size_t)r*D;
            for (int k = lane; k < D; k += 32) s += Mr[k]*v[k];
            #pragma unroll
            for (int o = 16; o > 0; o >>= 1) s += __shfl_down_sync(0xffffffffu, s, o);
            if (lane == 0) w[r] = s;
        }
        __syncthreads();
        float ns = 0.f;
        for (int i = t; i < D; i += 256) ns += w[i]*w[i];
        red[t] = ns; __syncthreads();
        for (int s = 128; s > 0; s >>= 1){ if (t < s) red[t] += red[t+s]; __syncthreads(); }
        lam = sqrtf(red[0]); __syncthreads();
        float inv = 1.0f/lam;
        for (int i = t; i < D; i += 256) v[i] = w[i]*inv;
        __syncthreads();
    }

    if (t == 0){
        float bound = 1.5f*lam + 0.3f;   // wider safety for 4 power iters
        g_ab[cls] = 2.0f/(0.09f + bound);
        float c0 = cK[cls];
        g_base[cls] = (c0 > 0.f) ? (logf(c0/csum) - 0.25f*logf(frobsq)) : -INFINITY;
    }
}

// ---------------- X0 = a*I in split bf16 ---------------------------------------
__global__ void __launch_bounds__(256) setx0_kernel()
{
    const int cls = blockIdx.y;
    const size_t co = (size_t)cls*DD;
    const float a = g_ab[cls];
    bf16 ahi = __float2bfloat16(a);
    bf16 alo = __float2bfloat16(a - __bfloat162float(ahi));
    const int t = threadIdx.x;
    #pragma unroll
    for (int j = 0; j < 4; j++){
        int id = blockIdx.x*1024 + j*256 + t;
        alignas(8) bf16 hh[4] = {bf16(0.f), bf16(0.f), bf16(0.f), bf16(0.f)};
        alignas(8) bf16 ll[4] = {bf16(0.f), bf16(0.f), bf16(0.f), bf16(0.f)};
        int e = id*4, row = e >> 9, c0 = e & (D-1);
        int dg = row - c0;
        if (dg >= 0 && dg < 4){ hh[dg] = ahi; ll[dg] = alo; }
        *(uint2*)(g_Xhi + co + e) = *(const uint2*)hh;
        *(uint2*)(g_Xlo + co + e) = *(const uint2*)ll;
    }
}

// ---------------- Newton GEMM (mma.sync, split-bf16 / cheap bf16) --------------
__global__ void __launch_bounds__(256, 2) mma_newton_kernel(
    const bf16* __restrict__ Ahi, const bf16* __restrict__ Alo,
    const bf16* __restrict__ Bhi, const bf16* __restrict__ Blo,
    bf16* __restrict__ Ohi, bf16* __restrict__ Olo, int mode, int prec)
{
    extern __shared__ char smem[];
    const u32 sb = smem_u32(smem);
    const int t = threadIdx.x, lane = t & 31, wid = t >> 5;
    const int warp_m = wid & 3, warp_n = wid >> 2;
    const int cls = blockIdx.z;
    const size_t co = (size_t)cls*DD;

    int bi, bj;
    if (mode == 1){
        int i = blockIdx.x; bi = 0;
        while (i >= bi + 1){ i -= bi + 1; bi++; }
        bj = i;
    } else { bi = blockIdx.x >> 2; bj = blockIdx.x & 3; }
    const int row0 = bi*128, col0 = bj*128;

    const bf16* Ah = Ahi + co; const bf16* Al = Alo + co;
    const bf16* Bh = Bhi + co; const bf16* Bl = Blo + co;

    float acc[2][8][4];
    #pragma unroll
    for (int ma = 0; ma < 2; ma++)
        #pragma unroll
        for (int na = 0; na < 8; na++)
            #pragma unroll
            for (int q = 0; q < 4; q++) acc[ma][na][q] = 0.f;

    if (prec){
        // BK=32, 16 steps, 3 split products
        cpa_tile(sb,            Ah, row0, 0, t);
        cpa_tile(sb +   TILE_B, Al, row0, 0, t);
        cpa_tile(sb + 2*TILE_B, Bh, col0, 0, t);
        cpa_tile(sb + 3*TILE_B, Bl, col0, 0, t);
        CP_COMMIT();
        for (int c = 0; c < 16; ++c){
            if (c + 1 < 16){
                u32 st = sb + ((c+1) & 1)*STAGE_B;
                int k0 = (c+1)*32;
                cpa_tile(st,            Ah, row0, k0, t);
                cpa_tile(st +   TILE_B, Al, row0, k0, t);
                cpa_tile(st + 2*TILE_B, Bh, col0, k0, t);
                cpa_tile(st + 3*TILE_B, Bl, col0, k0, t);
                CP_COMMIT();
                CP_WAIT1();
            } else {
                CP_WAIT0();
            }
            __syncthreads();
            compute_chunk2(acc, sb + (c & 1)*STAGE_B, warp_m, warp_n, lane);
            __syncthreads();
        }
    } else {
        // cheap: BK=64 per stage (hi tiles only), 8 steps
        cpa_tile(sb,            Ah, row0,  0, t);
        cpa_tile(sb +   TILE_B, Ah, row0, 32, t);
        cpa_tile(sb + 2*TILE_B, Bh, col0,  0, t);
        cpa_tile(sb + 3*TILE_B, Bh, col0, 32, t);
        CP_COMMIT();
        for (int c = 0; c < 8; ++c){
            if (c + 1 < 8){
                u32 st = sb + ((c+1) & 1)*STAGE_B;
                int k0 = (c+1)*64;
                cpa_tile(st,            Ah, row0, k0,      t);
                cpa_tile(st +   TILE_B, Ah, row0, k0 + 32, t);
                cpa_tile(st + 2*TILE_B, Bh, col0, k0,      t);
                cpa_tile(st + 3*TILE_B, Bh, col0, k0 + 32, t);
                CP_COMMIT();
                CP_WAIT1();
            } else {
                CP_WAIT0();
            }
            __syncthreads();
            u32 stg = sb + (c & 1)*STAGE_B;
            compute_chunk_cheap(acc, stg,          stg + 2*TILE_B, warp_m, warp_n, lane);
            compute_chunk_cheap(acc, stg + TILE_B, stg + 3*TILE_B, warp_m, warp_n, lane);
            __syncthreads();
        }
    }

    const int g = lane >> 2, tig = lane & 3;

    if (mode == 0){
        #pragma unroll
        for (int ma = 0; ma < 2; ma++){
            #pragma unroll
            for (int na = 0; na < 8; na++){
                const float* cc = acc[ma][na];
                int r0 = row0 + warp_m*32 + ma*16 + g;
                int col = col0 + warp_n*64 + na*8 + 2*tig;
                if (prec){
                    u32 h0, l0, h1, l1;
                    split2(cc[0], cc[1], h0, l0);
                    split2(cc[2], cc[3], h1, l1);
                    *(u32*)(Ohi + co + (size_t)r0*D + col)       = h0;
                    *(u32*)(Olo + co + (size_t)r0*D + col)       = l0;
                    *(u32*)(Ohi + co + (size_t)(r0+8)*D + col)   = h1;
                    *(u32*)(Olo + co + (size_t)(r0+8)*D + col)   = l1;
                } else {
                    *(u32*)(Ohi + co + (size_t)r0*D + col)
                        = pack_bf2(__float2bfloat16(cc[0]), __float2bfloat16(cc[1]));
                    *(u32*)(Ohi + co + (size_t)(r0+8)*D + col)
                        = pack_bf2(__float2bfloat16(cc[2]), __float2bfloat16(cc[3]));
                }
            }
        }
        return;
    }

    // ---- mode 1: fused symmetrizing epilogue ----
    u32* sh32 = (u32*)smem;
    #pragma unroll
    for (int ma = 0; ma < 2; ma++){
        #pragma unroll
        for (int na = 0; na < 8; na++){
            const float* cc = acc[ma][na];
            int rl = warp_m*32 + ma*16 + g;
            int cl = warp_n*64 + na*8 + 2*tig;
            #pragma unroll
            for (int h = 0; h < 2; h++){
                int r = rl + 8*h;
                size_t gidx = co + (size_t)(row0 + r)*D + col0 + cl;
                u32 xh = *(const u32*)(Bhi + gidx);   // B == current X
                u32 xl = *(const u32*)(Blo + gidx);
                __nv_bfloat162 bh2 = *(__nv_bfloat162*)&xh;
                __nv_bfloat162 bl2 = *(__nv_bfloat162*)&xl;
                float x0 = __bfloat162float(bh2.x) + __bfloat162float(bl2.x);
                float x1 = __bfloat162float(bh2.y) + __bfloat162float(bl2.y);
                float v0 = 2.0f*x0 - cc[2*h + 0];
                float v1 = 2.0f*x1 - cc[2*h + 1];
                bf16 h0 = __float2bfloat16(v0);
                bf16 l0 = __float2bfloat16(v0 - __bfloat162float(h0));
                bf16 h1 = __float2bfloat16(v1);
                bf16 l1 = __float2bfloat16(v1 - __bfloat162float(h1));
                sh32[r*PITCH + cl]     = pack_bf2(h0, l0);
                sh32[r*PITCH + cl + 1] = pack_bf2(h1, l1);
            }
        }
    }
    __syncthreads();

    const int wrow = t >> 5, lane5 = t & 31;
    if (bi != bj){
        #pragma unroll 4
        for (int it2 = 0; it2 < 16; it2++){
            int p = wrow + 8*it2;
            #pragma unroll
            for (int jq = 0; jq < 4; jq++){
                int q = lane5 + 32*jq;
                u32 u = sh32[p*PITCH + q];
                size_t di = co + (size_t)(row0 + p)*D + col0 + q;
                Ohi[di] = *(bf16*)&u;
                Olo[di] = *((bf16*)&u + 1);
                u32 ut = sh32[q*PITCH + p];
                size_t dt = co + (size_t)(col0 + p)*D + row0 + q;
                Ohi[dt] = *(bf16*)&ut;
                Olo[dt] = *((bf16*)&ut + 1);
            }
        }
    } else {
        #pragma unroll 4
        for (int it2 = 0; it2 < 16; it2++){
            int p = wrow + 8*it2;
            #pragma unroll
            for (int jq = 0; jq < 4; jq++){
                int q = lane5 + 32*jq;
                u32 u = (p >= q) ? sh32[p*PITCH + q] : sh32[q*PITCH + p];
                size_t di = co + (size_t)(row0 + p)*D + col0 + q;
                Ohi[di] = *(bf16*)&u;
                Olo[di] = *((bf16*)&u + 1);
            }
        }
    }
}

// ---------------- quad kernel: T = X*Lambda; part = dot(T, x - 2*mu) -----------
__global__ void __launch_bounds__(256, 2) mma_quad_kernel(
    const float* __restrict__ X, const float* __restrict__ muK,
    const bf16* __restrict__ Lhi, const bf16* __restrict__ Llo,
    float* __restrict__ part)
{
    extern __shared__ char smem[];
    const u32 sb = smem_u32(smem);
    const int t = threadIdx.x, lane = t & 31, wid = t >> 5;
    const int warp_m = wid & 3, warp_n = wid >> 2;
    const int cls = blockIdx.z;
    const size_t co = (size_t)cls*DD;
    const float* mu = muK + (size_t)cls*D;
    const int row0 = blockIdx.y*128, col0 = blockIdx.x*128;

    const bf16* Ah = g_XShi;      const bf16* Al = g_XSlo;
    const bf16* Bh = Lhi + co;    const bf16* Bl = Llo + co;

    float acc[2][8][4];
    #pragma unroll
    for (int ma = 0; ma < 2; ma++)
        #pragma unroll
        for (int na = 0; na < 8; na++)
            #pragma unroll
            for (int q = 0; q < 4; q++) acc[ma][na][q] = 0.f;

    cpa_tile(sb,            Ah, row0, 0, t);
    cpa_tile(sb +   TILE_B, Al, row0, 0, t);
    cpa_tile(sb + 2*TILE_B, Bh, col0, 0, t);
    cpa_tile(sb + 3*TILE_B, Bl, col0, 0, t);
    CP_COMMIT();

    for (int c = 0; c < 16; ++c){
        if (c + 1 < 16){
            u32 st = sb + ((c+1) & 1)*STAGE_B;
            int k0 = (c+1)*32;
            cpa_tile(st,            Ah, row0, k0, t);
            cpa_tile(st +   TILE_B, Al, row0, k0, t);
            cpa_tile(st + 2*TILE_B, Bh, col0, k0, t);
            cpa_tile(st + 3*TILE_B, Bl, col0, k0, t);
            CP_COMMIT();
            CP_WAIT1();
        } else {
            CP_WAIT0();
        }
        __syncthreads();
        compute_chunk2(acc, sb + (c & 1)*STAGE_B, warp_m, warp_n, lane);
        __syncthreads();
    }

    // epilogue: p = sum_j T[n,j]*(x_j - 2*mu_j) over this 128-col block
    const int g = lane >> 2, tig = lane & 3;
    float* sred = (float*)smem;   // [128][2]
    __syncthreads();

    #pragma unroll
    for (int ma = 0; ma < 2; ma++){
        float p0 = 0.f, p1 = 0.f;
        int r0 = row0 + warp_m*32 + ma*16 + g;
        int r1 = r0 + 8;
        #pragma unroll
        for (int na = 0; na < 8; na++){
            int col = col0 + warp_n*64 + na*8 + 2*tig;
            float m0 = 2.0f*mu[col], m1 = 2.0f*mu[col+1];
            float d00 = X[(size_t)r0*D + col]   - m0;
            float d01 = X[(size_t)r0*D + col+1] - m1;
            float d10 = X[(size_t)r1*D + col]   - m0;
            float d11 = X[(size_t)r1*D + col+1] - m1;
            const float* cc = acc[ma][na];
            p0 += cc[0]*d00 + cc[1]*d01;
            p1 += cc[2]*d10 + cc[3]*d11;
        }
        p0 += __shfl_down_sync(0xffffffffu, p0, 2);
        p0 += __shfl_down_sync(0xffffffffu, p0, 1);
        p1 += __shfl_down_sync(0xffffffffu, p1, 2);
        p1 += __shfl_down_sync(0xffffffffu, p1, 1);
        if (tig == 0){
            int rl0 = warp_m*32 + ma*16 + g;
            sred[rl0*2 + warp_n]     = p0;
            sred[(rl0+8)*2 + warp_n] = p1;
        }
    }
    __syncthreads();
    if (t < 128){
        float s = sred[t*2] + sred[t*2 + 1];
        part[((size_t)blockIdx.x*NX + row0 + t)*C + cls] = s;
    }
}

// ---------------- mu^T Lambda mu per class -------------------------------------
__global__ void __launch_bounds__(256) muLmu_kernel(const float* __restrict__ muK,
                                                    const bf16* __restrict__ Lhi,
                                                    const bf16* __restrict__ Llo)
{
    const int cls  = blockIdx.x;
    const int t    = threadIdx.x;
    const int lane = t & 31, warp = t >> 5;
    const size_t co = (size_t)cls*DD;
    const float* mu = muK + (size_t)cls*D;
    __shared__ float sm[D], w[D], red[256];

    for (int i = t; i < D; i += 256) sm[i] = mu[i];
    __syncthreads();

    for (int r = warp; r < D; r += 8){
        float s = 0.f;
        const bf16* Lh = Lhi + co + (size_t)r*D;
        const bf16* Ll = Llo + co + (size_t)r*D;
        for (int k = lane; k < D; k += 32)
            s += (__bfloat162float(Lh[k]) + __bfloat162float(Ll[k]))*sm[k];
        #pragma unroll
        for (int o = 16; o > 0; o >>= 1) s += __shfl_down_sync(0xffffffffu, s, o);
        if (lane == 0) w[r] = s;
    }
    __syncthreads();
    float acc = 0.f;
    for (int i = t; i < D; i += 256) acc += sm[i]*w[i];
    red[t] = acc; __syncthreads();
    for (int s = 128; s > 0; s >>= 1){ if (t < s) red[t] += red[t+s]; __syncthreads(); }
    if (t == 0) g_muLmu[cls] = red[0];
}

// ---------------- combine ------------------------------------------------------
__global__ void __launch_bounds__(256) combine_kernel(float* __restrict__ out)
{
    int idx = blockIdx.x*256 + threadIdx.x;
    if (idx >= NX*C) return;
    int c = idx % C;
    float q = g_part[idx] + g_part[NX*C + idx] + g_part[2*NX*C + idx] + g_part[3*NX*C + idx]
            + g_muLmu[c];
    out[idx] = g_base[c] - 0.5f*q;
}

// ---------------- host launcher ------------------------------------------------
extern "C" void kernel_launch(void* const* d_in, const int* in_sizes, int n_in,
                              void* d_out, int out_size)
{
    const float* X      = (const float*)d_in[0];
    const float* muK    = (const float*)d_in[1];
    const float* SigmaK = (const float*)d_in[2];
    const float* Sigma  = (const float*)d_in[3];
    const float* cK     = (const float*)d_in[4];
    float* out = (float*)d_out;

    float *pPart;
    bf16 *pMhi, *pMlo, *pXhi, *pXlo, *pYhi, *pYlo, *pZhi, *pZlo;
    cudaGetSymbolAddress((void**)&pMhi,  g_Mhi);
    cudaGetSymbolAddress((void**)&pMlo,  g_Mlo);
    cudaGetSymbolAddress((void**)&pXhi,  g_Xhi);
    cudaGetSymbolAddress((void**)&pXlo,  g_Xlo);
    cudaGetSymbolAddress((void**)&pYhi,  g_Yhi);
    cudaGetSymbolAddress((void**)&pYlo,  g_Ylo);
    cudaGetSymbolAddress((void**)&pZhi,  g_Zhi);
    cudaGetSymbolAddress((void**)&pZlo,  g_Zlo);
    cudaGetSymbolAddress((void**)&pPart, g_part);

    cudaFuncSetAttribute(mma_newton_kernel, cudaFuncAttributeMaxDynamicSharedMemorySize, SMEM_DYN);
    cudaFuncSetAttribute(mma_quad_kernel,   cudaFuncAttributeMaxDynamicSharedMemorySize, SMEM_DYN);

    prep_kernel <<<dim3(64, C), 256>>>(SigmaK, Sigma);
    splitx_kernel<<<NX*D/(256*4), 256>>>(X);
    power_kernel<<<C, 256>>>(cK);
    setx0_kernel<<<dim3(64, C), 256>>>();

    bf16 *curh = pXhi, *curl = pXlo, *nxth = pZhi, *nxtl = pZlo;
    for (int it = 0; it < NEWTON_ITERS; ++it){
        int prec = (it >= CHEAP_ITERS) ? 1 : 0;
        mma_newton_kernel<<<dim3(16, 1, C), 256, SMEM_DYN>>>(
            curh, curl, pMhi, pMlo, pYhi, pYlo, 0, prec);
        mma_newton_kernel<<<dim3(10, 1, C), 256, SMEM_DYN>>>(
            pYhi, pYlo, curh, curl, nxth, nxtl, 1, prec);
        bf16* th = curh; curh = nxth; nxth = th;
        bf16* tl = curl; curl = nxtl; nxtl = tl;
    }

    muLmu_kernel  <<<C, 256>>>(muK, curh, curl);
    mma_quad_kernel<<<dim3(4, 16, C), 256, SMEM_DYN>>>(X, muK, curh, curl, pPart);
    combine_kernel <<<(NX*C + 255)/256, 256>>>(out);
}

// round 12
// speedup vs baseline: 4.3776x; 1.0664x over previous
#include <cuda_runtime.h>
#include <cuda_bf16.h>
#include <math.h>
#include <stdint.h>

// ---------------- problem constants ----------------
#define D      512
#define C      100
#define NX     2048
#define DD     (D*D)
#define ALPHA  0.5f
#define SHRINK 1e-4f
#define OMS    (1.0f - SHRINK)

#define NEWTON_ITERS 8
#define CHEAP_ITERS  6      // iters [0, CHEAP_ITERS) use bf16-only products
#define POWER_ITERS  4

typedef unsigned int u32;
typedef __nv_bfloat16 bf16;

// ---------------- scratch (device globals; no allocs allowed) ----------------
__device__ bf16  g_Mhi[C*DD];
__device__ bf16  g_Mlo[C*DD];
__device__ bf16  g_Xhi[C*DD];    // Newton iterate ping
__device__ bf16  g_Xlo[C*DD];
__device__ bf16  g_Yhi[C*DD];    // T = X*M
__device__ bf16  g_Ylo[C*DD];
__device__ bf16  g_Zhi[C*DD];    // Newton iterate pong
__device__ bf16  g_Zlo[C*DD];
__device__ bf16  g_XShi[NX*D];   // presplit test matrix X
__device__ bf16  g_XSlo[NX*D];
__device__ float g_fpart[C*64];
__device__ float g_ab[C];
__device__ float g_base[C];
__device__ float g_muLmu8[C*8];  // 8 row-slice partials of mu^T Lambda mu
__device__ float g_part[4*NX*C];

// ---------------- PTX helpers -------------------------------------------------
__device__ __forceinline__ u32 smem_u32(const void* p){
    u32 a; asm("{ .reg .u64 t; cvta.to.shared.u64 t, %1; cvt.u32.u64 %0, t; }" : "=r"(a) : "l"(p));
    return a;
}
#define CPA16(dst, src) \
    asm volatile("cp.async.cg.shared.global [%0], [%1], 16;" :: "r"(dst), "l"(src) : "memory")
#define CP_COMMIT() asm volatile("cp.async.commit_group;" ::: "memory")
#define CP_WAIT1()  asm volatile("cp.async.wait_group 1;" ::: "memory")
#define CP_WAIT0()  asm volatile("cp.async.wait_group 0;" ::: "memory")

#define LDMX4(d0, d1, d2, d3, addr) \
    asm volatile("ldmatrix.sync.aligned.m8n8.x4.shared.b16 {%0,%1,%2,%3}, [%4];" \
        : "=r"(d0), "=r"(d1), "=r"(d2), "=r"(d3) : "r"(addr))

#define MMA(c, a, b) \
    asm volatile("mma.sync.aligned.m16n8k16.row.col.f32.bf16.bf16.f32 " \
        "{%0,%1,%2,%3}, {%4,%5,%6,%7}, {%8,%9}, {%0,%1,%2,%3};" \
        : "+f"((c)[0]), "+f"((c)[1]), "+f"((c)[2]), "+f"((c)[3]) \
        : "r"((a)[0]), "r"((a)[1]), "r"((a)[2]), "r"((a)[3]), "r"((b)[0]), "r"((b)[1]))

// ---------------- smem layout --------------------------------------------------
#define ROWB    80
#define TILE_B  10240
#define STAGE_B 40960
#define SMEM_DYN (2*STAGE_B)
#define PITCH   129

__device__ __forceinline__ u32 pack_bf2(bf16 a, bf16 b){
    __nv_bfloat162 v = __halves2bfloat162(a, b);
    return *(u32*)&v;
}
__device__ __forceinline__ void split2(float a, float b, u32& h, u32& l){
    bf16 ha = __float2bfloat16(a), hb = __float2bfloat16(b);
    bf16 la = __float2bfloat16(a - __bfloat162float(ha));
    bf16 lb = __float2bfloat16(b - __bfloat162float(hb));
    h = pack_bf2(ha, hb); l = pack_bf2(la, lb);
}

// ---------------- loaders ------------------------------------------------------
__device__ __forceinline__ void cpa_tile(u32 sdst, const bf16* __restrict__ g,
                                         int row0, int k0, int t){
    int r = t >> 1, half = t & 1;
    const bf16* src = g + (size_t)(row0 + r)*D + k0 + half*16;
    u32 dst = sdst + r*ROWB + half*32;
    CPA16(dst,      src);
    CPA16(dst + 16, src + 8);
}

// ---------------- warp-tile compute --------------------------------------------
// Precise: 3 split products, BK=32 chunk.
__device__ __forceinline__ void compute_chunk2(float acc[2][8][4], u32 stage,
                                               int warp_m, int warp_n, int lane){
    const u32 aoff = stage + (warp_m*32 + (lane & 15))*ROWB + (lane >> 4)*16;
    const u32 boff = stage + 2*TILE_B
                   + (warp_n*64 + (lane & 7) + ((lane >> 4) << 3))*ROWB
                   + ((lane >> 3) & 1)*16;
    #pragma unroll
    for (int ks = 0; ks < 2; ks++){
        u32 ah[2][4], al[2][4], b[8][2];
        #pragma unroll
        for (int ma = 0; ma < 2; ma++){
            LDMX4(ah[ma][0], ah[ma][1], ah[ma][2], ah[ma][3], aoff + ma*1280 + ks*32);
            LDMX4(al[ma][0], al[ma][1], al[ma][2], al[ma][3], aoff + TILE_B + ma*1280 + ks*32);
        }
        #pragma unroll
        for (int p = 0; p < 4; p++)
            LDMX4(b[2*p][0], b[2*p][1], b[2*p+1][0], b[2*p+1][1], boff + p*1280 + ks*32);
        #pragma unroll
        for (int ma = 0; ma < 2; ma++)
            #pragma unroll
            for (int na = 0; na < 8; na++){
                MMA(acc[ma][na], ah[ma], b[na]);
                MMA(acc[ma][na], al[ma], b[na]);
            }
        #pragma unroll
        for (int p = 0; p < 4; p++)
            LDMX4(b[2*p][0], b[2*p][1], b[2*p+1][0], b[2*p+1][1], boff + TILE_B + p*1280 + ks*32);
        #pragma unroll
        for (int ma = 0; ma < 2; ma++)
            #pragma unroll
            for (int na = 0; na < 8; na++)
                MMA(acc[ma][na], ah[ma], b[na]);
    }
}

// Cheap: single bf16 product on one BK=32 sub-chunk; A at abase, B at bbase
__device__ __forceinline__ void compute_chunk_cheap(float acc[2][8][4],
                                                    u32 abase, u32 bbase,
                                                    int warp_m, int warp_n, int lane){
    const u32 aoff = abase + (warp_m*32 + (lane & 15))*ROWB + (lane >> 4)*16;
    const u32 boff = bbase + (warp_n*64 + (lane & 7) + ((lane >> 4) << 3))*ROWB
                   + ((lane >> 3) & 1)*16;
    #pragma unroll
    for (int ks = 0; ks < 2; ks++){
        u32 ah[2][4], b[8][2];
        #pragma unroll
        for (int ma = 0; ma < 2; ma++)
            LDMX4(ah[ma][0], ah[ma][1], ah[ma][2], ah[ma][3], aoff + ma*1280 + ks*32);
        #pragma unroll
        for (int p = 0; p < 4; p++)
            LDMX4(b[2*p][0], b[2*p][1], b[2*p+1][0], b[2*p+1][1], boff + p*1280 + ks*32);
        #pragma unroll
        for (int ma = 0; ma < 2; ma++)
            #pragma unroll
            for (int na = 0; na < 8; na++)
                MMA(acc[ma][na], ah[ma], b[na]);
    }
}

// ---------------- prep: build split(M), Frobenius partials ---------------------
__global__ void __launch_bounds__(256) prep_kernel(const float* __restrict__ SigmaK,
                                                   const float* __restrict__ Sigma)
{
    const int cls = blockIdx.y;
    const int t   = threadIdx.x;
    const size_t co = (size_t)cls*DD;
    const float4* Sk = (const float4*)(SigmaK + co);
    const float4* Sg = (const float4*)Sigma;
    float fr = 0.f;
    #pragma unroll
    for (int j = 0; j < 4; j++){
        int id = blockIdx.x*1024 + j*256 + t;
        float4 a = Sk[id], b = Sg[id];
        float4 r;
        r.x = ALPHA*a.x + (1.0f-ALPHA)*b.x;
        r.y = ALPHA*a.y + (1.0f-ALPHA)*b.y;
        r.z = ALPHA*a.z + (1.0f-ALPHA)*b.z;
        r.w = ALPHA*a.w + (1.0f-ALPHA)*b.w;
        fr += r.x*r.x + r.y*r.y + r.z*r.z + r.w*r.w;
        float4 m;
        m.x = OMS*r.x; m.y = OMS*r.y; m.z = OMS*r.z; m.w = OMS*r.w;
        int e = id*4, row = e >> 9, c0 = e & (D-1);
        int dg = row - c0;
        if (dg >= 0 && dg < 4) ((float*)&m)[dg] += SHRINK;
        alignas(8) bf16 hh[4], ll[4];
        #pragma unroll
        for (int q = 0; q < 4; q++){
            float v = ((float*)&m)[q];
            hh[q] = __float2bfloat16(v);
            ll[q] = __float2bfloat16(v - __bfloat162float(hh[q]));
        }
        *(uint2*)(g_Mhi + co + e) = *(const uint2*)hh;
        *(uint2*)(g_Mlo + co + e) = *(const uint2*)ll;
    }
    __shared__ float red[256];
    red[t] = fr; __syncthreads();
    for (int s = 128; s > 0; s >>= 1){ if (t < s) red[t] += red[t+s]; __syncthreads(); }
    if (t == 0) g_fpart[cls*64 + blockIdx.x] = red[0];
}

// ---------------- split X once -------------------------------------------------
__global__ void __launch_bounds__(256) splitx_kernel(const float* __restrict__ X)
{
    int id = blockIdx.x*256 + threadIdx.x;      // float4 index, NX*D/4 total
    float4 v = ((const float4*)X)[id];
    alignas(8) bf16 hh[4], ll[4];
    #pragma unroll
    for (int q = 0; q < 4; q++){
        float x = ((float*)&v)[q];
        hh[q] = __float2bfloat16(x);
        ll[q] = __float2bfloat16(x - __bfloat162float(hh[q]));
    }
    *(uint2*)(g_XShi + id*4) = *(const uint2*)hh;
    *(uint2*)(g_XSlo + id*4) = *(const uint2*)ll;
}

// ---------------- power iteration (bf16 M) + per-class constants ---------------
__global__ void __launch_bounds__(256) power_kernel(const float* __restrict__ cK)
{
    const int cls  = blockIdx.x;
    const int t    = threadIdx.x;
    const int lane = t & 31, warp = t >> 5;
    const bf16* Mc = g_Mhi + (size_t)cls*DD;
    __shared__ float v[D], w[D], red[256];

    float x = (t < 64) ? g_fpart[cls*64 + t] : 0.f;
    red[t] = x; __syncthreads();
    for (int s = 128; s > 0; s >>= 1){ if (t < s) red[t] += red[t+s]; __syncthreads(); }
    float frobsq = red[0]; __syncthreads();

    float ckv = (t < C) ? cK[t] : 0.f;
    red[t] = ckv; __syncthreads();
    for (int s = 128; s > 0; s >>= 1){ if (t < s) red[t] += red[t+s]; __syncthreads(); }
    float csum = red[0]; __syncthreads();

    for (int i = t; i < D; i += 256) v[i] = 1.0f;
    __syncthreads();

    float lam = 1.0f;
    for (int it = 0; it < POWER_ITERS; ++it){
        for (int r = warp; r < D; r += 8){
            float s = 0.f;
            const bf16* Mr = Mc + (size_t)r*D;
            for (int k = lane; k < D; k += 32) s += __bfloat162float(Mr[k])*v[k];
            #pragma unroll
            for (int o = 16; o > 0; o >>= 1) s += __shfl_down_sync(0xffffffffu, s, o);
            if (lane == 0) w[r] = s;
        }
        __syncthreads();
        float ns = 0.f;
        for (int i = t; i < D; i += 256) ns += w[i]*w[i];
        red[t] = ns; __syncthreads();
        for (int s = 128; s > 0; s >>= 1){ if (t < s) red[t] += red[t+s]; __syncthreads(); }
        lam = sqrtf(red[0]); __syncthreads();
        float inv = 1.0f/lam;
        for (int i = t; i < D; i += 256) v[i] = w[i]*inv;
        __syncthreads();
    }

    if (t == 0){
        float bound = 1.5f*lam + 0.3f;   // wide safety: 4 iters + bf16 matvec
        g_ab[cls] = 2.0f/(0.09f + bound);
        float c0 = cK[cls];
        g_base[cls] = (c0 > 0.f) ? (logf(c0/csum) - 0.25f*logf(frobsq)) : -INFINITY;
    }
}

// ---------------- X0 = a*I in split bf16 ---------------------------------------
__global__ void __launch_bounds__(256) setx0_kernel()
{
    const int cls = blockIdx.y;
    const size_t co = (size_t)cls*DD;
    const float a = g_ab[cls];
    bf16 ahi = __float2bfloat16(a);
    bf16 alo = __float2bfloat16(a - __bfloat162float(ahi));
    const int t = threadIdx.x;
    #pragma unroll
    for (int j = 0; j < 4; j++){
        int id = blockIdx.x*1024 + j*256 + t;
        alignas(8) bf16 hh[4] = {bf16(0.f), bf16(0.f), bf16(0.f), bf16(0.f)};
        alignas(8) bf16 ll[4] = {bf16(0.f), bf16(0.f), bf16(0.f), bf16(0.f)};
        int e = id*4, row = e >> 9, c0 = e & (D-1);
        int dg = row - c0;
        if (dg >= 0 && dg < 4){ hh[dg] = ahi; ll[dg] = alo; }
        *(uint2*)(g_Xhi + co + e) = *(const uint2*)hh;
        *(uint2*)(g_Xlo + co + e) = *(const uint2*)ll;
    }
}

// ---------------- Newton GEMM (mma.sync, split-bf16 / cheap bf16) --------------
__global__ void __launch_bounds__(256, 2) mma_newton_kernel(
    const bf16* __restrict__ Ahi, const bf16* __restrict__ Alo,
    const bf16* __restrict__ Bhi, const bf16* __restrict__ Blo,
    bf16* __restrict__ Ohi, bf16* __restrict__ Olo, int mode, int prec)
{
    extern __shared__ char smem[];
    const u32 sb = smem_u32(smem);
    const int t = threadIdx.x, lane = t & 31, wid = t >> 5;
    const int warp_m = wid & 3, warp_n = wid >> 2;
    const int cls = blockIdx.z;
    const size_t co = (size_t)cls*DD;

    int bi, bj;
    if (mode == 1){
        int i = blockIdx.x; bi = 0;
        while (i >= bi + 1){ i -= bi + 1; bi++; }
        bj = i;
    } else { bi = blockIdx.x >> 2; bj = blockIdx.x & 3; }
    const int row0 = bi*128, col0 = bj*128;

    const bf16* Ah = Ahi + co; const bf16* Al = Alo + co;
    const bf16* Bh = Bhi + co; const bf16* Bl = Blo + co;

    float acc[2][8][4];
    #pragma unroll
    for (int ma = 0; ma < 2; ma++)
        #pragma unroll
        for (int na = 0; na < 8; na++)
            #pragma unroll
            for (int q = 0; q < 4; q++) acc[ma][na][q] = 0.f;

    if (prec){
        cpa_tile(sb,            Ah, row0, 0, t);
        cpa_tile(sb +   TILE_B, Al, row0, 0, t);
        cpa_tile(sb + 2*TILE_B, Bh, col0, 0, t);
        cpa_tile(sb + 3*TILE_B, Bl, col0, 0, t);
        CP_COMMIT();
        for (int c = 0; c < 16; ++c){
            if (c + 1 < 16){
                u32 st = sb + ((c+1) & 1)*STAGE_B;
                int k0 = (c+1)*32;
                cpa_tile(st,            Ah, row0, k0, t);
                cpa_tile(st +   TILE_B, Al, row0, k0, t);
                cpa_tile(st + 2*TILE_B, Bh, col0, k0, t);
                cpa_tile(st + 3*TILE_B, Bl, col0, k0, t);
                CP_COMMIT();
                CP_WAIT1();
            } else {
                CP_WAIT0();
            }
            __syncthreads();
            compute_chunk2(acc, sb + (c & 1)*STAGE_B, warp_m, warp_n, lane);
            __syncthreads();
        }
    } else {
        cpa_tile(sb,            Ah, row0,  0, t);
        cpa_tile(sb +   TILE_B, Ah, row0, 32, t);
        cpa_tile(sb + 2*TILE_B, Bh, col0,  0, t);
        cpa_tile(sb + 3*TILE_B, Bh, col0, 32, t);
        CP_COMMIT();
        for (int c = 0; c < 8; ++c){
            if (c + 1 < 8){
                u32 st = sb + ((c+1) & 1)*STAGE_B;
                int k0 = (c+1)*64;
                cpa_tile(st,            Ah, row0, k0,      t);
                cpa_tile(st +   TILE_B, Ah, row0, k0 + 32, t);
                cpa_tile(st + 2*TILE_B, Bh, col0, k0,      t);
                cpa_tile(st + 3*TILE_B, Bh, col0, k0 + 32, t);
                CP_COMMIT();
                CP_WAIT1();
            } else {
                CP_WAIT0();
            }
            __syncthreads();
            u32 stg = sb + (c & 1)*STAGE_B;
            compute_chunk_cheap(acc, stg,          stg + 2*TILE_B, warp_m, warp_n, lane);
            compute_chunk_cheap(acc, stg + TILE_B, stg + 3*TILE_B, warp_m, warp_n, lane);
            __syncthreads();
        }
    }

    const int g = lane >> 2, tig = lane & 3;

    if (mode == 0){
        #pragma unroll
        for (int ma = 0; ma < 2; ma++){
            #pragma unroll
            for (int na = 0; na < 8; na++){
                const float* cc = acc[ma][na];
                int r0 = row0 + warp_m*32 + ma*16 + g;
                int col = col0 + warp_n*64 + na*8 + 2*tig;
                if (prec){
                    u32 h0, l0, h1, l1;
                    split2(cc[0], cc[1], h0, l0);
                    split2(cc[2], cc[3], h1, l1);
                    *(u32*)(Ohi + co + (size_t)r0*D + col)       = h0;
                    *(u32*)(Olo + co + (size_t)r0*D + col)       = l0;
                    *(u32*)(Ohi + co + (size_t)(r0+8)*D + col)   = h1;
                    *(u32*)(Olo + co + (size_t)(r0+8)*D + col)   = l1;
                } else {
                    *(u32*)(Ohi + co + (size_t)r0*D + col)
                        = pack_bf2(__float2bfloat16(cc[0]), __float2bfloat16(cc[1]));
                    *(u32*)(Ohi + co + (size_t)(r0+8)*D + col)
                        = pack_bf2(__float2bfloat16(cc[2]), __float2bfloat16(cc[3]));
                }
            }
        }
        return;
    }

    // ---- mode 1: fused symmetrizing epilogue ----
    u32* sh32 = (u32*)smem;
    #pragma unroll
    for (int ma = 0; ma < 2; ma++){
        #pragma unroll
        for (int na = 0; na < 8; na++){
            const float* cc = acc[ma][na];
            int rl = warp_m*32 + ma*16 + g;
            int cl = warp_n*64 + na*8 + 2*tig;
            #pragma unroll
            for (int h = 0; h < 2; h++){
                int r = rl + 8*h;
                size_t gidx = co + (size_t)(row0 + r)*D + col0 + cl;
                u32 xh = *(const u32*)(Bhi + gidx);   // B == current X
                u32 xl = *(const u32*)(Blo + gidx);
                __nv_bfloat162 bh2 = *(__nv_bfloat162*)&xh;
                __nv_bfloat162 bl2 = *(__nv_bfloat162*)&xl;
                float x0 = __bfloat162float(bh2.x) + __bfloat162float(bl2.x);
                float x1 = __bfloat162float(bh2.y) + __bfloat162float(bl2.y);
                float v0 = 2.0f*x0 - cc[2*h + 0];
                float v1 = 2.0f*x1 - cc[2*h + 1];
                bf16 h0 = __float2bfloat16(v0);
                bf16 l0 = __float2bfloat16(v0 - __bfloat162float(h0));
                bf16 h1 = __float2bfloat16(v1);
                bf16 l1 = __float2bfloat16(v1 - __bfloat162float(h1));
                sh32[r*PITCH + cl]     = pack_bf2(h0, l0);
                sh32[r*PITCH + cl + 1] = pack_bf2(h1, l1);
            }
        }
    }
    __syncthreads();

    const int wrow = t >> 5, lane5 = t & 31;
    if (bi != bj){
        #pragma unroll 4
        for (int it2 = 0; it2 < 16; it2++){
            int p = wrow + 8*it2;
            #pragma unroll
            for (int jq = 0; jq < 4; jq++){
                int q = lane5 + 32*jq;
                u32 u = sh32[p*PITCH + q];
                size_t di = co + (size_t)(row0 + p)*D + col0 + q;
                Ohi[di] = *(bf16*)&u;
                Olo[di] = *((bf16*)&u + 1);
                u32 ut = sh32[q*PITCH + p];
                size_t dt = co + (size_t)(col0 + p)*D + row0 + q;
                Ohi[dt] = *(bf16*)&ut;
                Olo[dt] = *((bf16*)&ut + 1);
            }
        }
    } else {
        #pragma unroll 4
        for (int it2 = 0; it2 < 16; it2++){
            int p = wrow + 8*it2;
            #pragma unroll
            for (int jq = 0; jq < 4; jq++){
                int q = lane5 + 32*jq;
                u32 u = (p >= q) ? sh32[p*PITCH + q] : sh32[q*PITCH + p];
                size_t di = co + (size_t)(row0 + p)*D + col0 + q;
                Ohi[di] = *(bf16*)&u;
                Olo[di] = *((bf16*)&u + 1);
            }
        }
    }
}

// ---------------- quad kernel: T = X*Lambda; part = dot(T, x - 2*mu) -----------
__global__ void __launch_bounds__(256, 2) mma_quad_kernel(
    const float* __restrict__ X, const float* __restrict__ muK,
    const bf16* __restrict__ Lhi, const bf16* __restrict__ Llo,
    float* __restrict__ part)
{
    extern __shared__ char smem[];
    const u32 sb = smem_u32(smem);
    const int t = threadIdx.x, lane = t & 31, wid = t >> 5;
    const int warp_m = wid & 3, warp_n = wid >> 2;
    const int cls = blockIdx.z;
    const size_t co = (size_t)cls*DD;
    const float* mu = muK + (size_t)cls*D;
    const int row0 = blockIdx.y*128, col0 = blockIdx.x*128;

    const bf16* Ah = g_XShi;      const bf16* Al = g_XSlo;
    const bf16* Bh = Lhi + co;    const bf16* Bl = Llo + co;

    float acc[2][8][4];
    #pragma unroll
    for (int ma = 0; ma < 2; ma++)
        #pragma unroll
        for (int na = 0; na < 8; na++)
            #pragma unroll
            for (int q = 0; q < 4; q++) acc[ma][na][q] = 0.f;

    cpa_tile(sb,            Ah, row0, 0, t);
    cpa_tile(sb +   TILE_B, Al, row0, 0, t);
    cpa_tile(sb + 2*TILE_B, Bh, col0, 0, t);
    cpa_tile(sb + 3*TILE_B, Bl, col0, 0, t);
    CP_COMMIT();

    for (int c = 0; c < 16; ++c){
        if (c + 1 < 16){
            u32 st = sb + ((c+1) & 1)*STAGE_B;
            int k0 = (c+1)*32;
            cpa_tile(st,            Ah, row0, k0, t);
            cpa_tile(st +   TILE_B, Al, row0, k0, t);
            cpa_tile(st + 2*TILE_B, Bh, col0, k0, t);
            cpa_tile(st + 3*TILE_B, Bl, col0, k0, t);
            CP_COMMIT();
            CP_WAIT1();
        } else {
            CP_WAIT0();
        }
        __syncthreads();
        compute_chunk2(acc, sb + (c & 1)*STAGE_B, warp_m, warp_n, lane);
        __syncthreads();
    }

    // epilogue: p = sum_j T[n,j]*(x_j - 2*mu_j) over this 128-col block
    const int g = lane >> 2, tig = lane & 3;
    float* sred = (float*)smem;   // [128][2]
    __syncthreads();

    #pragma unroll
    for (int ma = 0; ma < 2; ma++){
        float p0 = 0.f, p1 = 0.f;
        int r0 = row0 + warp_m*32 + ma*16 + g;
        int r1 = r0 + 8;
        #pragma unroll
        for (int na = 0; na < 8; na++){
            int col = col0 + warp_n*64 + na*8 + 2*tig;
            float m0 = 2.0f*mu[col], m1 = 2.0f*mu[col+1];
            float d00 = X[(size_t)r0*D + col]   - m0;
            float d01 = X[(size_t)r0*D + col+1] - m1;
            float d10 = X[(size_t)r1*D + col]   - m0;
            float d11 = X[(size_t)r1*D + col+1] - m1;
            const float* cc = acc[ma][na];
            p0 += cc[0]*d00 + cc[1]*d01;
            p1 += cc[2]*d10 + cc[3]*d11;
        }
        p0 += __shfl_down_sync(0xffffffffu, p0, 2);
        p0 += __shfl_down_sync(0xffffffffu, p0, 1);
        p1 += __shfl_down_sync(0xffffffffu, p1, 2);
        p1 += __shfl_down_sync(0xffffffffu, p1, 1);
        if (tig == 0){
            int rl0 = warp_m*32 + ma*16 + g;
            sred[rl0*2 + warp_n]     = p0;
            sred[(rl0+8)*2 + warp_n] = p1;
        }
    }
    __syncthreads();
    if (t < 128){
        float s = sred[t*2] + sred[t*2 + 1];
        part[((size_t)blockIdx.x*NX + row0 + t)*C + cls] = s;
    }
}

// ---------------- mu^T Lambda mu, 8 row-slices per class -----------------------
// grid (8, C), 256 thr; slice s covers rows [s*64, s*64+64)
__global__ void __launch_bounds__(256) muLmu_kernel(const float* __restrict__ muK,
                                                    const bf16* __restrict__ Lhi,
                                                    const bf16* __restrict__ Llo)
{
    const int slice = blockIdx.x;
    const int cls   = blockIdx.y;
    const int t     = threadIdx.x;
    const int lane  = t & 31, warp = t >> 5;
    const size_t co = (size_t)cls*DD;
    const float* mu = muK + (size_t)cls*D;
    __shared__ float sm[D], red[256];

    for (int i = t; i < D; i += 256) sm[i] = mu[i];
    __syncthreads();

    // rows r = slice*64 + warp*8 .. +8 (each warp: 8 rows)
    float acc = 0.f;
    #pragma unroll
    for (int rr = 0; rr < 8; rr++){
        int r = slice*64 + warp*8 + rr;
        const bf16* Lh = Lhi + co + (size_t)r*D;
        const bf16* Ll = Llo + co + (size_t)r*D;
        float s = 0.f;
        for (int k = lane; k < D; k += 32)
            s += (__bfloat162float(Lh[k]) + __bfloat162float(Ll[k]))*sm[k];
        #pragma unroll
        for (int o = 16; o > 0; o >>= 1) s += __shfl_down_sync(0xffffffffu, s, o);
        if (lane == 0) acc += s*sm[r];
    }
    red[t] = (lane == 0) ? acc : 0.f;
    __syncthreads();
    for (int s = 128; s > 0; s >>= 1){ if (t < s) red[t] += red[t+s]; __syncthreads(); }
    if (t == 0) g_muLmu8[cls*8 + slice] = red[0];
}

// ---------------- combine ------------------------------------------------------
__global__ void __launch_bounds__(256) combine_kernel(float* __restrict__ out)
{
    int idx = blockIdx.x*256 + threadIdx.x;
    if (idx >= NX*C) return;
    int c = idx % C;
    float ml = 0.f;
    #pragma unroll
    for (int s = 0; s < 8; s++) ml += g_muLmu8[c*8 + s];
    float q = g_part[idx] + g_part[NX*C + idx] + g_part[2*NX*C + idx] + g_part[3*NX*C + idx]
            + ml;
    out[idx] = g_base[c] - 0.5f*q;
}

// ---------------- host launcher ------------------------------------------------
extern "C" void kernel_launch(void* const* d_in, const int* in_sizes, int n_in,
                              void* d_out, int out_size)
{
    const float* X      = (const float*)d_in[0];
    const float* muK    = (const float*)d_in[1];
    const float* SigmaK = (const float*)d_in[2];
    const float* Sigma  = (const float*)d_in[3];
    const float* cK     = (const float*)d_in[4];
    float* out = (float*)d_out;

    float *pPart;
    bf16 *pMhi, *pMlo, *pXhi, *pXlo, *pYhi, *pYlo, *pZhi, *pZlo;
    cudaGetSymbolAddress((void**)&pMhi,  g_Mhi);
    cudaGetSymbolAddress((void**)&pMlo,  g_Mlo);
    cudaGetSymbolAddress((void**)&pXhi,  g_Xhi);
    cudaGetSymbolAddress((void**)&pXlo,  g_Xlo);
    cudaGetSymbolAddress((void**)&pYhi,  g_Yhi);
    cudaGetSymbolAddress((void**)&pYlo,  g_Ylo);
    cudaGetSymbolAddress((void**)&pZhi,  g_Zhi);
    cudaGetSymbolAddress((void**)&pZlo,  g_Zlo);
    cudaGetSymbolAddress((void**)&pPart, g_part);

    cudaFuncSetAttribute(mma_newton_kernel, cudaFuncAttributeMaxDynamicSharedMemorySize, SMEM_DYN);
    cudaFuncSetAttribute(mma_quad_kernel,   cudaFuncAttributeMaxDynamicSharedMemorySize, SMEM_DYN);

    prep_kernel  <<<dim3(64, C), 256>>>(SigmaK, Sigma);
    splitx_kernel<<<NX*D/(256*4), 256>>>(X);
    power_kernel <<<C, 256>>>(cK);
    setx0_kernel <<<dim3(64, C), 256>>>();

    bf16 *curh = pXhi, *curl = pXlo, *nxth = pZhi, *nxtl = pZlo;
    for (int it = 0; it < NEWTON_ITERS; ++it){
        int prec = (it >= CHEAP_ITERS) ? 1 : 0;
        mma_newton_kernel<<<dim3(16, 1, C), 256, SMEM_DYN>>>(
            curh, curl, pMhi, pMlo, pYhi, pYlo, 0, prec);
        mma_newton_kernel<<<dim3(10, 1, C), 256, SMEM_DYN>>>(
            pYhi, pYlo, curh, curl, nxth, nxtl, 1, prec);
        bf16* th = curh; curh = nxth; nxth = th;
        bf16* tl = curl; curl = nxtl; nxtl = tl;
    }

    muLmu_kernel  <<<dim3(8, C), 256>>>(muK, curh, curl);
    mma_quad_kernel<<<dim3(4, 16, C), 256, SMEM_DYN>>>(X, muK, curh, curl, pPart);
    combine_kernel <<<(NX*C + 255)/256, 256>>>(out);
}

// round 14
// speedup vs baseline: 4.8288x; 1.1031x over previous
#include <cuda_runtime.h>
#include <cuda_bf16.h>
#include <math.h>
#include <stdint.h>

// ---------------- problem constants ----------------
#define D      512
#define C      100
#define NX     2048
#define DD     (D*D)
#define ALPHA  0.5f
#define SHRINK 1e-4f
#define OMS    (1.0f - SHRINK)

#define NEWTON_ITERS 7
#define CHEAP_ITERS  5      // iters [0, CHEAP_ITERS) use bf16-only products
#define POWER_ITERS  8

typedef unsigned int u32;
typedef __nv_bfloat16 bf16;

// ---------------- scratch (device globals; no allocs allowed) ----------------
__device__ bf16  g_Mhi[C*DD];
__device__ bf16  g_Mlo[C*DD];
__device__ bf16  g_Xhi[C*DD];    // Newton iterate ping
__device__ bf16  g_Xlo[C*DD];
__device__ bf16  g_Yhi[C*DD];    // T = X*M
__device__ bf16  g_Ylo[C*DD];
__device__ bf16  g_Zhi[C*DD];    // Newton iterate pong
__device__ bf16  g_Zlo[C*DD];
__device__ bf16  g_XShi[NX*D];   // presplit test matrix X
__device__ bf16  g_XSlo[NX*D];
__device__ float g_fpart[C*64];
__device__ float g_ab[C];
__device__ float g_base[C];
__device__ float g_muLmu8[C*8];  // 8 row-slice partials of mu^T Lambda mu
__device__ float g_part[4*NX*C];

// ---------------- PTX helpers -------------------------------------------------
__device__ __forceinline__ u32 smem_u32(const void* p){
    u32 a; asm("{ .reg .u64 t; cvta.to.shared.u64 t, %1; cvt.u32.u64 %0, t; }" : "=r"(a) : "l"(p));
    return a;
}
#define CPA16(dst, src) \
    asm volatile("cp.async.cg.shared.global [%0], [%1], 16;" :: "r"(dst), "l"(src) : "memory")
#define CP_COMMIT() asm volatile("cp.async.commit_group;" ::: "memory")
#define CP_WAIT0()  asm volatile("cp.async.wait_group 0;" ::: "memory")

#define LDMX4(d0, d1, d2, d3, addr) \
    asm volatile("ldmatrix.sync.aligned.m8n8.x4.shared.b16 {%0,%1,%2,%3}, [%4];" \
        : "=r"(d0), "=r"(d1), "=r"(d2), "=r"(d3) : "r"(addr))

#define MMA(c, a, b) \
    asm volatile("mma.sync.aligned.m16n8k16.row.col.f32.bf16.bf16.f32 " \
        "{%0,%1,%2,%3}, {%4,%5,%6,%7}, {%8,%9}, {%0,%1,%2,%3};" \
        : "+f"((c)[0]), "+f"((c)[1]), "+f"((c)[2]), "+f"((c)[3]) \
        : "r"((a)[0]), "r"((a)[1]), "r"((a)[2]), "r"((a)[3]), "r"((b)[0]), "r"((b)[1]))

// ---------------- smem layout --------------------------------------------------
#define ROWB    80
#define TILE_B  10240
#define STAGE_B 40960
#define SMEM_DYN (2*STAGE_B)
#define PITCH   129

__device__ __forceinline__ u32 pack_bf2(bf16 a, bf16 b){
    __nv_bfloat162 v = __halves2bfloat162(a, b);
    return *(u32*)&v;
}
__device__ __forceinline__ void split2(float a, float b, u32& h, u32& l){
    bf16 ha = __float2bfloat16(a), hb = __float2bfloat16(b);
    bf16 la = __float2bfloat16(a - __bfloat162float(ha));
    bf16 lb = __float2bfloat16(b - __bfloat162float(hb));
    h = pack_bf2(ha, hb); l = pack_bf2(la, lb);
}

// ---------------- loaders ------------------------------------------------------
__device__ __forceinline__ void cpa_tile(u32 sdst, const bf16* __restrict__ g,
                                         int row0, int k0, int t){
    int r = t >> 1, half = t & 1;
    const bf16* src = g + (size_t)(row0 + r)*D + k0 + half*16;
    u32 dst = sdst + r*ROWB + half*32;
    CPA16(dst,      src);
    CPA16(dst + 16, src + 8);
}

// ---------------- warp-tile compute --------------------------------------------
// Precise: 3 split products, BK=32 chunk.
__device__ __forceinline__ void compute_chunk2(float acc[2][8][4], u32 stage,
                                               int warp_m, int warp_n, int lane){
    const u32 aoff = stage + (warp_m*32 + (lane & 15))*ROWB + (lane >> 4)*16;
    const u32 boff = stage + 2*TILE_B
                   + (warp_n*64 + (lane & 7) + ((lane >> 4) << 3))*ROWB
                   + ((lane >> 3) & 1)*16;
    #pragma unroll
    for (int ks = 0; ks < 2; ks++){
        u32 ah[2][4], al[2][4], b[8][2];
        #pragma unroll
        for (int ma = 0; ma < 2; ma++){
            LDMX4(ah[ma][0], ah[ma][1], ah[ma][2], ah[ma][3], aoff + ma*1280 + ks*32);
            LDMX4(al[ma][0], al[ma][1], al[ma][2], al[ma][3], aoff + TILE_B + ma*1280 + ks*32);
        }
        #pragma unroll
        for (int p = 0; p < 4; p++)
            LDMX4(b[2*p][0], b[2*p][1], b[2*p+1][0], b[2*p+1][1], boff + p*1280 + ks*32);
        #pragma unroll
        for (int ma = 0; ma < 2; ma++)
            #pragma unroll
            for (int na = 0; na < 8; na++){
                MMA(acc[ma][na], ah[ma], b[na]);
                MMA(acc[ma][na], al[ma], b[na]);
            }
        #pragma unroll
        for (int p = 0; p < 4; p++)
            LDMX4(b[2*p][0], b[2*p][1], b[2*p+1][0], b[2*p+1][1], boff + TILE_B + p*1280 + ks*32);
        #pragma unroll
        for (int ma = 0; ma < 2; ma++)
            #pragma unroll
            for (int na = 0; na < 8; na++)
                MMA(acc[ma][na], ah[ma], b[na]);
    }
}

// Cheap: single bf16 product on one BK=32 sub-chunk; A at abase, B at bbase
__device__ __forceinline__ void compute_chunk_cheap(float acc[2][8][4],
                                                    u32 abase, u32 bbase,
                                                    int warp_m, int warp_n, int lane){
    const u32 aoff = abase + (warp_m*32 + (lane & 15))*ROWB + (lane >> 4)*16;
    const u32 boff = bbase + (warp_n*64 + (lane & 7) + ((lane >> 4) << 3))*ROWB
                   + ((lane >> 3) & 1)*16;
    #pragma unroll
    for (int ks = 0; ks < 2; ks++){
        u32 ah[2][4], b[8][2];
        #pragma unroll
        for (int ma = 0; ma < 2; ma++)
            LDMX4(ah[ma][0], ah[ma][1], ah[ma][2], ah[ma][3], aoff + ma*1280 + ks*32);
        #pragma unroll
        for (int p = 0; p < 4; p++)
            LDMX4(b[2*p][0], b[2*p][1], b[2*p+1][0], b[2*p+1][1], boff + p*1280 + ks*32);
        #pragma unroll
        for (int ma = 0; ma < 2; ma++)
            #pragma unroll
            for (int na = 0; na < 8; na++)
                MMA(acc[ma][na], ah[ma], b[na]);
    }
}

// ---------------- prep: build split(M), Frobenius partials ---------------------
__global__ void __launch_bounds__(256) prep_kernel(const float* __restrict__ SigmaK,
                                                   const float* __restrict__ Sigma)
{
    const int cls = blockIdx.y;
    const int t   = threadIdx.x;
    const size_t co = (size_t)cls*DD;
    const float4* Sk = (const float4*)(SigmaK + co);
    const float4* Sg = (const float4*)Sigma;
    float fr = 0.f;
    #pragma unroll
    for (int j = 0; j < 4; j++){
        int id = blockIdx.x*1024 + j*256 + t;
        float4 a = Sk[id], b = Sg[id];
        float4 r;
        r.x = ALPHA*a.x + (1.0f-ALPHA)*b.x;
        r.y = ALPHA*a.y + (1.0f-ALPHA)*b.y;
        r.z = ALPHA*a.z + (1.0f-ALPHA)*b.z;
        r.w = ALPHA*a.w + (1.0f-ALPHA)*b.w;
        fr += r.x*r.x + r.y*r.y + r.z*r.z + r.w*r.w;
        float4 m;
        m.x = OMS*r.x; m.y = OMS*r.y; m.z = OMS*r.z; m.w = OMS*r.w;
        int e = id*4, row = e >> 9, c0 = e & (D-1);
        int dg = row - c0;
        if (dg >= 0 && dg < 4) ((float*)&m)[dg] += SHRINK;
        alignas(8) bf16 hh[4], ll[4];
        #pragma unroll
        for (int q = 0; q < 4; q++){
            float v = ((float*)&m)[q];
            hh[q] = __float2bfloat16(v);
            ll[q] = __float2bfloat16(v - __bfloat162float(hh[q]));
        }
        *(uint2*)(g_Mhi + co + e) = *(const uint2*)hh;
        *(uint2*)(g_Mlo + co + e) = *(const uint2*)ll;
    }
    __shared__ float red[256];
    red[t] = fr; __syncthreads();
    for (int s = 128; s > 0; s >>= 1){ if (t < s) red[t] += red[t+s]; __syncthreads(); }
    if (t == 0) g_fpart[cls*64 + blockIdx.x] = red[0];
}

// ---------------- split X once -------------------------------------------------
__global__ void __launch_bounds__(256) splitx_kernel(const float* __restrict__ X)
{
    int id = blockIdx.x*256 + threadIdx.x;      // float4 index, NX*D/4 total
    float4 v = ((const float4*)X)[id];
    alignas(8) bf16 hh[4], ll[4];
    #pragma unroll
    for (int q = 0; q < 4; q++){
        float x = ((float*)&v)[q];
        hh[q] = __float2bfloat16(x);
        ll[q] = __float2bfloat16(x - __bfloat162float(hh[q]));
    }
    *(uint2*)(g_XShi + id*4) = *(const uint2*)hh;
    *(uint2*)(g_XSlo + id*4) = *(const uint2*)ll;
}

// ---------------- power iteration (bf16 M) + per-class constants ---------------
__global__ void __launch_bounds__(256) power_kernel(const float* __restrict__ cK)
{
    const int cls  = blockIdx.x;
    const int t    = threadIdx.x;
    const int lane = t & 31, warp = t >> 5;
    const bf16* Mc = g_Mhi + (size_t)cls*DD;
    __shared__ float v[D], w[D], red[256];

    float x = (t < 64) ? g_fpart[cls*64 + t] : 0.f;
    red[t] = x; __syncthreads();
    for (int s = 128; s > 0; s >>= 1){ if (t < s) red[t] += red[t+s]; __syncthreads(); }
    float frobsq = red[0]; __syncthreads();

    float ckv = (t < C) ? cK[t] : 0.f;
    red[t] = ckv; __syncthreads();
    for (int s = 128; s > 0; s >>= 1){ if (t < s) red[t] += red[t+s]; __syncthreads(); }
    float csum = red[0]; __syncthreads();

    for (int i = t; i < D; i += 256) v[i] = 1.0f;
    __syncthreads();

    float lam = 1.0f;
    for (int it = 0; it < POWER_ITERS; ++it){
        for (int r = warp; r < D; r += 8){
            float s = 0.f;
            const bf16* Mr = Mc + (size_t)r*D;
            for (int k = lane; k < D; k += 32) s += __bfloat162float(Mr[k])*v[k];
            #pragma unroll
            for (int o = 16; o > 0; o >>= 1) s += __shfl_down_sync(0xffffffffu, s, o);
            if (lane == 0) w[r] = s;
        }
        __syncthreads();
        float ns = 0.f;
        for (int i = t; i < D; i += 256) ns += w[i]*w[i];
        red[t] = ns; __syncthreads();
        for (int s = 128; s > 0; s >>= 1){ if (t < s) red[t] += red[t+s]; __syncthreads(); }
        lam = sqrtf(red[0]); __syncthreads();
        float inv = 1.0f/lam;
        for (int i = t; i < D; i += 256) v[i] = w[i]*inv;
        __syncthreads();
    }

    if (t == 0){
        // 8 power iters give lam >= ~0.9*lambda_max; 1.25 safety + 0.09 shrink
        // cushion keeps a*lambda_max < 2 guaranteed.
        float bound = 1.25f*lam + 0.05f;
        g_ab[cls] = 2.0f/(0.09f + bound);
        float c0 = cK[cls];
        g_base[cls] = (c0 > 0.f) ? (logf(c0/csum) - 0.25f*logf(frobsq)) : -INFINITY;
    }
}

// ---------------- X0 = a*I in split bf16 ---------------------------------------
__global__ void __launch_bounds__(256) setx0_kernel()
{
    const int cls = blockIdx.y;
    const size_t co = (size_t)cls*DD;
    const float a = g_ab[cls];
    bf16 ahi = __float2bfloat16(a);
    bf16 alo = __float2bfloat16(a - __bfloat162float(ahi));
    const int t = threadIdx.x;
    #pragma unroll
    for (int j = 0; j < 4; j++){
        int id = blockIdx.x*1024 + j*256 + t;
        alignas(8) bf16 hh[4] = {bf16(0.f), bf16(0.f), bf16(0.f), bf16(0.f)};
        alignas(8) bf16 ll[4] = {bf16(0.f), bf16(0.f), bf16(0.f), bf16(0.f)};
        int e = id*4, row = e >> 9, c0 = e & (D-1);
        int dg = row - c0;
        if (dg >= 0 && dg < 4){ hh[dg] = ahi; ll[dg] = alo; }
        *(uint2*)(g_Xhi + co + e) = *(const uint2*)hh;
        *(uint2*)(g_Xlo + co + e) = *(const uint2*)ll;
    }
}

// ---------------- Newton GEMM (mma.sync, split-bf16 / cheap bf16) --------------
// mode 0: grid (16,1,C), full;    Ohi(/Olo if prec) = A * B^T
// mode 1: grid (10,1,C), lower-triangle tiles; fused symmetrizing epilogue:
//         X' = split(2*X - A*B^T), written to (bi,bj) and mirrored (bj,bi).
// prec 0: bf16-only products (hi tiles); epilogue X term hi-only.
// wlo  : mode-1 epilogue writes lo plane (needed when next iter is precise).
__global__ void __launch_bounds__(256, 2) mma_newton_kernel(
    const bf16* __restrict__ Ahi, const bf16* __restrict__ Alo,
    const bf16* __restrict__ Bhi, const bf16* __restrict__ Blo,
    bf16* __restrict__ Ohi, bf16* __restrict__ Olo, int mode, int prec, int wlo)
{
    extern __shared__ char smem[];
    const u32 sb = smem_u32(smem);
    const int t = threadIdx.x, lane = t & 31, wid = t >> 5;
    const int warp_m = wid & 3, warp_n = wid >> 2;
    const int cls = blockIdx.z;
    const size_t co = (size_t)cls*DD;

    int bi, bj;
    if (mode == 1){
        int i = blockIdx.x; bi = 0;
        while (i >= bi + 1){ i -= bi + 1; bi++; }
        bj = i;
    } else { bi = blockIdx.x >> 2; bj = blockIdx.x & 3; }
    const int row0 = bi*128, col0 = bj*128;

    const bf16* Ah = Ahi + co; const bf16* Al = Alo + co;
    const bf16* Bh = Bhi + co; const bf16* Bl = Blo + co;

    float acc[2][8][4];
    #pragma unroll
    for (int ma = 0; ma < 2; ma++)
        #pragma unroll
        for (int na = 0; na < 8; na++)
            #pragma unroll
            for (int q = 0; q < 4; q++) acc[ma][na][q] = 0.f;

    if (prec){
        // BK=32, 16 steps, 3 split products. Single sync per chunk.
        cpa_tile(sb,            Ah, row0, 0, t);
        cpa_tile(sb +   TILE_B, Al, row0, 0, t);
        cpa_tile(sb + 2*TILE_B, Bh, col0, 0, t);
        cpa_tile(sb + 3*TILE_B, Bl, col0, 0, t);
        CP_COMMIT();
        for (int c = 0; c < 16; ++c){
            CP_WAIT0();
            __syncthreads();
            if (c + 1 < 16){
                u32 st = sb + ((c+1) & 1)*STAGE_B;
                int k0 = (c+1)*32;
                cpa_tile(st,            Ah, row0, k0, t);
                cpa_tile(st +   TILE_B, Al, row0, k0, t);
                cpa_tile(st + 2*TILE_B, Bh, col0, k0, t);
                cpa_tile(st + 3*TILE_B, Bl, col0, k0, t);
                CP_COMMIT();
            }
            compute_chunk2(acc, sb + (c & 1)*STAGE_B, warp_m, warp_n, lane);
        }
        __syncthreads();
    } else {
        // cheap: BK=64 per stage (hi tiles only), 8 steps, single sync per chunk
        cpa_tile(sb,            Ah, row0,  0, t);
        cpa_tile(sb +   TILE_B, Ah, row0, 32, t);
        cpa_tile(sb + 2*TILE_B, Bh, col0,  0, t);
        cpa_tile(sb + 3*TILE_B, Bh, col0, 32, t);
        CP_COMMIT();
        for (int c = 0; c < 8; ++c){
            CP_WAIT0();
            __syncthreads();
            if (c + 1 < 8){
                u32 st = sb + ((c+1) & 1)*STAGE_B;
                int k0 = (c+1)*64;
                cpa_tile(st,            Ah, row0, k0,      t);
                cpa_tile(st +   TILE_B, Ah, row0, k0 + 32, t);
                cpa_tile(st + 2*TILE_B, Bh, col0, k0,      t);
                cpa_tile(st + 3*TILE_B, Bh, col0, k0 + 32, t);
                CP_COMMIT();
            }
            u32 stg = sb + (c & 1)*STAGE_B;
            compute_chunk_cheap(acc, stg,          stg + 2*TILE_B, warp_m, warp_n, lane);
            compute_chunk_cheap(acc, stg + TILE_B, stg + 3*TILE_B, warp_m, warp_n, lane);
        }
        __syncthreads();
    }

    const int g = lane >> 2, tig = lane & 3;

    if (mode == 0){
        #pragma unroll
        for (int ma = 0; ma < 2; ma++){
            #pragma unroll
            for (int na = 0; na < 8; na++){
                const float* cc = acc[ma][na];
                int r0 = row0 + warp_m*32 + ma*16 + g;
                int col = col0 + warp_n*64 + na*8 + 2*tig;
                if (prec){
                    u32 h0, l0, h1, l1;
                    split2(cc[0], cc[1], h0, l0);
                    split2(cc[2], cc[3], h1, l1);
                    *(u32*)(Ohi + co + (size_t)r0*D + col)       = h0;
                    *(u32*)(Olo + co + (size_t)r0*D + col)       = l0;
                    *(u32*)(Ohi + co + (size_t)(r0+8)*D + col)   = h1;
                    *(u32*)(Olo + co + (size_t)(r0+8)*D + col)   = l1;
                } else {
                    *(u32*)(Ohi + co + (size_t)r0*D + col)
                        = pack_bf2(__float2bfloat16(cc[0]), __float2bfloat16(cc[1]));
                    *(u32*)(Ohi + co + (size_t)(r0+8)*D + col)
                        = pack_bf2(__float2bfloat16(cc[2]), __float2bfloat16(cc[3]));
                }
            }
        }
        return;
    }

    // ---- mode 1: fused symmetrizing epilogue ----
    // Phase A: v = 2*X - acc  -> packed split (hi|lo) into sh32[r][c], pitch 129
    u32* sh32 = (u32*)smem;
    #pragma unroll
    for (int ma = 0; ma < 2; ma++){
        #pragma unroll
        for (int na = 0; na < 8; na++){
            const float* cc = acc[ma][na];
            int rl = warp_m*32 + ma*16 + g;
            int cl = warp_n*64 + na*8 + 2*tig;
            #pragma unroll
            for (int h = 0; h < 2; h++){
                int r = rl + 8*h;
                size_t gidx = co + (size_t)(row0 + r)*D + col0 + cl;
                u32 xh = *(const u32*)(Bhi + gidx);   // B == current X
                __nv_bfloat162 bh2 = *(__nv_bfloat162*)&xh;
                float x0 = __bfloat162float(bh2.x);
                float x1 = __bfloat162float(bh2.y);
                if (prec){
                    u32 xl = *(const u32*)(Blo + gidx);
                    __nv_bfloat162 bl2 = *(__nv_bfloat162*)&xl;
                    x0 += __bfloat162float(bl2.x);
                    x1 += __bfloat162float(bl2.y);
                }
                float v0 = 2.0f*x0 - cc[2*h + 0];
                float v1 = 2.0f*x1 - cc[2*h + 1];
                bf16 h0 = __float2bfloat16(v0);
                bf16 l0 = __float2bfloat16(v0 - __bfloat162float(h0));
                bf16 h1 = __float2bfloat16(v1);
                bf16 l1 = __float2bfloat16(v1 - __bfloat162float(h1));
                sh32[r*PITCH + cl]     = pack_bf2(h0, l0);
                sh32[r*PITCH + cl + 1] = pack_bf2(h1, l1);
            }
        }
    }
    __syncthreads();

    // Phase B: coalesced writes of (bi,bj) tile and mirrored (bj,bi) tile
    const int wrow = t >> 5, lane5 = t & 31;
    if (bi != bj){
        #pragma unroll 4
        for (int it2 = 0; it2 < 16; it2++){
            int p = wrow + 8*it2;
            #pragma unroll
            for (int jq = 0; jq < 4; jq++){
                int q = lane5 + 32*jq;
                u32 u = sh32[p*PITCH + q];
                size_t di = co + (size_t)(row0 + p)*D + col0 + q;
                Ohi[di] = *(bf16*)&u;
                if (wlo) Olo[di] = *((bf16*)&u + 1);
                u32 ut = sh32[q*PITCH + p];
                size_t dt = co + (size_t)(col0 + p)*D + row0 + q;
                Ohi[dt] = *(bf16*)&ut;
                if (wlo) Olo[dt] = *((bf16*)&ut + 1);
            }
        }
    } else {
        #pragma unroll 4
        for (int it2 = 0; it2 < 16; it2++){
            int p = wrow + 8*it2;
            #pragma unroll
            for (int jq = 0; jq < 4; jq++){
                int q = lane5 + 32*jq;
                u32 u = (p >= q) ? sh32[p*PITCH + q] : sh32[q*PITCH + p];
                size_t di = co + (size_t)(row0 + p)*D + col0 + q;
                Ohi[di] = *(bf16*)&u;
                if (wlo) Olo[di] = *((bf16*)&u + 1);
            }
        }
    }
}

// ---------------- quad kernel: T = X*Lambda; part = dot(T, x - 2*mu) -----------
__global__ void __launch_bounds__(256, 2) mma_quad_kernel(
    const float* __restrict__ X, const float* __restrict__ muK,
    const bf16* __restrict__ Lhi, const bf16* __restrict__ Llo,
    float* __restrict__ part)
{
    extern __shared__ char smem[];
    const u32 sb = smem_u32(smem);
    const int t = threadIdx.x, lane = t & 31, wid = t >> 5;
    const int warp_m = wid & 3, warp_n = wid >> 2;
    const int cls = blockIdx.z;
    const size_t co = (size_t)cls*DD;
    const float* mu = muK + (size_t)cls*D;
    const int row0 = blockIdx.y*128, col0 = blockIdx.x*128;

    const bf16* Ah = g_XShi;      const bf16* Al = g_XSlo;
    const bf16* Bh = Lhi + co;    const bf16* Bl = Llo + co;

    float acc[2][8][4];
    #pragma unroll
    for (int ma = 0; ma < 2; ma++)
        #pragma unroll
        for (int na = 0; na < 8; na++)
            #pragma unroll
            for (int q = 0; q < 4; q++) acc[ma][na][q] = 0.f;

    cpa_tile(sb,            Ah, row0, 0, t);
    cpa_tile(sb +   TILE_B, Al, row0, 0, t);
    cpa_tile(sb + 2*TILE_B, Bh, col0, 0, t);
    cpa_tile(sb + 3*TILE_B, Bl, col0, 0, t);
    CP_COMMIT();

    for (int c = 0; c < 16; ++c){
        CP_WAIT0();
        __syncthreads();
        if (c + 1 < 16){
            u32 st = sb + ((c+1) & 1)*STAGE_B;
            int k0 = (c+1)*32;
            cpa_tile(st,            Ah, row0, k0, t);
            cpa_tile(st +   TILE_B, Al, row0, k0, t);
            cpa_tile(st + 2*TILE_B, Bh, col0, k0, t);
            cpa_tile(st + 3*TILE_B, Bl, col0, k0, t);
            CP_COMMIT();
        }
        compute_chunk2(acc, sb + (c & 1)*STAGE_B, warp_m, warp_n, lane);
    }
    __syncthreads();

    // epilogue: p = sum_j T[n,j]*(x_j - 2*mu_j) over this 128-col block
    const int g = lane >> 2, tig = lane & 3;
    float* sred = (float*)smem;   // [128][2]

    #pragma unroll
    for (int ma = 0; ma < 2; ma++){
        float p0 = 0.f, p1 = 0.f;
        int r0 = row0 + warp_m*32 + ma*16 + g;
        int r1 = r0 + 8;
        #pragma unroll
        for (int na = 0; na < 8; na++){
            int col = col0 + warp_n*64 + na*8 + 2*tig;
            float m0 = 2.0f*mu[col], m1 = 2.0f*mu[col+1];
            float d00 = X[(size_t)r0*D + col]   - m0;
            float d01 = X[(size_t)r0*D + col+1] - m1;
            float d10 = X[(size_t)r1*D + col]   - m0;
            float d11 = X[(size_t)r1*D + col+1] - m1;
            const float* cc = acc[ma][na];
            p0 += cc[0]*d00 + cc[1]*d01;
            p1 += cc[2]*d10 + cc[3]*d11;
        }
        p0 += __shfl_down_sync(0xffffffffu, p0, 2);
        p0 += __shfl_down_sync(0xffffffffu, p0, 1);
        p1 += __shfl_down_sync(0xffffffffu, p1, 2);
        p1 += __shfl_down_sync(0xffffffffu, p1, 1);
        if (tig == 0){
            int rl0 = warp_m*32 + ma*16 + g;
            sred[rl0*2 + warp_n]     = p0;
            sred[(rl0+8)*2 + warp_n] = p1;
        }
    }
    __syncthreads();
    if (t < 128){
        float s = sred[t*2] + sred[t*2 + 1];
        part[((size_t)blockIdx.x*NX + row0 + t)*C + cls] = s;
    }
}

// ---------------- mu^T Lambda mu, 8 row-slices per class -----------------------
__global__ void __launch_bounds__(256) muLmu_kernel(const float* __restrict__ muK,
                                                    const bf16* __restrict__ Lhi,
                                                    const bf16* __restrict__ Llo)
{
    const int slice = blockIdx.x;
    const int cls   = blockIdx.y;
    const int t     = threadIdx.x;
    const int lane  = t & 31, warp = t >> 5;
    const size_t co = (size_t)cls*DD;
    const float* mu = muK + (size_t)cls*D;
    __shared__ float sm[D], red[256];

    for (int i = t; i < D; i += 256) sm[i] = mu[i];
    __syncthreads();

    float acc = 0.f;
    #pragma unroll
    for (int rr = 0; rr < 8; rr++){
        int r = slice*64 + warp*8 + rr;
        const bf16* Lh = Lhi + co + (size_t)r*D;
        const bf16* Ll = Llo + co + (size_t)r*D;
        float s = 0.f;
        for (int k = lane; k < D; k += 32)
            s += (__bfloat162float(Lh[k]) + __bfloat162float(Ll[k]))*sm[k];
        #pragma unroll
        for (int o = 16; o > 0; o >>= 1) s += __shfl_down_sync(0xffffffffu, s, o);
        if (lane == 0) acc += s*sm[r];
    }
    red[t] = (lane == 0) ? acc : 0.f;
    __syncthreads();
    for (int s = 128; s > 0; s >>= 1){ if (t < s) red[t] += red[t+s]; __syncthreads(); }
    if (t == 0) g_muLmu8[cls*8 + slice] = red[0];
}

// ---------------- combine ------------------------------------------------------
__global__ void __launch_bounds__(256) combine_kernel(float* __restrict__ out)
{
    int idx = blockIdx.x*256 + threadIdx.x;
    if (idx >= NX*C) return;
    int c = idx % C;
    float ml = 0.f;
    #pragma unroll
    for (int s = 0; s < 8; s++) ml += g_muLmu8[c*8 + s];
    float q = g_part[idx] + g_part[NX*C + idx] + g_part[2*NX*C + idx] + g_part[3*NX*C + idx]
            + ml;
    out[idx] = g_base[c] - 0.5f*q;
}

// ---------------- host launcher ------------------------------------------------
extern "C" void kernel_launch(void* const* d_in, const int* in_sizes, int n_in,
                              void* d_out, int out_size)
{
    const float* X      = (const float*)d_in[0];
    const float* muK    = (const float*)d_in[1];
    const float* SigmaK = (const float*)d_in[2];
    const float* Sigma  = (const float*)d_in[3];
    const float* cK     = (const float*)d_in[4];
    float* out = (float*)d_out;

    float *pPart;
    bf16 *pMhi, *pMlo, *pXhi, *pXlo, *pYhi, *pYlo, *pZhi, *pZlo;
    cudaGetSymbolAddress((void**)&pMhi,  g_Mhi);
    cudaGetSymbolAddress((void**)&pMlo,  g_Mlo);
    cudaGetSymbolAddress((void**)&pXhi,  g_Xhi);
    cudaGetSymbolAddress((void**)&pXlo,  g_Xlo);
    cudaGetSymbolAddress((void**)&pYhi,  g_Yhi);
    cudaGetSymbolAddress((void**)&pYlo,  g_Ylo);
    cudaGetSymbolAddress((void**)&pZhi,  g_Zhi);
    cudaGetSymbolAddress((void**)&pZlo,  g_Zlo);
    cudaGetSymbolAddress((void**)&pPart, g_part);

    cudaFuncSetAttribute(mma_newton_kernel, cudaFuncAttributeMaxDynamicSharedMemorySize, SMEM_DYN);
    cudaFuncSetAttribute(mma_quad_kernel,   cudaFuncAttributeMaxDynamicSharedMemorySize, SMEM_DYN);

    prep_kernel  <<<dim3(64, C), 256>>>(SigmaK, Sigma);
    splitx_kernel<<<NX*D/(256*4), 256>>>(X);
    power_kernel <<<C, 256>>>(cK);
    setx0_kernel <<<dim3(64, C), 256>>>();

    bf16 *curh = pXhi, *curl = pXlo, *nxth = pZhi, *nxtl = pZlo;
    for (int it = 0; it < NEWTON_ITERS; ++it){
        int prec = (it >= CHEAP_ITERS) ? 1 : 0;
        int wlo  = (prec || it == CHEAP_ITERS - 1) ? 1 : 0;
        mma_newton_kernel<<<dim3(16, 1, C), 256, SMEM_DYN>>>(
            curh, curl, pMhi, pMlo, pYhi, pYlo, 0, prec, 0);
        mma_newton_kernel<<<dim3(10, 1, C), 256, SMEM_DYN>>>(
            pYhi, pYlo, curh, curl, nxth, nxtl, 1, prec, wlo);
        bf16* th = curh; curh = nxth; nxth = th;
        bf16* tl = curl; curl = nxtl; nxtl = tl;
    }

    muLmu_kernel  <<<dim3(8, C), 256>>>(muK, curh, curl);
    mma_quad_kernel<<<dim3(4, 16, C), 256, SMEM_DYN>>>(X, muK, curh, curl, pPart);
    combine_kernel <<<(NX*C + 255)/256, 256>>>(out);
}

// round 16
// speedup vs baseline: 5.6438x; 1.1688x over previous
#include <cuda_runtime.h>
#include <cuda_bf16.h>
#include <math.h>
#include <stdint.h>

// ---------------- problem constants ----------------
#define D      512
#define C      100
#define NX     2048
#define DD     (D*D)
#define ALPHA  0.5f
#define SHRINK 1e-4f
#define OMS    (1.0f - SHRINK)

#define NEWTON_ITERS 6
#define CHEAP_ITERS  5      // iters [0, CHEAP_ITERS) use bf16-only products
#define POWER_ITERS  8

typedef unsigned int u32;
typedef __nv_bfloat16 bf16;

// ---------------- scratch (device globals; no allocs allowed) ----------------
__device__ bf16  g_Mhi[C*DD];
__device__ bf16  g_Mlo[C*DD];
__device__ bf16  g_Xhi[C*DD];    // Newton iterate ping
__device__ bf16  g_Xlo[C*DD];
__device__ bf16  g_Yhi[C*DD];    // T = X*M
__device__ bf16  g_Ylo[C*DD];
__device__ bf16  g_Zhi[C*DD];    // Newton iterate pong
__device__ bf16  g_Zlo[C*DD];
__device__ bf16  g_XShi[NX*D];   // presplit test matrix X
__device__ bf16  g_XSlo[NX*D];
__device__ float g_fpart[C*64];
__device__ float g_alpha[C];     // Chebyshev init: X0 = alpha*I + beta*M
__device__ float g_beta[C];
__device__ float g_base[C];
__device__ float g_muLmu8[C*8];  // 8 row-slice partials of mu^T Lambda mu
__device__ float g_part[4*NX*C];

// ---------------- PTX helpers -------------------------------------------------
__device__ __forceinline__ u32 smem_u32(const void* p){
    u32 a; asm("{ .reg .u64 t; cvta.to.shared.u64 t, %1; cvt.u32.u64 %0, t; }" : "=r"(a) : "l"(p));
    return a;
}
#define CPA16(dst, src) \
    asm volatile("cp.async.cg.shared.global [%0], [%1], 16;" :: "r"(dst), "l"(src) : "memory")
#define CP_COMMIT() asm volatile("cp.async.commit_group;" ::: "memory")
#define CP_WAIT0()  asm volatile("cp.async.wait_group 0;" ::: "memory")

#define LDMX4(d0, d1, d2, d3, addr) \
    asm volatile("ldmatrix.sync.aligned.m8n8.x4.shared.b16 {%0,%1,%2,%3}, [%4];" \
        : "=r"(d0), "=r"(d1), "=r"(d2), "=r"(d3) : "r"(addr))

#define MMA(c, a, b) \
    asm volatile("mma.sync.aligned.m16n8k16.row.col.f32.bf16.bf16.f32 " \
        "{%0,%1,%2,%3}, {%4,%5,%6,%7}, {%8,%9}, {%0,%1,%2,%3};" \
        : "+f"((c)[0]), "+f"((c)[1]), "+f"((c)[2]), "+f"((c)[3]) \
        : "r"((a)[0]), "r"((a)[1]), "r"((a)[2]), "r"((a)[3]), "r"((b)[0]), "r"((b)[1]))

// ---------------- smem layout --------------------------------------------------
#define ROWB    80
#define TILE_B  10240
#define STAGE_B 40960
#define SMEM_DYN (2*STAGE_B)
#define PITCH   129

__device__ __forceinline__ u32 pack_bf2(bf16 a, bf16 b){
    __nv_bfloat162 v = __halves2bfloat162(a, b);
    return *(u32*)&v;
}
__device__ __forceinline__ void split2(float a, float b, u32& h, u32& l){
    bf16 ha = __float2bfloat16(a), hb = __float2bfloat16(b);
    bf16 la = __float2bfloat16(a - __bfloat162float(ha));
    bf16 lb = __float2bfloat16(b - __bfloat162float(hb));
    h = pack_bf2(ha, hb); l = pack_bf2(la, lb);
}

// ---------------- loaders ------------------------------------------------------
__device__ __forceinline__ void cpa_tile(u32 sdst, const bf16* __restrict__ g,
                                         int row0, int k0, int t){
    int r = t >> 1, half = t & 1;
    const bf16* src = g + (size_t)(row0 + r)*D + k0 + half*16;
    u32 dst = sdst + r*ROWB + half*32;
    CPA16(dst,      src);
    CPA16(dst + 16, src + 8);
}

// ---------------- warp-tile compute --------------------------------------------
// Precise: 3 split products, BK=32 chunk.
__device__ __forceinline__ void compute_chunk2(float acc[2][8][4], u32 stage,
                                               int warp_m, int warp_n, int lane){
    const u32 aoff = stage + (warp_m*32 + (lane & 15))*ROWB + (lane >> 4)*16;
    const u32 boff = stage + 2*TILE_B
                   + (warp_n*64 + (lane & 7) + ((lane >> 4) << 3))*ROWB
                   + ((lane >> 3) & 1)*16;
    #pragma unroll
    for (int ks = 0; ks < 2; ks++){
        u32 ah[2][4], al[2][4], b[8][2];
        #pragma unroll
        for (int ma = 0; ma < 2; ma++){
            LDMX4(ah[ma][0], ah[ma][1], ah[ma][2], ah[ma][3], aoff + ma*1280 + ks*32);
            LDMX4(al[ma][0], al[ma][1], al[ma][2], al[ma][3], aoff + TILE_B + ma*1280 + ks*32);
        }
        #pragma unroll
        for (int p = 0; p < 4; p++)
            LDMX4(b[2*p][0], b[2*p][1], b[2*p+1][0], b[2*p+1][1], boff + p*1280 + ks*32);
        #pragma unroll
        for (int ma = 0; ma < 2; ma++)
            #pragma unroll
            for (int na = 0; na < 8; na++){
                MMA(acc[ma][na], ah[ma], b[na]);
                MMA(acc[ma][na], al[ma], b[na]);
            }
        #pragma unroll
        for (int p = 0; p < 4; p++)
            LDMX4(b[2*p][0], b[2*p][1], b[2*p+1][0], b[2*p+1][1], boff + TILE_B + p*1280 + ks*32);
        #pragma unroll
        for (int ma = 0; ma < 2; ma++)
            #pragma unroll
            for (int na = 0; na < 8; na++)
                MMA(acc[ma][na], ah[ma], b[na]);
    }
}

// Cheap: single bf16 product on one BK=32 sub-chunk; A at abase, B at bbase
__device__ __forceinline__ void compute_chunk_cheap(float acc[2][8][4],
                                                    u32 abase, u32 bbase,
                                                    int warp_m, int warp_n, int lane){
    const u32 aoff = abase + (warp_m*32 + (lane & 15))*ROWB + (lane >> 4)*16;
    const u32 boff = bbase + (warp_n*64 + (lane & 7) + ((lane >> 4) << 3))*ROWB
                   + ((lane >> 3) & 1)*16;
    #pragma unroll
    for (int ks = 0; ks < 2; ks++){
        u32 ah[2][4], b[8][2];
        #pragma unroll
        for (int ma = 0; ma < 2; ma++)
            LDMX4(ah[ma][0], ah[ma][1], ah[ma][2], ah[ma][3], aoff + ma*1280 + ks*32);
        #pragma unroll
        for (int p = 0; p < 4; p++)
            LDMX4(b[2*p][0], b[2*p][1], b[2*p+1][0], b[2*p+1][1], boff + p*1280 + ks*32);
        #pragma unroll
        for (int ma = 0; ma < 2; ma++)
            #pragma unroll
            for (int na = 0; na < 8; na++)
                MMA(acc[ma][na], ah[ma], b[na]);
    }
}

// ---------------- prep: build split(M), Frobenius partials ---------------------
__global__ void __launch_bounds__(256) prep_kernel(const float* __restrict__ SigmaK,
                                                   const float* __restrict__ Sigma)
{
    const int cls = blockIdx.y;
    const int t   = threadIdx.x;
    const size_t co = (size_t)cls*DD;
    const float4* Sk = (const float4*)(SigmaK + co);
    const float4* Sg = (const float4*)Sigma;
    float fr = 0.f;
    #pragma unroll
    for (int j = 0; j < 4; j++){
        int id = blockIdx.x*1024 + j*256 + t;
        float4 a = Sk[id], b = Sg[id];
        float4 r;
        r.x = ALPHA*a.x + (1.0f-ALPHA)*b.x;
        r.y = ALPHA*a.y + (1.0f-ALPHA)*b.y;
        r.z = ALPHA*a.z + (1.0f-ALPHA)*b.z;
        r.w = ALPHA*a.w + (1.0f-ALPHA)*b.w;
        fr += r.x*r.x + r.y*r.y + r.z*r.z + r.w*r.w;
        float4 m;
        m.x = OMS*r.x; m.y = OMS*r.y; m.z = OMS*r.z; m.w = OMS*r.w;
        int e = id*4, row = e >> 9, c0 = e & (D-1);
        int dg = row - c0;
        if (dg >= 0 && dg < 4) ((float*)&m)[dg] += SHRINK;
        alignas(8) bf16 hh[4], ll[4];
        #pragma unroll
        for (int q = 0; q < 4; q++){
            float v = ((float*)&m)[q];
            hh[q] = __float2bfloat16(v);
            ll[q] = __float2bfloat16(v - __bfloat162float(hh[q]));
        }
        *(uint2*)(g_Mhi + co + e) = *(const uint2*)hh;
        *(uint2*)(g_Mlo + co + e) = *(const uint2*)ll;
    }
    __shared__ float red[256];
    red[t] = fr; __syncthreads();
    for (int s = 128; s > 0; s >>= 1){ if (t < s) red[t] += red[t+s]; __syncthreads(); }
    if (t == 0) g_fpart[cls*64 + blockIdx.x] = red[0];
}

// ---------------- split X once -------------------------------------------------
__global__ void __launch_bounds__(256) splitx_kernel(const float* __restrict__ X)
{
    int id = blockIdx.x*256 + threadIdx.x;      // float4 index, NX*D/4 total
    float4 v = ((const float4*)X)[id];
    alignas(8) bf16 hh[4], ll[4];
    #pragma unroll
    for (int q = 0; q < 4; q++){
        float x = ((float*)&v)[q];
        hh[q] = __float2bfloat16(x);
        ll[q] = __float2bfloat16(x - __bfloat162float(hh[q]));
    }
    *(uint2*)(g_XShi + id*4) = *(const uint2*)hh;
    *(uint2*)(g_XSlo + id*4) = *(const uint2*)ll;
}

// ---------------- power iteration (bf16 M) + per-class constants ---------------
__global__ void __launch_bounds__(256) power_kernel(const float* __restrict__ cK)
{
    const int cls  = blockIdx.x;
    const int t    = threadIdx.x;
    const int lane = t & 31, warp = t >> 5;
    const bf16* Mc = g_Mhi + (size_t)cls*DD;
    __shared__ float v[D], w[D], red[256];

    float x = (t < 64) ? g_fpart[cls*64 + t] : 0.f;
    red[t] = x; __syncthreads();
    for (int s = 128; s > 0; s >>= 1){ if (t < s) red[t] += red[t+s]; __syncthreads(); }
    float frobsq = red[0]; __syncthreads();

    float ckv = (t < C) ? cK[t] : 0.f;
    red[t] = ckv; __syncthreads();
    for (int s = 128; s > 0; s >>= 1){ if (t < s) red[t] += red[t+s]; __syncthreads(); }
    float csum = red[0]; __syncthreads();

    for (int i = t; i < D; i += 256) v[i] = 1.0f;
    __syncthreads();

    float lam = 1.0f;
    for (int it = 0; it < POWER_ITERS; ++it){
        for (int r = warp; r < D; r += 8){
            float s = 0.f;
            const bf16* Mr = Mc + (size_t)r*D;
            for (int k = lane; k < D; k += 32) s += __bfloat162float(Mr[k])*v[k];
            #pragma unroll
            for (int o = 16; o > 0; o >>= 1) s += __shfl_down_sync(0xffffffffu, s, o);
            if (lane == 0) w[r] = s;
        }
        __syncthreads();
        float ns = 0.f;
        for (int i = t; i < D; i += 256) ns += w[i]*w[i];
        red[t] = ns; __syncthreads();
        for (int s = 128; s > 0; s >>= 1){ if (t < s) red[t] += red[t+s]; __syncthreads(); }
        lam = sqrtf(red[0]); __syncthreads();
        float inv = 1.0f/lam;
        for (int i = t; i < D; i += 256) v[i] = w[i]*inv;
        __syncthreads();
    }

    if (t == 0){
        // Chebyshev degree-1 Newton init on [l, L]:
        //   X0 = c*(S*I - M), S = L + l, dd = L - l, c = 8/(2*S^2 - dd^2)
        //   residual r0 = 1/T2((L+l)/(L-l)) ~ 0.88 for kappa~50.
        // l = structural lambda_min; L = safe lambda_max upper bound.
        float l = 0.0999f;
        float L = 1.15f*lam + 0.05f;
        float S = L + l, dd = L - l;
        float c = 8.0f/(2.0f*S*S - dd*dd);
        g_alpha[cls] = c*S;
        g_beta[cls]  = -c;
        float c0 = cK[cls];
        g_base[cls] = (c0 > 0.f) ? (logf(c0/csum) - 0.25f*logf(frobsq)) : -INFINITY;
    }
}

// ---------------- X0 = alpha*I + beta*M in split bf16 --------------------------
__global__ void __launch_bounds__(256) setx0_kernel()
{
    const int cls = blockIdx.y;
    const size_t co = (size_t)cls*DD;
    const float alpha = g_alpha[cls];
    const float beta  = g_beta[cls];
    const int t = threadIdx.x;
    #pragma unroll
    for (int j = 0; j < 4; j++){
        int id = blockIdx.x*1024 + j*256 + t;
        int e = id*4, row = e >> 9, c0 = e & (D-1);
        int dg = row - c0;
        union { uint2 u; bf16 b[4]; } mh, ml;
        mh.u = *(const uint2*)(g_Mhi + co + e);
        ml.u = *(const uint2*)(g_Mlo + co + e);
        alignas(8) bf16 hh[4], ll[4];
        #pragma unroll
        for (int q = 0; q < 4; q++){
            float m = __bfloat162float(mh.b[q]) + __bfloat162float(ml.b[q]);
            float v = beta*m + ((dg == q) ? alpha : 0.0f);
            hh[q] = __float2bfloat16(v);
            ll[q] = __float2bfloat16(v - __bfloat162float(hh[q]));
        }
        *(uint2*)(g_Xhi + co + e) = *(const uint2*)hh;
        *(uint2*)(g_Xlo + co + e) = *(const uint2*)ll;
    }
}

// ---------------- Newton GEMM (mma.sync, split-bf16 / cheap bf16) --------------
// mode 0: grid (16,1,C), full;    Ohi(/Olo if prec) = A * B^T
// mode 1: grid (10,1,C), lower-triangle tiles; fused symmetrizing epilogue:
//         X' = split(2*X - A*B^T), written to (bi,bj) and mirrored (bj,bi).
// prec 0: bf16-only products (hi tiles); epilogue X term hi-only.
// wlo  : mode-1 epilogue writes lo plane (needed when next iter is precise).
__global__ void __launch_bounds__(256, 2) mma_newton_kernel(
    const bf16* __restrict__ Ahi, const bf16* __restrict__ Alo,
    const bf16* __restrict__ Bhi, const bf16* __restrict__ Blo,
    bf16* __restrict__ Ohi, bf16* __restrict__ Olo, int mode, int prec, int wlo)
{
    extern __shared__ char smem[];
    const u32 sb = smem_u32(smem);
    const int t = threadIdx.x, lane = t & 31, wid = t >> 5;
    const int warp_m = wid & 3, warp_n = wid >> 2;
    const int cls = blockIdx.z;
    const size_t co = (size_t)cls*DD;

    int bi, bj;
    if (mode == 1){
        int i = blockIdx.x; bi = 0;
        while (i >= bi + 1){ i -= bi + 1; bi++; }
        bj = i;
    } else { bi = blockIdx.x >> 2; bj = blockIdx.x & 3; }
    const int row0 = bi*128, col0 = bj*128;

    const bf16* Ah = Ahi + co; const bf16* Al = Alo + co;
    const bf16* Bh = Bhi + co; const bf16* Bl = Blo + co;

    float acc[2][8][4];
    #pragma unroll
    for (int ma = 0; ma < 2; ma++)
        #pragma unroll
        for (int na = 0; na < 8; na++)
            #pragma unroll
            for (int q = 0; q < 4; q++) acc[ma][na][q] = 0.f;

    if (prec){
        // BK=32, 16 steps, 3 split products. Single sync per chunk.
        cpa_tile(sb,            Ah, row0, 0, t);
        cpa_tile(sb +   TILE_B, Al, row0, 0, t);
        cpa_tile(sb + 2*TILE_B, Bh, col0, 0, t);
        cpa_tile(sb + 3*TILE_B, Bl, col0, 0, t);
        CP_COMMIT();
        for (int c = 0; c < 16; ++c){
            CP_WAIT0();
            __syncthreads();
            if (c + 1 < 16){
                u32 st = sb + ((c+1) & 1)*STAGE_B;
                int k0 = (c+1)*32;
                cpa_tile(st,            Ah, row0, k0, t);
                cpa_tile(st +   TILE_B, Al, row0, k0, t);
                cpa_tile(st + 2*TILE_B, Bh, col0, k0, t);
                cpa_tile(st + 3*TILE_B, Bl, col0, k0, t);
                CP_COMMIT();
            }
            compute_chunk2(acc, sb + (c & 1)*STAGE_B, warp_m, warp_n, lane);
        }
        __syncthreads();
    } else {
        // cheap: BK=64 per stage (hi tiles only), 8 steps, single sync per chunk
        cpa_tile(sb,            Ah, row0,  0, t);
        cpa_tile(sb +   TILE_B, Ah, row0, 32, t);
        cpa_tile(sb + 2*TILE_B, Bh, col0,  0, t);
        cpa_tile(sb + 3*TILE_B, Bh, col0, 32, t);
        CP_COMMIT();
        for (int c = 0; c < 8; ++c){
            CP_WAIT0();
            __syncthreads();
            if (c + 1 < 8){
                u32 st = sb + ((c+1) & 1)*STAGE_B;
                int k0 = (c+1)*64;
                cpa_tile(st,            Ah, row0, k0,      t);
                cpa_tile(st +   TILE_B, Ah, row0, k0 + 32, t);
                cpa_tile(st + 2*TILE_B, Bh, col0, k0,      t);
                cpa_tile(st + 3*TILE_B, Bh, col0, k0 + 32, t);
                CP_COMMIT();
            }
            u32 stg = sb + (c & 1)*STAGE_B;
            compute_chunk_cheap(acc, stg,          stg + 2*TILE_B, warp_m, warp_n, lane);
            compute_chunk_cheap(acc, stg + TILE_B, stg + 3*TILE_B, warp_m, warp_n, lane);
        }
        __syncthreads();
    }

    const int g = lane >> 2, tig = lane & 3;

    if (mode == 0){
        #pragma unroll
        for (int ma = 0; ma < 2; ma++){
            #pragma unroll
            for (int na = 0; na < 8; na++){
                const float* cc = acc[ma][na];
                int r0 = row0 + warp_m*32 + ma*16 + g;
                int col = col0 + warp_n*64 + na*8 + 2*tig;
                if (prec){
                    u32 h0, l0, h1, l1;
                    split2(cc[0], cc[1], h0, l0);
                    split2(cc[2], cc[3], h1, l1);
                    *(u32*)(Ohi + co + (size_t)r0*D + col)       = h0;
                    *(u32*)(Olo + co + (size_t)r0*D + col)       = l0;
                    *(u32*)(Ohi + co + (size_t)(r0+8)*D + col)   = h1;
                    *(u32*)(Olo + co + (size_t)(r0+8)*D + col)   = l1;
                } else {
                    *(u32*)(Ohi + co + (size_t)r0*D + col)
                        = pack_bf2(__float2bfloat16(cc[0]), __float2bfloat16(cc[1]));
                    *(u32*)(Ohi + co + (size_t)(r0+8)*D + col)
                        = pack_bf2(__float2bfloat16(cc[2]), __float2bfloat16(cc[3]));
                }
            }
        }
        return;
    }

    // ---- mode 1: fused symmetrizing epilogue ----
    // Phase A: v = 2*X - acc  -> packed split (hi|lo) into sh32[r][c], pitch 129
    u32* sh32 = (u32*)smem;
    #pragma unroll
    for (int ma = 0; ma < 2; ma++){
        #pragma unroll
        for (int na = 0; na < 8; na++){
            const float* cc = acc[ma][na];
            int rl = warp_m*32 + ma*16 + g;
            int cl = warp_n*64 + na*8 + 2*tig;
            #pragma unroll
            for (int h = 0; h < 2; h++){
                int r = rl + 8*h;
                size_t gidx = co + (size_t)(row0 + r)*D + col0 + cl;
                u32 xh = *(const u32*)(Bhi + gidx);   // B == current X
                __nv_bfloat162 bh2 = *(__nv_bfloat162*)&xh;
                float x0 = __bfloat162float(bh2.x);
                float x1 = __bfloat162float(bh2.y);
                if (prec){
                    u32 xl = *(const u32*)(Blo + gidx);
                    __nv_bfloat162 bl2 = *(__nv_bfloat162*)&xl;
                    x0 += __bfloat162float(bl2.x);
                    x1 += __bfloat162float(bl2.y);
                }
                float v0 = 2.0f*x0 - cc[2*h + 0];
                float v1 = 2.0f*x1 - cc[2*h + 1];
                bf16 h0 = __float2bfloat16(v0);
                bf16 l0 = __float2bfloat16(v0 - __bfloat162float(h0));
                bf16 h1 = __float2bfloat16(v1);
                bf16 l1 = __float2bfloat16(v1 - __bfloat162float(h1));
                sh32[r*PITCH + cl]     = pack_bf2(h0, l0);
                sh32[r*PITCH + cl + 1] = pack_bf2(h1, l1);
            }
        }
    }
    __syncthreads();

    // Phase B: coalesced writes of (bi,bj) tile and mirrored (bj,bi) tile
    const int wrow = t >> 5, lane5 = t & 31;
    if (bi != bj){
        #pragma unroll 4
        for (int it2 = 0; it2 < 16; it2++){
            int p = wrow + 8*it2;
            #pragma unroll
            for (int jq = 0; jq < 4; jq++){
                int q = lane5 + 32*jq;
                u32 u = sh32[p*PITCH + q];
                size_t di = co + (size_t)(row0 + p)*D + col0 + q;
                Ohi[di] = *(bf16*)&u;
                if (wlo) Olo[di] = *((bf16*)&u + 1);
                u32 ut = sh32[q*PITCH + p];
                size_t dt = co + (size_t)(col0 + p)*D + row0 + q;
                Ohi[dt] = *(bf16*)&ut;
                if (wlo) Olo[dt] = *((bf16*)&ut + 1);
            }
        }
    } else {
        #pragma unroll 4
        for (int it2 = 0; it2 < 16; it2++){
            int p = wrow + 8*it2;
            #pragma unroll
            for (int jq = 0; jq < 4; jq++){
                int q = lane5 + 32*jq;
                u32 u = (p >= q) ? sh32[p*PITCH + q] : sh32[q*PITCH + p];
                size_t di = co + (size_t)(row0 + p)*D + col0 + q;
                Ohi[di] = *(bf16*)&u;
                if (wlo) Olo[di] = *((bf16*)&u + 1);
            }
        }
    }
}

// ---------------- quad kernel: T = X*Lambda; part = dot(T, x - 2*mu) -----------
__global__ void __launch_bounds__(256, 2) mma_quad_kernel(
    const float* __restrict__ X, const float* __restrict__ muK,
    const bf16* __restrict__ Lhi, const bf16* __restrict__ Llo,
    float* __restrict__ part)
{
    extern __shared__ char smem[];
    const u32 sb = smem_u32(smem);
    const int t = threadIdx.x, lane = t & 31, wid = t >> 5;
    const int warp_m = wid & 3, warp_n = wid >> 2;
    const int cls = blockIdx.z;
    const size_t co = (size_t)cls*DD;
    const float* mu = muK + (size_t)cls*D;
    const int row0 = blockIdx.y*128, col0 = blockIdx.x*128;

    const bf16* Ah = g_XShi;      const bf16* Al = g_XSlo;
    const bf16* Bh = Lhi + co;    const bf16* Bl = Llo + co;

    float acc[2][8][4];
    #pragma unroll
    for (int ma = 0; ma < 2; ma++)
        #pragma unroll
        for (int na = 0; na < 8; na++)
            #pragma unroll
            for (int q = 0; q < 4; q++) acc[ma][na][q] = 0.f;

    cpa_tile(sb,            Ah, row0, 0, t);
    cpa_tile(sb +   TILE_B, Al, row0, 0, t);
    cpa_tile(sb + 2*TILE_B, Bh, col0, 0, t);
    cpa_tile(sb + 3*TILE_B, Bl, col0, 0, t);
    CP_COMMIT();

    for (int c = 0; c < 16; ++c){
        CP_WAIT0();
        __syncthreads();
        if (c + 1 < 16){
            u32 st = sb + ((c+1) & 1)*STAGE_B;
            int k0 = (c+1)*32;
            cpa_tile(st,            Ah, row0, k0, t);
            cpa_tile(st +   TILE_B, Al, row0, k0, t);
            cpa_tile(st + 2*TILE_B, Bh, col0, k0, t);
            cpa_tile(st + 3*TILE_B, Bl, col0, k0, t);
            CP_COMMIT();
        }
        compute_chunk2(acc, sb + (c & 1)*STAGE_B, warp_m, warp_n, lane);
    }
    __syncthreads();

    // epilogue: p = sum_j T[n,j]*(x_j - 2*mu_j) over this 128-col block
    const int g = lane >> 2, tig = lane & 3;
    float* sred = (float*)smem;   // [128][2]

    #pragma unroll
    for (int ma = 0; ma < 2; ma++){
        float p0 = 0.f, p1 = 0.f;
        int r0 = row0 + warp_m*32 + ma*16 + g;
        int r1 = r0 + 8;
        #pragma unroll
        for (int na = 0; na < 8; na++){
            int col = col0 + warp_n*64 + na*8 + 2*tig;
            float m0 = 2.0f*mu[col], m1 = 2.0f*mu[col+1];
            float d00 = X[(size_t)r0*D + col]   - m0;
            float d01 = X[(size_t)r0*D + col+1] - m1;
            float d10 = X[(size_t)r1*D + col]   - m0;
            float d11 = X[(size_t)r1*D + col+1] - m1;
            const float* cc = acc[ma][na];
            p0 += cc[0]*d00 + cc[1]*d01;
            p1 += cc[2]*d10 + cc[3]*d11;
        }
        p0 += __shfl_down_sync(0xffffffffu, p0, 2);
        p0 += __shfl_down_sync(0xffffffffu, p0, 1);
        p1 += __shfl_down_sync(0xffffffffu, p1, 2);
        p1 += __shfl_down_sync(0xffffffffu, p1, 1);
        if (tig == 0){
            int rl0 = warp_m*32 + ma*16 + g;
            sred[rl0*2 + warp_n]     = p0;
            sred[(rl0+8)*2 + warp_n] = p1;
        }
    }
    __syncthreads();
    if (t < 128){
        float s = sred[t*2] + sred[t*2 + 1];
        part[((size_t)blockIdx.x*NX + row0 + t)*C + cls] = s;
    }
}

// ---------------- mu^T Lambda mu, 8 row-slices per class -----------------------
__global__ void __launch_bounds__(256) muLmu_kernel(const float* __restrict__ muK,
                                                    const bf16* __restrict__ Lhi,
                                                    const bf16* __restrict__ Llo)
{
    const int slice = blockIdx.x;
    const int cls   = blockIdx.y;
    const int t     = threadIdx.x;
    const int lane  = t & 31, warp = t >> 5;
    const size_t co = (size_t)cls*DD;
    const float* mu = muK + (size_t)cls*D;
    __shared__ float sm[D], red[256];

    for (int i = t; i < D; i += 256) sm[i] = mu[i];
    __syncthreads();

    float acc = 0.f;
    #pragma unroll
    for (int rr = 0; rr < 8; rr++){
        int r = slice*64 + warp*8 + rr;
        const bf16* Lh = Lhi + co + (size_t)r*D;
        const bf16* Ll = Llo + co + (size_t)r*D;
        float s = 0.f;
        for (int k = lane; k < D; k += 32)
            s += (__bfloat162float(Lh[k]) + __bfloat162float(Ll[k]))*sm[k];
        #pragma unroll
        for (int o = 16; o > 0; o >>= 1) s += __shfl_down_sync(0xffffffffu, s, o);
        if (lane == 0) acc += s*sm[r];
    }
    red[t] = (lane == 0) ? acc : 0.f;
    __syncthreads();
    for (int s = 128; s > 0; s >>= 1){ if (t < s) red[t] += red[t+s]; __syncthreads(); }
    if (t == 0) g_muLmu8[cls*8 + slice] = red[0];
}

// ---------------- combine ------------------------------------------------------
__global__ void __launch_bounds__(256) combine_kernel(float* __restrict__ out)
{
    int idx = blockIdx.x*256 + threadIdx.x;
    if (idx >= NX*C) return;
    int c = idx % C;
    float ml = 0.f;
    #pragma unroll
    for (int s = 0; s < 8; s++) ml += g_muLmu8[c*8 + s];
    float q = g_part[idx] + g_part[NX*C + idx] + g_part[2*NX*C + idx] + g_part[3*NX*C + idx]
            + ml;
    out[idx] = g_base[c] - 0.5f*q;
}

// ---------------- host launcher ------------------------------------------------
extern "C" void kernel_launch(void* const* d_in, const int* in_sizes, int n_in,
                              void* d_out, int out_size)
{
    const float* X      = (const float*)d_in[0];
    const float* muK    = (const float*)d_in[1];
    const float* SigmaK = (const float*)d_in[2];
    const float* Sigma  = (const float*)d_in[3];
    const float* cK     = (const float*)d_in[4];
    float* out = (float*)d_out;

    float *pPart;
    bf16 *pMhi, *pMlo, *pXhi, *pXlo, *pYhi, *pYlo, *pZhi, *pZlo;
    cudaGetSymbolAddress((void**)&pMhi,  g_Mhi);
    cudaGetSymbolAddress((void**)&pMlo,  g_Mlo);
    cudaGetSymbolAddress((void**)&pXhi,  g_Xhi);
    cudaGetSymbolAddress((void**)&pXlo,  g_Xlo);
    cudaGetSymbolAddress((void**)&pYhi,  g_Yhi);
    cudaGetSymbolAddress((void**)&pYlo,  g_Ylo);
    cudaGetSymbolAddress((void**)&pZhi,  g_Zhi);
    cudaGetSymbolAddress((void**)&pZlo,  g_Zlo);
    cudaGetSymbolAddress((void**)&pPart, g_part);

    cudaFuncSetAttribute(mma_newton_kernel, cudaFuncAttributeMaxDynamicSharedMemorySize, SMEM_DYN);
    cudaFuncSetAttribute(mma_quad_kernel,   cudaFuncAttributeMaxDynamicSharedMemorySize, SMEM_DYN);

    prep_kernel  <<<dim3(64, C), 256>>>(SigmaK, Sigma);
    splitx_kernel<<<NX*D/(256*4), 256>>>(X);
    power_kernel <<<C, 256>>>(cK);
    setx0_kernel <<<dim3(64, C), 256>>>();

    bf16 *curh = pXhi, *curl = pXlo, *nxth = pZhi, *nxtl = pZlo;
    for (int it = 0; it < NEWTON_ITERS; ++it){
        int prec = (it >= CHEAP_ITERS) ? 1 : 0;
        int wlo  = (prec || it == CHEAP_ITERS - 1) ? 1 : 0;
        mma_newton_kernel<<<dim3(16, 1, C), 256, SMEM_DYN>>>(
            curh, curl, pMhi, pMlo, pYhi, pYlo, 0, prec, 0);
        mma_newton_kernel<<<dim3(10, 1, C), 256, SMEM_DYN>>>(
            pYhi, pYlo, curh, curl, nxth, nxtl, 1, prec, wlo);
        bf16* th = curh; curh = nxth; nxth = th;
        bf16* tl = curl; curl = nxtl; nxtl = tl;
    }

    muLmu_kernel  <<<dim3(8, C), 256>>>(muK, curh, curl);
    mma_quad_kernel<<<dim3(4, 16, C), 256, SMEM_DYN>>>(X, muK, curh, curl, pPart);
    combine_kernel <<<(NX*C + 255)/256, 256>>>(out);
}